// round 2
// baseline (speedup 1.0000x reference)
#include <cuda_runtime.h>
#include <math.h>
#include <stdint.h>

// RNG variant: 1 = threefry_partitionable (modern JAX default), 0 = legacy
#define JAX_PARTITIONABLE 1

#define BB 8
#define DD 512
#define DFF 2048
#define L0 4096
#define UMAX 45
#define LN_EPS 1e-5f

// ------------------- scratch (device globals; no allocs) -------------------
__device__ __align__(16) float g_h  [BB*L0*DD];
__device__ __align__(16) float g_h2 [BB*L0*DD];
__device__ __align__(16) float g_x  [BB*L0*DD];
__device__ __align__(16) float g_z  [BB*L0*DD];
__device__ __align__(16) float g_y  [BB*L0*DFF];
__device__ __align__(16) float g_M  [BB*8*L0];
__device__ __align__(16) int   g_idx[L0*UMAX];
__device__ __align__(16) int   g_top[BB*8*UMAX];
__device__ __align__(16) int   g_rowmap[BB*8*L0];
__device__ __align__(16) float g_ctx[BB*8*UMAX*64];
__device__ __align__(16) float g_qmean[BB*8*64];

// ------------------- threefry2x32 (JAX-compatible) -------------------------
#define TF_R(x0,x1,r) { x0 += x1; x1 = ((x1 << (r)) | (x1 >> (32-(r)))); x1 ^= x0; }
__host__ __device__ inline void threefry2x32(unsigned ks0, unsigned ks1,
                                             unsigned &x0, unsigned &x1)
{
  unsigned ks2 = ks0 ^ ks1 ^ 0x1BD11BDAu;
  x0 += ks0; x1 += ks1;
  TF_R(x0,x1,13) TF_R(x0,x1,15) TF_R(x0,x1,26) TF_R(x0,x1,6)
  x0 += ks1; x1 += ks2 + 1u;
  TF_R(x0,x1,17) TF_R(x0,x1,29) TF_R(x0,x1,16) TF_R(x0,x1,24)
  x0 += ks2; x1 += ks0 + 2u;
  TF_R(x0,x1,13) TF_R(x0,x1,15) TF_R(x0,x1,26) TF_R(x0,x1,6)
  x0 += ks0; x1 += ks1 + 3u;
  TF_R(x0,x1,17) TF_R(x0,x1,29) TF_R(x0,x1,16) TF_R(x0,x1,24)
  x0 += ks1; x1 += ks2 + 4u;
  TF_R(x0,x1,13) TF_R(x0,x1,15) TF_R(x0,x1,26) TF_R(x0,x1,6)
  x0 += ks2; x1 += ks0 + 5u;
}

__global__ void idx_part(unsigned k0, unsigned k1, int total, int mask)
{
  int t = blockIdx.x * 256 + threadIdx.x;
  if (t >= total) return;
  unsigned x0 = 0u, x1 = (unsigned)t;
  threefry2x32(k0, k1, x0, x1);
  g_idx[t] = (int)((x0 ^ x1) & (unsigned)mask);
}

__global__ void idx_leg(unsigned k0, unsigned k1, int total, int mask)
{
  int half = total >> 1;
  int j = blockIdx.x * 256 + threadIdx.x;
  if (j >= half) return;
  unsigned x0 = (unsigned)j, x1 = (unsigned)(j + half);
  threefry2x32(k0, k1, x0, x1);
  g_idx[j]        = (int)(x0 & (unsigned)mask);
  g_idx[j + half] = (int)(x1 & (unsigned)mask);
}

// ------------------- M = max_s qk - sum_s qk / L ----------------------------
__global__ __launch_bounds__(256) void prob_m_kernel(
    const float* __restrict__ h, int L, int u, float invL)
{
  __shared__ float qs[8][64];
  int bh = blockIdx.y; int b = bh >> 3, hh = bh & 7;
  int warp = threadIdx.x >> 5, lane = threadIdx.x & 31;
  int l = blockIdx.x * 8 + warp;
  const float* base = h + (size_t)b * L * DD + hh * 64;
  const float* qrow = base + (size_t)l * DD;
  qs[warp][lane]      = qrow[lane];
  qs[warp][lane + 32] = qrow[lane + 32];
  __syncwarp();
  float mx = -INFINITY, sm = 0.f;
  for (int s = lane; s < u; s += 32) {
    int kl = g_idx[l * u + s];
    const float4* krow = (const float4*)(base + (size_t)kl * DD);
    float dot = 0.f;
    #pragma unroll
    for (int q4 = 0; q4 < 16; q4++) {
      float4 kv = krow[q4];
      dot += qs[warp][q4*4+0]*kv.x + qs[warp][q4*4+1]*kv.y
           + qs[warp][q4*4+2]*kv.z + qs[warp][q4*4+3]*kv.w;
    }
    mx = fmaxf(mx, dot); sm += dot;
  }
  #pragma unroll
  for (int o = 16; o; o >>= 1) {
    mx = fmaxf(mx, __shfl_xor_sync(0xffffffffu, mx, o));
    sm += __shfl_xor_sync(0xffffffffu, sm, o);
  }
  if (lane == 0) g_M[(size_t)bh * L + l] = mx - sm * invL;
}

// ------------------- top-k (iterative argmax, lower-index tiebreak) --------
__global__ __launch_bounds__(256) void topk_kernel(int L, int u)
{
  __shared__ float sM[L0];
  __shared__ float sval[256];
  __shared__ int   sidx[256];
  int bh = blockIdx.x;
  int tid = threadIdx.x;
  for (int l = tid; l < L; l += 256) {
    sM[l] = g_M[(size_t)bh * L + l];
    g_rowmap[(size_t)bh * L + l] = -1;
  }
  __syncthreads();
  for (int r = 0; r < u; r++) {
    float bv = -INFINITY; int bi = 0x7fffffff;
    for (int l = tid; l < L; l += 256) {
      float v = sM[l];
      if (v > bv || (v == bv && l < bi)) { bv = v; bi = l; }
    }
    sval[tid] = bv; sidx[tid] = bi;
    __syncthreads();
    for (int st = 128; st > 0; st >>= 1) {
      if (tid < st) {
        float v2 = sval[tid + st]; int i2 = sidx[tid + st];
        if (v2 > sval[tid] || (v2 == sval[tid] && i2 < sidx[tid])) {
          sval[tid] = v2; sidx[tid] = i2;
        }
      }
      __syncthreads();
    }
    if (tid == 0) {
      int sel = sidx[0];
      g_top[bh * u + r] = sel;
      g_rowmap[(size_t)bh * L + sel] = r;
      sM[sel] = -INFINITY;
    }
    __syncthreads();
  }
}

// ------------------- qmean over L per (b,h,d) -------------------------------
__global__ __launch_bounds__(512) void qmean_kernel(const float* __restrict__ h, int L)
{
  __shared__ float part[512];
  int bh = blockIdx.x; int b = bh >> 3, hh = bh & 7;
  int tid = threadIdx.x; int d = tid & 63; int p = tid >> 6;
  const float* base = h + (size_t)b * L * DD + hh * 64;
  float s = 0.f;
  for (int l = p; l < L; l += 8) s += base[(size_t)l * DD + d];
  part[tid] = s;
  __syncthreads();
  if (p == 0) {
    float t = 0.f;
    #pragma unroll
    for (int q = 0; q < 8; q++) t += part[q * 64 + d];
    g_qmean[bh * 64 + d] = t / (float)L;
  }
}

// ------------------- ctx_top: online softmax over all L keys ---------------
__global__ __launch_bounds__(256) void ctx_kernel(const float* __restrict__ h, int L, int u)
{
  __shared__ float qr[64];
  __shared__ float cm[8], cs[8], cw[8], cS;
  __shared__ float cacc[8][64];
  int bh = blockIdx.y; int b = bh >> 3, hh = bh & 7;
  int r = blockIdx.x;
  int tid = threadIdx.x;
  int topl = g_top[bh * u + r];
  const float* base = h + (size_t)b * L * DD + hh * 64;
  if (tid < 64) qr[tid] = base[(size_t)topl * DD + tid];
  __syncthreads();

  float m = -INFINITY, sum = 0.f;
  float acc[64];
  #pragma unroll
  for (int d = 0; d < 64; d++) acc[d] = 0.f;

  for (int l = tid; l < L; l += 256) {
    const float4* krow = (const float4*)(base + (size_t)l * DD);
    float kv[64];
    #pragma unroll
    for (int q4 = 0; q4 < 16; q4++) {
      float4 t4 = krow[q4];
      kv[q4*4+0] = t4.x; kv[q4*4+1] = t4.y; kv[q4*4+2] = t4.z; kv[q4*4+3] = t4.w;
    }
    float dot = 0.f;
    #pragma unroll
    for (int d = 0; d < 64; d++) dot += qr[d] * kv[d];
    float s = dot * 0.125f;
    float mn = fmaxf(m, s);
    float c = __expf(m - mn);
    float p = __expf(s - mn);
    sum = sum * c + p;
    #pragma unroll
    for (int d = 0; d < 64; d++) acc[d] = acc[d] * c + p * kv[d];
    m = mn;
  }
  #pragma unroll
  for (int o = 16; o; o >>= 1) {
    float mo = __shfl_xor_sync(0xffffffffu, m, o);
    float so = __shfl_xor_sync(0xffffffffu, sum, o);
    float mn = fmaxf(m, mo);
    float ca = __expf(m - mn), cb = __expf(mo - mn);
    sum = sum * ca + so * cb;
    #pragma unroll
    for (int d = 0; d < 64; d++) {
      float ao = __shfl_xor_sync(0xffffffffu, acc[d], o);
      acc[d] = acc[d] * ca + ao * cb;
    }
    m = mn;
  }
  if ((tid & 31) == 0) {
    int w = tid >> 5;
    cm[w] = m; cs[w] = sum;
    #pragma unroll
    for (int d = 0; d < 64; d++) cacc[w][d] = acc[d];
  }
  __syncthreads();
  if (tid == 0) {
    float M0 = cm[0];
    #pragma unroll
    for (int w = 1; w < 8; w++) M0 = fmaxf(M0, cm[w]);
    float S = 0.f;
    #pragma unroll
    for (int w = 0; w < 8; w++) {
      float c = __expf(cm[w] - M0);
      cw[w] = c; S += cs[w] * c;
    }
    cS = S;
  }
  __syncthreads();
  if (tid < 64) {
    float a = 0.f;
    #pragma unroll
    for (int w = 0; w < 8; w++) a += cacc[w][tid] * cw[w];
    g_ctx[((size_t)(bh * u + r)) * 64 + tid] = a / cS;
  }
}

// ------------------- block reduce helper (128 threads) ---------------------
__device__ __forceinline__ float blocksum128(float v, float* sred)
{
  #pragma unroll
  for (int o = 16; o; o >>= 1) v += __shfl_xor_sync(0xffffffffu, v, o);
  if ((threadIdx.x & 31) == 0) sred[threadIdx.x >> 5] = v;
  __syncthreads();
  float t = sred[0] + sred[1] + sred[2] + sred[3];
  __syncthreads();
  return t;
}

// ------------------- assemble attention out + residual + LN1 ---------------
__global__ __launch_bounds__(128) void assemble_ln1_kernel(
    const float* __restrict__ hin, float* __restrict__ xout,
    const float* __restrict__ gamma, const float* __restrict__ beta,
    int L, int u)
{
  __shared__ float sred[4];
  int row = blockIdx.x;
  int b = row / L, l = row - b * L;
  int tid = threadIdx.x;
  float v[4];
  #pragma unroll
  for (int i = 0; i < 4; i++) {
    int e = i * 128 + tid;
    int hh = e >> 6, dd = e & 63;
    int bh = b * 8 + hh;
    int r = g_rowmap[(size_t)bh * L + l];
    float nv = (r >= 0) ? g_ctx[((size_t)(bh * u + r)) * 64 + dd]
                        : g_qmean[bh * 64 + dd];
    v[i] = hin[(size_t)row * DD + e] + nv;
  }
  float s = blocksum128(v[0] + v[1] + v[2] + v[3], sred);
  float mu = s * (1.0f / 512.0f);
  float vs = 0.f;
  #pragma unroll
  for (int i = 0; i < 4; i++) { float d = v[i] - mu; vs += d * d; }
  vs = blocksum128(vs, sred);
  float rstd = rsqrtf(vs * (1.0f / 512.0f) + LN_EPS);
  #pragma unroll
  for (int i = 0; i < 4; i++) {
    int e = i * 128 + tid;
    xout[(size_t)row * DD + e] = (v[i] - mu) * rstd * gamma[e] + beta[e];
  }
}

// ------------------- residual + LN2 ----------------------------------------
__global__ __launch_bounds__(128) void ln2_kernel(
    const float* __restrict__ xin, const float* __restrict__ zin,
    float* __restrict__ outp,
    const float* __restrict__ gamma, const float* __restrict__ beta)
{
  __shared__ float sred[4];
  size_t row = blockIdx.x;
  int tid = threadIdx.x;
  float v[4];
  #pragma unroll
  for (int i = 0; i < 4; i++) {
    int e = i * 128 + tid;
    v[i] = xin[row * DD + e] + zin[row * DD + e];
  }
  float s = blocksum128(v[0] + v[1] + v[2] + v[3], sred);
  float mu = s * (1.0f / 512.0f);
  float vs = 0.f;
  #pragma unroll
  for (int i = 0; i < 4; i++) { float d = v[i] - mu; vs += d * d; }
  vs = blocksum128(vs, sred);
  float rstd = rsqrtf(vs * (1.0f / 512.0f) + LN_EPS);
  #pragma unroll
  for (int i = 0; i < 4; i++) {
    int e = i * 128 + tid;
    outp[row * DD + e] = (v[i] - mu) * rstd * gamma[e] + beta[e];
  }
}

// ------------------- distil: mean of row pairs ------------------------------
__global__ void distil_kernel(const float* __restrict__ in, float* __restrict__ outp, int L2)
{
  int o = blockIdx.x * 256 + threadIdx.x;
  int total = BB * L2 * DD;
  if (o >= total) return;
  int e = o & 511; int rest = o >> 9;
  int l2 = rest % L2; int b = rest / L2;
  size_t base = ((size_t)b * (2 * L2) + 2 * l2) * DD + e;
  outp[o] = 0.5f * (in[base] + in[base + DD]);
}

// ------------------- SGEMM: C = A(M,K) * B(N,K)^T + epilogue ----------------
// EPI: 0 = +bias, 1 = +bias then exact GELU, 2 = +bias +positional encoding
template<int EPI>
__global__ __launch_bounds__(256, 2) void sgemm_k(
    const float* __restrict__ A, const float* __restrict__ Bm,
    const float* __restrict__ bias, float* __restrict__ C,
    int M, int N, int K, int Lmask)
{
  __shared__ float As[16][132];
  __shared__ float Bs[16][132];
  const int bm = blockIdx.y * 128, bn = blockIdx.x * 128;
  const int t = threadIdx.x;
  const int lr = t >> 2;
  const int lc = (t & 3) << 2;
  const int tx = t & 15, ty = t >> 4;
  float acc[8][8];
  #pragma unroll
  for (int i = 0; i < 8; i++)
    #pragma unroll
    for (int j = 0; j < 8; j++) acc[i][j] = 0.f;

  const float* Ap = A + (size_t)(bm + lr) * K + lc;
  const float* Bp = Bm + (size_t)(bn + lr) * K + lc;

  for (int k0 = 0; k0 < K; k0 += 16) {
    float4 a0 = *(const float4*)(Ap + k0);
    float4 a1 = *(const float4*)(Ap + (size_t)64 * K + k0);
    float4 b0 = *(const float4*)(Bp + k0);
    float4 b1 = *(const float4*)(Bp + (size_t)64 * K + k0);
    __syncthreads();
    As[lc+0][lr] = a0.x; As[lc+1][lr] = a0.y; As[lc+2][lr] = a0.z; As[lc+3][lr] = a0.w;
    As[lc+0][lr+64] = a1.x; As[lc+1][lr+64] = a1.y; As[lc+2][lr+64] = a1.z; As[lc+3][lr+64] = a1.w;
    Bs[lc+0][lr] = b0.x; Bs[lc+1][lr] = b0.y; Bs[lc+2][lr] = b0.z; Bs[lc+3][lr] = b0.w;
    Bs[lc+0][lr+64] = b1.x; Bs[lc+1][lr+64] = b1.y; Bs[lc+2][lr+64] = b1.z; Bs[lc+3][lr+64] = b1.w;
    __syncthreads();
    #pragma unroll
    for (int kk = 0; kk < 16; kk++) {
      float4 av0 = *(const float4*)&As[kk][ty * 8];
      float4 av1 = *(const float4*)&As[kk][ty * 8 + 4];
      float4 bv0 = *(const float4*)&Bs[kk][tx * 8];
      float4 bv1 = *(const float4*)&Bs[kk][tx * 8 + 4];
      float a[8] = {av0.x, av0.y, av0.z, av0.w, av1.x, av1.y, av1.z, av1.w};
      float bb[8] = {bv0.x, bv0.y, bv0.z, bv0.w, bv1.x, bv1.y, bv1.z, bv1.w};
      #pragma unroll
      for (int i = 0; i < 8; i++)
        #pragma unroll
        for (int j = 0; j < 8; j++) acc[i][j] += a[i] * bb[j];
    }
  }

  #pragma unroll
  for (int i = 0; i < 8; i++) {
    int row = bm + ty * 8 + i;
    #pragma unroll
    for (int j = 0; j < 8; j++) {
      int col = bn + tx * 8 + j;
      float v = acc[i][j] + bias[col];
      if (EPI == 1) v = 0.5f * v * (1.f + erff(v * 0.70710678118654752f));
      if (EPI == 2) {
        int l = row & Lmask;
        float df = expf((float)(col & ~1) * (-0.017988946039015984f));
        float arg = (float)l * df;
        v += (col & 1) ? cosf(arg) : sinf(arg);
      }
      C[(size_t)row * N + col] = v;
    }
  }
}

// ------------------- host: layer key derivation ----------------------------
static void layer_key(int i, unsigned &k0, unsigned &k1)
{
  unsigned a = 0u, b = (unsigned)i;
  threefry2x32(0u, 42u, a, b);               // fold_in(key(42), i)
#if JAX_PARTITIONABLE
  unsigned c = 0u, d = 1u;
  threefry2x32(a, b, c, d);                  // split foldlike: k2 = TF(key,(0,1))
  k0 = c; k1 = d;
#else
  unsigned c0 = 0u, c1 = 2u; threefry2x32(a, b, c0, c1);
  unsigned d0 = 1u, d1 = 3u; threefry2x32(a, b, d0, d1);
  k0 = c1; k1 = d1;                          // legacy split: second-row words
#endif
}

extern "C" void kernel_launch(void* const* d_in, const int* in_sizes, int n_in,
                              void* d_out, int out_size)
{
  const float* x     = (const float*)d_in[0];
  const float* emb_w = (const float*)d_in[1];
  const float* emb_b = (const float*)d_in[2];
  const float* ln1_s = (const float*)d_in[3];
  const float* ln1_b = (const float*)d_in[4];
  const float* w1    = (const float*)d_in[5];
  const float* b1    = (const float*)d_in[6];
  const float* w2    = (const float*)d_in[7];
  const float* b2    = (const float*)d_in[8];
  const float* ln2_s = (const float*)d_in[9];
  const float* ln2_b = (const float*)d_in[10];
  const float* out_w = (const float*)d_in[11];
  const float* out_b = (const float*)d_in[12];
  float* out = (float*)d_out;

  float *ph, *poth, *px, *pz, *py;
  cudaGetSymbolAddress((void**)&ph,   g_h);
  cudaGetSymbolAddress((void**)&poth, g_h2);
  cudaGetSymbolAddress((void**)&px,   g_x);
  cudaGetSymbolAddress((void**)&pz,   g_z);
  cudaGetSymbolAddress((void**)&py,   g_y);

  // Embed: h = x @ emb_w^T + emb_b + PE   (M=32768, N=512, K=64)
  {
    int M = BB * L0;
    sgemm_k<2><<<dim3(DD / 128, M / 128), 256>>>(x, emb_w, emb_b, ph, M, DD, 64, L0 - 1);
  }

  int L = L0;
  float* cur = ph;   // layer input
  for (int i = 0; i < 3; i++) {
    int u = (i == 0) ? 45 : (i == 1) ? 40 : 35;
    int M = BB * L;
    unsigned k0, k1; layer_key(i, k0, k1);
    int total = L * u;
#if JAX_PARTITIONABLE
    idx_part<<<(total + 255) / 256, 256>>>(k0, k1, total, L - 1);
#else
    idx_leg<<<((total >> 1) + 255) / 256, 256>>>(k0, k1, total, L - 1);
#endif
    prob_m_kernel<<<dim3(L / 8, 64), 256>>>(cur, L, u, 1.0f / (float)L);
    topk_kernel<<<64, 256>>>(L, u);
    qmean_kernel<<<64, 512>>>(cur, L);
    ctx_kernel<<<dim3(u, 64), 256>>>(cur, L, u);
    assemble_ln1_kernel<<<M, 128>>>(cur, px, ln1_s + i * DD, ln1_b + i * DD, L, u);

    sgemm_k<1><<<dim3(DFF / 128, M / 128), 256>>>(px, w1 + (size_t)i * DFF * DD,
                                                  b1 + i * DFF, py, M, DFF, DD, 0);
    sgemm_k<0><<<dim3(DD / 128, M / 128), 256>>>(py, w2 + (size_t)i * DD * DFF,
                                                 b2 + i * DD, pz, M, DD, DFF, 0);
    ln2_kernel<<<M, 128>>>(px, pz, poth, ln2_s + i * DD, ln2_b + i * DD);

    if (i < 2) {
      int L2 = L / 2;
      int tot = BB * L2 * DD;
      distil_kernel<<<(tot + 255) / 256, 256>>>(poth, cur, L2);
      L = L2;
    }
  }

  // Final projection: out = h @ out_w^T + out_b  (M=8192, N=512, K=512)
  {
    int M = BB * L;   // L = 1024
    sgemm_k<0><<<dim3(DD / 128, M / 128), 256>>>(poth, out_w, out_b, out, M, DD, DD, 0);
  }
}

// round 3
// speedup vs baseline: 1.1437x; 1.1437x over previous
#include <cuda_runtime.h>
#include <math.h>
#include <stdint.h>

#define BB 8
#define DD 512
#define DFF 2048
#define L0 4096
#define UMAX 45
#define LN_EPS 1e-5f

// ------------------- scratch (device globals; no allocs) -------------------
__device__ __align__(16) float g_h  [BB*L0*DD];
__device__ __align__(16) float g_h2 [BB*L0*DD];
__device__ __align__(16) float g_x  [BB*L0*DD];
__device__ __align__(16) float g_z  [BB*L0*DD];
__device__ __align__(16) unsigned g_xhi[BB*L0*DD];
__device__ __align__(16) unsigned g_xlo[BB*L0*DD];
__device__ __align__(16) unsigned g_yhi[BB*L0*DFF];
__device__ __align__(16) unsigned g_ylo[BB*L0*DFF];
__device__ __align__(16) unsigned g_w1hi[3*DFF*DD];
__device__ __align__(16) unsigned g_w1lo[3*DFF*DD];
__device__ __align__(16) unsigned g_w2hi[3*DD*DFF];
__device__ __align__(16) unsigned g_w2lo[3*DD*DFF];
__device__ __align__(16) unsigned g_owhi[DD*DD];
__device__ __align__(16) unsigned g_owlo[DD*DD];
__device__ __align__(16) float g_M  [BB*8*L0];
__device__ __align__(16) int   g_idx[L0*UMAX];
__device__ __align__(16) int   g_top[BB*8*UMAX];
__device__ __align__(16) int   g_rowmap[BB*8*L0];
__device__ __align__(16) float g_ctx[BB*8*UMAX*64];
__device__ __align__(16) float g_qmean[BB*8*64];

// ------------------- tf32 helpers ------------------------------------------
__device__ __forceinline__ unsigned cvt_tf32(float f)
{
  unsigned r;
  asm("cvt.rna.tf32.f32 %0, %1;" : "=r"(r) : "f"(f));
  return r;
}
__device__ __forceinline__ void split_tf32(float v, unsigned &hi, unsigned &lo)
{
  hi = cvt_tf32(v);
  float hf = __uint_as_float(hi);
  lo = cvt_tf32(v - hf);
}

// ------------------- threefry2x32 (JAX-compatible) -------------------------
#define TF_R(x0,x1,r) { x0 += x1; x1 = ((x1 << (r)) | (x1 >> (32-(r)))); x1 ^= x0; }
__host__ __device__ inline void threefry2x32(unsigned ks0, unsigned ks1,
                                             unsigned &x0, unsigned &x1)
{
  unsigned ks2 = ks0 ^ ks1 ^ 0x1BD11BDAu;
  x0 += ks0; x1 += ks1;
  TF_R(x0,x1,13) TF_R(x0,x1,15) TF_R(x0,x1,26) TF_R(x0,x1,6)
  x0 += ks1; x1 += ks2 + 1u;
  TF_R(x0,x1,17) TF_R(x0,x1,29) TF_R(x0,x1,16) TF_R(x0,x1,24)
  x0 += ks2; x1 += ks0 + 2u;
  TF_R(x0,x1,13) TF_R(x0,x1,15) TF_R(x0,x1,26) TF_R(x0,x1,6)
  x0 += ks0; x1 += ks1 + 3u;
  TF_R(x0,x1,17) TF_R(x0,x1,29) TF_R(x0,x1,16) TF_R(x0,x1,24)
  x0 += ks1; x1 += ks2 + 4u;
  TF_R(x0,x1,13) TF_R(x0,x1,15) TF_R(x0,x1,26) TF_R(x0,x1,6)
  x0 += ks2; x1 += ks0 + 5u;
}

__global__ void idx_part(unsigned k0, unsigned k1, int total, int mask)
{
  int t = blockIdx.x * 256 + threadIdx.x;
  if (t >= total) return;
  unsigned x0 = 0u, x1 = (unsigned)t;
  threefry2x32(k0, k1, x0, x1);
  g_idx[t] = (int)((x0 ^ x1) & (unsigned)mask);
}

// ------------------- weight split ------------------------------------------
__global__ void wsplit_kernel(const float* __restrict__ w,
                              unsigned* __restrict__ hi, unsigned* __restrict__ lo, int n)
{
  int i = blockIdx.x * 256 + threadIdx.x;
  if (i >= n) return;
  unsigned h, l;
  split_tf32(w[i], h, l);
  hi[i] = h; lo[i] = l;
}

// ------------------- M = max_s qk - sum_s qk / L ----------------------------
__global__ __launch_bounds__(256) void prob_m_kernel(
    const float* __restrict__ h, int L, int u, float invL)
{
  __shared__ float qs[8][64];
  int bh = blockIdx.y; int b = bh >> 3, hh = bh & 7;
  int warp = threadIdx.x >> 5, lane = threadIdx.x & 31;
  int l = blockIdx.x * 8 + warp;
  const float* base = h + (size_t)b * L * DD + hh * 64;
  const float* qrow = base + (size_t)l * DD;
  qs[warp][lane]      = qrow[lane];
  qs[warp][lane + 32] = qrow[lane + 32];
  __syncwarp();
  float mx = -INFINITY, sm = 0.f;
  for (int s = lane; s < u; s += 32) {
    int kl = g_idx[l * u + s];
    const float4* krow = (const float4*)(base + (size_t)kl * DD);
    float dot = 0.f;
    #pragma unroll
    for (int q4 = 0; q4 < 16; q4++) {
      float4 kv = krow[q4];
      dot += qs[warp][q4*4+0]*kv.x + qs[warp][q4*4+1]*kv.y
           + qs[warp][q4*4+2]*kv.z + qs[warp][q4*4+3]*kv.w;
    }
    mx = fmaxf(mx, dot); sm += dot;
  }
  #pragma unroll
  for (int o = 16; o; o >>= 1) {
    mx = fmaxf(mx, __shfl_xor_sync(0xffffffffu, mx, o));
    sm += __shfl_xor_sync(0xffffffffu, sm, o);
  }
  if (lane == 0) g_M[(size_t)bh * L + l] = mx - sm * invL;
}

// ------------------- top-k (iterative argmax, lower-index tiebreak) --------
__global__ __launch_bounds__(256) void topk_kernel(int L, int u)
{
  __shared__ float sM[L0];
  __shared__ float sval[256];
  __shared__ int   sidx[256];
  int bh = blockIdx.x;
  int tid = threadIdx.x;
  for (int l = tid; l < L; l += 256) {
    sM[l] = g_M[(size_t)bh * L + l];
    g_rowmap[(size_t)bh * L + l] = -1;
  }
  __syncthreads();
  for (int r = 0; r < u; r++) {
    float bv = -INFINITY; int bi = 0x7fffffff;
    for (int l = tid; l < L; l += 256) {
      float v = sM[l];
      if (v > bv || (v == bv && l < bi)) { bv = v; bi = l; }
    }
    sval[tid] = bv; sidx[tid] = bi;
    __syncthreads();
    for (int st = 128; st > 0; st >>= 1) {
      if (tid < st) {
        float v2 = sval[tid + st]; int i2 = sidx[tid + st];
        if (v2 > sval[tid] || (v2 == sval[tid] && i2 < sidx[tid])) {
          sval[tid] = v2; sidx[tid] = i2;
        }
      }
      __syncthreads();
    }
    if (tid == 0) {
      int sel = sidx[0];
      g_top[bh * u + r] = sel;
      g_rowmap[(size_t)bh * L + sel] = r;
      sM[sel] = -INFINITY;
    }
    __syncthreads();
  }
}

// ------------------- qmean over L per (b,h,d) -------------------------------
__global__ __launch_bounds__(512) void qmean_kernel(const float* __restrict__ h, int L)
{
  __shared__ float part[512];
  int bh = blockIdx.x; int b = bh >> 3, hh = bh & 7;
  int tid = threadIdx.x; int d = tid & 63; int p = tid >> 6;
  const float* base = h + (size_t)b * L * DD + hh * 64;
  float s = 0.f;
  for (int l = p; l < L; l += 8) s += base[(size_t)l * DD + d];
  part[tid] = s;
  __syncthreads();
  if (p == 0) {
    float t = 0.f;
    #pragma unroll
    for (int q = 0; q < 8; q++) t += part[q * 64 + d];
    g_qmean[bh * 64 + d] = t / (float)L;
  }
}

// ------------------- ctx_top: online softmax over all L keys ---------------
__global__ __launch_bounds__(256) void ctx_kernel(const float* __restrict__ h, int L, int u)
{
  __shared__ float qr[64];
  __shared__ float cm[8], cs[8], cw[8], cS;
  __shared__ float cacc[8][64];
  int bh = blockIdx.y; int b = bh >> 3, hh = bh & 7;
  int r = blockIdx.x;
  int tid = threadIdx.x;
  int topl = g_top[bh * u + r];
  const float* base = h + (size_t)b * L * DD + hh * 64;
  if (tid < 64) qr[tid] = base[(size_t)topl * DD + tid];
  __syncthreads();

  float m = -INFINITY, sum = 0.f;
  float acc[64];
  #pragma unroll
  for (int d = 0; d < 64; d++) acc[d] = 0.f;

  for (int l = tid; l < L; l += 256) {
    const float4* krow = (const float4*)(base + (size_t)l * DD);
    float kv[64];
    #pragma unroll
    for (int q4 = 0; q4 < 16; q4++) {
      float4 t4 = krow[q4];
      kv[q4*4+0] = t4.x; kv[q4*4+1] = t4.y; kv[q4*4+2] = t4.z; kv[q4*4+3] = t4.w;
    }
    float dot = 0.f;
    #pragma unroll
    for (int d = 0; d < 64; d++) dot += qr[d] * kv[d];
    float s = dot * 0.125f;
    float mn = fmaxf(m, s);
    float c = __expf(m - mn);
    float p = __expf(s - mn);
    sum = sum * c + p;
    #pragma unroll
    for (int d = 0; d < 64; d++) acc[d] = acc[d] * c + p * kv[d];
    m = mn;
  }
  #pragma unroll
  for (int o = 16; o; o >>= 1) {
    float mo = __shfl_xor_sync(0xffffffffu, m, o);
    float so = __shfl_xor_sync(0xffffffffu, sum, o);
    float mn = fmaxf(m, mo);
    float ca = __expf(m - mn), cb = __expf(mo - mn);
    sum = sum * ca + so * cb;
    #pragma unroll
    for (int d = 0; d < 64; d++) {
      float ao = __shfl_xor_sync(0xffffffffu, acc[d], o);
      acc[d] = acc[d] * ca + ao * cb;
    }
    m = mn;
  }
  if ((tid & 31) == 0) {
    int w = tid >> 5;
    cm[w] = m; cs[w] = sum;
    #pragma unroll
    for (int d = 0; d < 64; d++) cacc[w][d] = acc[d];
  }
  __syncthreads();
  if (tid == 0) {
    float M0 = cm[0];
    #pragma unroll
    for (int w = 1; w < 8; w++) M0 = fmaxf(M0, cm[w]);
    float S = 0.f;
    #pragma unroll
    for (int w = 0; w < 8; w++) {
      float c = __expf(cm[w] - M0);
      cw[w] = c; S += cs[w] * c;
    }
    cS = S;
  }
  __syncthreads();
  if (tid < 64) {
    float a = 0.f;
    #pragma unroll
    for (int w = 0; w < 8; w++) a += cacc[w][tid] * cw[w];
    g_ctx[((size_t)(bh * u + r)) * 64 + tid] = a / cS;
  }
}

// ------------------- block reduce helper (128 threads) ---------------------
__device__ __forceinline__ float blocksum128(float v, float* sred)
{
  #pragma unroll
  for (int o = 16; o; o >>= 1) v += __shfl_xor_sync(0xffffffffu, v, o);
  if ((threadIdx.x & 31) == 0) sred[threadIdx.x >> 5] = v;
  __syncthreads();
  float t = sred[0] + sred[1] + sred[2] + sred[3];
  __syncthreads();
  return t;
}

// ------------------- assemble attention out + residual + LN1 + tf32 split --
__global__ __launch_bounds__(128) void assemble_ln1_kernel(
    const float* __restrict__ hin, float* __restrict__ xout,
    unsigned* __restrict__ xhi, unsigned* __restrict__ xlo,
    const float* __restrict__ gamma, const float* __restrict__ beta,
    int L, int u)
{
  __shared__ float sred[4];
  int row = blockIdx.x;
  int b = row / L, l = row - b * L;
  int tid = threadIdx.x;
  float v[4];
  #pragma unroll
  for (int i = 0; i < 4; i++) {
    int e = i * 128 + tid;
    int hh = e >> 6, dd = e & 63;
    int bh = b * 8 + hh;
    int r = g_rowmap[(size_t)bh * L + l];
    float nv = (r >= 0) ? g_ctx[((size_t)(bh * u + r)) * 64 + dd]
                        : g_qmean[bh * 64 + dd];
    v[i] = hin[(size_t)row * DD + e] + nv;
  }
  float s = blocksum128(v[0] + v[1] + v[2] + v[3], sred);
  float mu = s * (1.0f / 512.0f);
  float vs = 0.f;
  #pragma unroll
  for (int i = 0; i < 4; i++) { float d = v[i] - mu; vs += d * d; }
  vs = blocksum128(vs, sred);
  float rstd = rsqrtf(vs * (1.0f / 512.0f) + LN_EPS);
  #pragma unroll
  for (int i = 0; i < 4; i++) {
    int e = i * 128 + tid;
    float o = (v[i] - mu) * rstd * gamma[e] + beta[e];
    xout[(size_t)row * DD + e] = o;
    unsigned h32, l32;
    split_tf32(o, h32, l32);
    xhi[(size_t)row * DD + e] = h32;
    xlo[(size_t)row * DD + e] = l32;
  }
}

// ------------------- residual + LN2 (optional tf32 split) ------------------
__global__ __launch_bounds__(128) void ln2_kernel(
    const float* __restrict__ xin, const float* __restrict__ zin,
    float* __restrict__ outp,
    unsigned* __restrict__ ohi, unsigned* __restrict__ olo,
    const float* __restrict__ gamma, const float* __restrict__ beta)
{
  __shared__ float sred[4];
  size_t row = blockIdx.x;
  int tid = threadIdx.x;
  float v[4];
  #pragma unroll
  for (int i = 0; i < 4; i++) {
    int e = i * 128 + tid;
    v[i] = xin[row * DD + e] + zin[row * DD + e];
  }
  float s = blocksum128(v[0] + v[1] + v[2] + v[3], sred);
  float mu = s * (1.0f / 512.0f);
  float vs = 0.f;
  #pragma unroll
  for (int i = 0; i < 4; i++) { float d = v[i] - mu; vs += d * d; }
  vs = blocksum128(vs, sred);
  float rstd = rsqrtf(vs * (1.0f / 512.0f) + LN_EPS);
  #pragma unroll
  for (int i = 0; i < 4; i++) {
    int e = i * 128 + tid;
    float o = (v[i] - mu) * rstd * gamma[e] + beta[e];
    outp[row * DD + e] = o;
    if (ohi) {
      unsigned h32, l32;
      split_tf32(o, h32, l32);
      ohi[row * DD + e] = h32;
      olo[row * DD + e] = l32;
    }
  }
}

// ------------------- distil: mean of row pairs ------------------------------
__global__ void distil_kernel(const float* __restrict__ in, float* __restrict__ outp, int L2)
{
  int o = blockIdx.x * 256 + threadIdx.x;
  int total = BB * L2 * DD;
  if (o >= total) return;
  int e = o & 511; int rest = o >> 9;
  int l2 = rest % L2; int b = rest / L2;
  size_t base = ((size_t)b * (2 * L2) + 2 * l2) * DD + e;
  outp[o] = 0.5f * (in[base] + in[base + DD]);
}

// ------------------- SIMT SGEMM (embed only): C = A*B^T + bias + PE --------
__global__ __launch_bounds__(256, 2) void sgemm_embed(
    const float* __restrict__ A, const float* __restrict__ Bm,
    const float* __restrict__ bias, float* __restrict__ C,
    int M, int N, int K, int Lmask)
{
  __shared__ float As[16][132];
  __shared__ float Bs[16][132];
  const int bm = blockIdx.y * 128, bn = blockIdx.x * 128;
  const int t = threadIdx.x;
  const int lr = t >> 2;
  const int lc = (t & 3) << 2;
  const int tx = t & 15, ty = t >> 4;
  float acc[8][8];
  #pragma unroll
  for (int i = 0; i < 8; i++)
    #pragma unroll
    for (int j = 0; j < 8; j++) acc[i][j] = 0.f;

  const float* Ap = A + (size_t)(bm + lr) * K + lc;
  const float* Bp = Bm + (size_t)(bn + lr) * K + lc;

  for (int k0 = 0; k0 < K; k0 += 16) {
    float4 a0 = *(const float4*)(Ap + k0);
    float4 a1 = *(const float4*)(Ap + (size_t)64 * K + k0);
    float4 b0 = *(const float4*)(Bp + k0);
    float4 b1 = *(const float4*)(Bp + (size_t)64 * K + k0);
    __syncthreads();
    As[lc+0][lr] = a0.x; As[lc+1][lr] = a0.y; As[lc+2][lr] = a0.z; As[lc+3][lr] = a0.w;
    As[lc+0][lr+64] = a1.x; As[lc+1][lr+64] = a1.y; As[lc+2][lr+64] = a1.z; As[lc+3][lr+64] = a1.w;
    Bs[lc+0][lr] = b0.x; Bs[lc+1][lr] = b0.y; Bs[lc+2][lr] = b0.z; Bs[lc+3][lr] = b0.w;
    Bs[lc+0][lr+64] = b1.x; Bs[lc+1][lr+64] = b1.y; Bs[lc+2][lr+64] = b1.z; Bs[lc+3][lr+64] = b1.w;
    __syncthreads();
    #pragma unroll
    for (int kk = 0; kk < 16; kk++) {
      float4 av0 = *(const float4*)&As[kk][ty * 8];
      float4 av1 = *(const float4*)&As[kk][ty * 8 + 4];
      float4 bv0 = *(const float4*)&Bs[kk][tx * 8];
      float4 bv1 = *(const float4*)&Bs[kk][tx * 8 + 4];
      float a[8] = {av0.x, av0.y, av0.z, av0.w, av1.x, av1.y, av1.z, av1.w};
      float bb[8] = {bv0.x, bv0.y, bv0.z, bv0.w, bv1.x, bv1.y, bv1.z, bv1.w};
      #pragma unroll
      for (int i = 0; i < 8; i++)
        #pragma unroll
        for (int j = 0; j < 8; j++) acc[i][j] += a[i] * bb[j];
    }
  }

  #pragma unroll
  for (int i = 0; i < 8; i++) {
    int row = bm + ty * 8 + i;
    #pragma unroll
    for (int j = 0; j < 8; j++) {
      int col = bn + tx * 8 + j;
      float v = acc[i][j] + bias[col];
      int l = row & Lmask;
      float df = expf((float)(col & ~1) * (-0.017988946039015984f));
      float arg = (float)l * df;
      v += (col & 1) ? cosf(arg) : sinf(arg);
      C[(size_t)row * N + col] = v;
    }
  }
}

// ------------------- 3xTF32 tensor-core GEMM --------------------------------
// C(M,N) = A(M,K) * B(N,K)^T with fp32-accurate 3-pass tf32 mma.
// EPI 0: C = acc + bias (fp32 out)
// EPI 1: v = gelu(acc + bias); write tf32 split (Chi, Clo) only
#define KC 16
#define LDP 20                  // padded k stride
#define PLANE_U32 (128*LDP)     // 2560
#define STG_U32 (4*PLANE_U32)   // 10240 (40KB)

__device__ __forceinline__ void mma_tf32(float* c, const unsigned* a, const unsigned* b)
{
  asm volatile(
    "mma.sync.aligned.m16n8k8.row.col.f32.tf32.tf32.f32 "
    "{%0,%1,%2,%3},{%4,%5,%6,%7},{%8,%9},{%0,%1,%2,%3};\n"
    : "+f"(c[0]), "+f"(c[1]), "+f"(c[2]), "+f"(c[3])
    : "r"(a[0]), "r"(a[1]), "r"(a[2]), "r"(a[3]), "r"(b[0]), "r"(b[1]));
}

template<int EPI>
__global__ __launch_bounds__(256, 2) void mma_gemm(
    const unsigned* __restrict__ Ahi, const unsigned* __restrict__ Alo,
    const unsigned* __restrict__ Bhi, const unsigned* __restrict__ Blo,
    const float* __restrict__ bias,
    float* __restrict__ Cf, unsigned* __restrict__ Chi, unsigned* __restrict__ Clo,
    int M, int N, int K)
{
  extern __shared__ unsigned smu[];
  const int tid = threadIdx.x;
  const int bm = blockIdx.y * 128, bn = blockIdx.x * 128;
  const int lane = tid & 31;
  const int g = lane >> 2, t4 = lane & 3;
  const int warp = tid >> 5;
  const int wm = warp >> 2, wn = warp & 3;      // warps 2(m) x 4(n)
  const int moff = wm * 64, noff = wn * 32;

  float acc[4][4][4];
  #pragma unroll
  for (int i = 0; i < 4; i++)
    #pragma unroll
    for (int j = 0; j < 4; j++)
      #pragma unroll
      for (int q = 0; q < 4; q++) acc[i][j][q] = 0.f;

  const unsigned* gp0 = Ahi; const unsigned* gp1 = Alo;
  const unsigned* gp2 = Bhi; const unsigned* gp3 = Blo;

  const int KT = K / KC;

  // ---- prefetch stage `s` for k-tile `kt` ----
  #define PREFETCH(kt, s) do {                                                   \
    int k0_ = (kt) * KC;                                                         \
    const unsigned* srcs_[4] = {                                                 \
      gp0 + (size_t)bm * K + k0_, gp1 + (size_t)bm * K + k0_,                    \
      gp2 + (size_t)bn * K + k0_, gp3 + (size_t)bn * K + k0_ };                  \
    _Pragma("unroll")                                                            \
    for (int p_ = 0; p_ < 4; p_++) {                                             \
      unsigned* dstp_ = smu + (s) * STG_U32 + p_ * PLANE_U32;                    \
      _Pragma("unroll")                                                          \
      for (int j_ = 0; j_ < 2; j_++) {                                           \
        int idx_ = j_ * 256 + tid;                                               \
        int row_ = idx_ >> 2, kq_ = (idx_ & 3) << 2;                             \
        unsigned sa_ = (unsigned)__cvta_generic_to_shared(dstp_ + row_ * LDP + kq_); \
        const unsigned* ga_ = srcs_[p_] + (size_t)row_ * K + kq_;                \
        asm volatile("cp.async.ca.shared.global [%0], [%1], 16;\n"               \
                     :: "r"(sa_), "l"(ga_));                                     \
      }                                                                          \
    }                                                                            \
    asm volatile("cp.async.commit_group;\n");                                    \
  } while (0)

  PREFETCH(0, 0);

  for (int kt = 0; kt < KT; kt++) {
    asm volatile("cp.async.wait_group 0;\n");
    __syncthreads();
    if (kt + 1 < KT) PREFETCH(kt + 1, (kt + 1) & 1);

    const unsigned* Sahi = smu + (kt & 1) * STG_U32;
    const unsigned* Salo = Sahi + PLANE_U32;
    const unsigned* Sbhi = Sahi + 2 * PLANE_U32;
    const unsigned* Sblo = Sahi + 3 * PLANE_U32;

    #pragma unroll
    for (int ks = 0; ks < 2; ks++) {
      int kb = ks * 8;
      unsigned bh[4][2], bl[4][2];
      #pragma unroll
      for (int tn = 0; tn < 4; tn++) {
        int n = noff + tn * 8 + g;
        bh[tn][0] = Sbhi[n * LDP + kb + t4];
        bh[tn][1] = Sbhi[n * LDP + kb + t4 + 4];
        bl[tn][0] = Sblo[n * LDP + kb + t4];
        bl[tn][1] = Sblo[n * LDP + kb + t4 + 4];
      }
      #pragma unroll
      for (int tm = 0; tm < 4; tm++) {
        int m0 = moff + tm * 16 + g;
        unsigned ah[4], al[4];
        ah[0] = Sahi[m0 * LDP + kb + t4];
        ah[1] = Sahi[(m0 + 8) * LDP + kb + t4];
        ah[2] = Sahi[m0 * LDP + kb + t4 + 4];
        ah[3] = Sahi[(m0 + 8) * LDP + kb + t4 + 4];
        al[0] = Salo[m0 * LDP + kb + t4];
        al[1] = Salo[(m0 + 8) * LDP + kb + t4];
        al[2] = Salo[m0 * LDP + kb + t4 + 4];
        al[3] = Salo[(m0 + 8) * LDP + kb + t4 + 4];
        #pragma unroll
        for (int tn = 0; tn < 4; tn++) {
          mma_tf32(acc[tm][tn], ah, bh[tn]);
          mma_tf32(acc[tm][tn], ah, bl[tn]);
          mma_tf32(acc[tm][tn], al, bh[tn]);
        }
      }
    }
    __syncthreads();
  }

  // ---- epilogue ----
  #pragma unroll
  for (int tm = 0; tm < 4; tm++) {
    int r0 = bm + moff + tm * 16 + g;
    int r1 = r0 + 8;
    #pragma unroll
    for (int tn = 0; tn < 4; tn++) {
      int c0 = bn + noff + tn * 8 + 2 * t4;
      float b0 = bias[c0], b1 = bias[c0 + 1];
      float v00 = acc[tm][tn][0] + b0;
      float v01 = acc[tm][tn][1] + b1;
      float v10 = acc[tm][tn][2] + b0;
      float v11 = acc[tm][tn][3] + b1;
      if (EPI == 1) {
        v00 = 0.5f * v00 * (1.f + erff(v00 * 0.70710678118654752f));
        v01 = 0.5f * v01 * (1.f + erff(v01 * 0.70710678118654752f));
        v10 = 0.5f * v10 * (1.f + erff(v10 * 0.70710678118654752f));
        v11 = 0.5f * v11 * (1.f + erff(v11 * 0.70710678118654752f));
        uint2 h0, l0, h1, l1;
        split_tf32(v00, h0.x, l0.x); split_tf32(v01, h0.y, l0.y);
        split_tf32(v10, h1.x, l1.x); split_tf32(v11, h1.y, l1.y);
        *(uint2*)(Chi + (size_t)r0 * N + c0) = h0;
        *(uint2*)(Clo + (size_t)r0 * N + c0) = l0;
        *(uint2*)(Chi + (size_t)r1 * N + c0) = h1;
        *(uint2*)(Clo + (size_t)r1 * N + c0) = l1;
      } else {
        *(float2*)(Cf + (size_t)r0 * N + c0) = make_float2(v00, v01);
        *(float2*)(Cf + (size_t)r1 * N + c0) = make_float2(v10, v11);
      }
    }
  }
  #undef PREFETCH
}

// ------------------- host: layer key derivation ----------------------------
static void layer_key(int i, unsigned &k0, unsigned &k1)
{
  unsigned a = 0u, b = (unsigned)i;
  threefry2x32(0u, 42u, a, b);               // fold_in(key(42), i)
  unsigned c = 0u, d = 1u;
  threefry2x32(a, b, c, d);                  // partitionable split
  k0 = c; k1 = d;
}

extern "C" void kernel_launch(void* const* d_in, const int* in_sizes, int n_in,
                              void* d_out, int out_size)
{
  const float* x     = (const float*)d_in[0];
  const float* emb_w = (const float*)d_in[1];
  const float* emb_b = (const float*)d_in[2];
  const float* ln1_s = (const float*)d_in[3];
  const float* ln1_b = (const float*)d_in[4];
  const float* w1    = (const float*)d_in[5];
  const float* b1    = (const float*)d_in[6];
  const float* w2    = (const float*)d_in[7];
  const float* b2    = (const float*)d_in[8];
  const float* ln2_s = (const float*)d_in[9];
  const float* ln2_b = (const float*)d_in[10];
  const float* out_w = (const float*)d_in[11];
  const float* out_b = (const float*)d_in[12];
  float* out = (float*)d_out;

  float *ph, *poth, *px, *pz;
  unsigned *pxhi, *pxlo, *pyhi, *pylo;
  unsigned *pw1hi, *pw1lo, *pw2hi, *pw2lo, *powhi, *powlo;
  cudaGetSymbolAddress((void**)&ph,   g_h);
  cudaGetSymbolAddress((void**)&poth, g_h2);
  cudaGetSymbolAddress((void**)&px,   g_x);
  cudaGetSymbolAddress((void**)&pz,   g_z);
  cudaGetSymbolAddress((void**)&pxhi, g_xhi);
  cudaGetSymbolAddress((void**)&pxlo, g_xlo);
  cudaGetSymbolAddress((void**)&pyhi, g_yhi);
  cudaGetSymbolAddress((void**)&pylo, g_ylo);
  cudaGetSymbolAddress((void**)&pw1hi, g_w1hi);
  cudaGetSymbolAddress((void**)&pw1lo, g_w1lo);
  cudaGetSymbolAddress((void**)&pw2hi, g_w2hi);
  cudaGetSymbolAddress((void**)&pw2lo, g_w2lo);
  cudaGetSymbolAddress((void**)&powhi, g_owhi);
  cudaGetSymbolAddress((void**)&powlo, g_owlo);

  static int smem_set = 0;
  if (!smem_set) {
    cudaFuncSetAttribute(mma_gemm<0>, cudaFuncAttributeMaxDynamicSharedMemorySize, 2 * STG_U32 * 4);
    cudaFuncSetAttribute(mma_gemm<1>, cudaFuncAttributeMaxDynamicSharedMemorySize, 2 * STG_U32 * 4);
    smem_set = 1;
  }
  const int smem_bytes = 2 * STG_U32 * 4;   // 80KB

  // Split weights into tf32 hi/lo (cheap; runs per replay)
  {
    int n1 = 3 * DFF * DD;
    wsplit_kernel<<<(n1 + 255) / 256, 256>>>(w1, pw1hi, pw1lo, n1);
    wsplit_kernel<<<(n1 + 255) / 256, 256>>>(w2, pw2hi, pw2lo, n1);
    int n2 = DD * DD;
    wsplit_kernel<<<(n2 + 255) / 256, 256>>>(out_w, powhi, powlo, n2);
  }

  // Embed: h = x @ emb_w^T + emb_b + PE   (M=32768, N=512, K=64)
  {
    int M = BB * L0;
    sgemm_embed<<<dim3(DD / 128, M / 128), 256>>>(x, emb_w, emb_b, ph, M, DD, 64, L0 - 1);
  }

  int L = L0;
  float* cur = ph;
  for (int i = 0; i < 3; i++) {
    int u = (i == 0) ? 45 : (i == 1) ? 40 : 35;
    int M = BB * L;
    unsigned k0, k1; layer_key(i, k0, k1);
    int total = L * u;
    idx_part<<<(total + 255) / 256, 256>>>(k0, k1, total, L - 1);
    prob_m_kernel<<<dim3(L / 8, 64), 256>>>(cur, L, u, 1.0f / (float)L);
    topk_kernel<<<64, 256>>>(L, u);
    qmean_kernel<<<64, 512>>>(cur, L);
    ctx_kernel<<<dim3(u, 64), 256>>>(cur, L, u);
    assemble_ln1_kernel<<<M, 128>>>(cur, px, pxhi, pxlo,
                                    ln1_s + i * DD, ln1_b + i * DD, L, u);

    // FFN1: y = gelu(x @ w1^T + b1)  -> tf32 split
    mma_gemm<1><<<dim3(DFF / 128, M / 128), 256, smem_bytes>>>(
        pxhi, pxlo, pw1hi + (size_t)i * DFF * DD, pw1lo + (size_t)i * DFF * DD,
        b1 + i * DFF, nullptr, pyhi, pylo, M, DFF, DD);
    // FFN2: z = y @ w2^T + b2  (fp32 out)
    mma_gemm<0><<<dim3(DD / 128, M / 128), 256, smem_bytes>>>(
        pyhi, pylo, pw2hi + (size_t)i * DD * DFF, pw2lo + (size_t)i * DD * DFF,
        b2 + i * DD, pz, nullptr, nullptr, M, DD, DFF);

    // LN2 (+ split on last layer for the final GEMM)
    ln2_kernel<<<M, 128>>>(px, pz, poth,
                           (i == 2) ? pxhi : nullptr, (i == 2) ? pxlo : nullptr,
                           ln2_s + i * DD, ln2_b + i * DD);

    if (i < 2) {
      int L2 = L / 2;
      int tot = BB * L2 * DD;
      distil_kernel<<<(tot + 255) / 256, 256>>>(poth, cur, L2);
      L = L2;
    }
  }

  // Final projection: out = h @ out_w^T + out_b  (M=8192, N=512, K=512)
  {
    int M = BB * L;   // L = 1024
    mma_gemm<0><<<dim3(DD / 128, M / 128), 256, smem_bytes>>>(
        pxhi, pxlo, powhi, powlo, out_b, out, nullptr, nullptr, M, DD, DD);
  }
}

// round 4
// speedup vs baseline: 1.3674x; 1.1955x over previous
#include <cuda_runtime.h>
#include <math.h>
#include <stdint.h>

#define BB 8
#define DD 512
#define DFF 2048
#define L0 4096
#define UMAX 45
#define LN_EPS 1e-5f

// ------------------- scratch (device globals; no allocs) -------------------
__device__ __align__(16) float g_h  [BB*L0*DD];
__device__ __align__(16) float g_h2 [BB*L0*DD];
__device__ __align__(16) float g_x  [BB*L0*DD];
__device__ __align__(16) float g_z  [BB*L0*DD];
__device__ __align__(16) unsigned g_xhi[BB*L0*DD];
__device__ __align__(16) unsigned g_xlo[BB*L0*DD];
__device__ __align__(16) unsigned g_yhi[BB*L0*DFF];
__device__ __align__(16) unsigned g_ylo[BB*L0*DFF];
__device__ __align__(16) unsigned g_w1hi[3*DFF*DD];
__device__ __align__(16) unsigned g_w1lo[3*DFF*DD];
__device__ __align__(16) unsigned g_w2hi[3*DD*DFF];
__device__ __align__(16) unsigned g_w2lo[3*DD*DFF];
__device__ __align__(16) unsigned g_owhi[DD*DD];
__device__ __align__(16) unsigned g_owlo[DD*DD];
__device__ __align__(16) float g_M  [BB*8*L0];
__device__ __align__(16) int   g_idx[L0*UMAX];
__device__ __align__(16) int   g_top[BB*8*UMAX];
__device__ __align__(16) int   g_rowmap[BB*8*L0];
__device__ __align__(16) float g_ctx[BB*8*UMAX*64];
__device__ __align__(16) float g_qmean[BB*8*64];

// ------------------- tf32 helpers ------------------------------------------
__device__ __forceinline__ unsigned cvt_tf32(float f)
{
  unsigned r;
  asm("cvt.rna.tf32.f32 %0, %1;" : "=r"(r) : "f"(f));
  return r;
}
__device__ __forceinline__ void split_tf32(float v, unsigned &hi, unsigned &lo)
{
  hi = cvt_tf32(v);
  float hf = __uint_as_float(hi);
  lo = cvt_tf32(v - hf);
}

// ------------------- threefry2x32 (JAX-compatible) -------------------------
#define TF_R(x0,x1,r) { x0 += x1; x1 = ((x1 << (r)) | (x1 >> (32-(r)))); x1 ^= x0; }
__host__ __device__ inline void threefry2x32(unsigned ks0, unsigned ks1,
                                             unsigned &x0, unsigned &x1)
{
  unsigned ks2 = ks0 ^ ks1 ^ 0x1BD11BDAu;
  x0 += ks0; x1 += ks1;
  TF_R(x0,x1,13) TF_R(x0,x1,15) TF_R(x0,x1,26) TF_R(x0,x1,6)
  x0 += ks1; x1 += ks2 + 1u;
  TF_R(x0,x1,17) TF_R(x0,x1,29) TF_R(x0,x1,16) TF_R(x0,x1,24)
  x0 += ks2; x1 += ks0 + 2u;
  TF_R(x0,x1,13) TF_R(x0,x1,15) TF_R(x0,x1,26) TF_R(x0,x1,6)
  x0 += ks0; x1 += ks1 + 3u;
  TF_R(x0,x1,17) TF_R(x0,x1,29) TF_R(x0,x1,16) TF_R(x0,x1,24)
  x0 += ks1; x1 += ks2 + 4u;
  TF_R(x0,x1,13) TF_R(x0,x1,15) TF_R(x0,x1,26) TF_R(x0,x1,6)
  x0 += ks2; x1 += ks0 + 5u;
}

__global__ void idx_part(unsigned k0, unsigned k1, int total, int mask)
{
  int t = blockIdx.x * 256 + threadIdx.x;
  if (t >= total) return;
  unsigned x0 = 0u, x1 = (unsigned)t;
  threefry2x32(k0, k1, x0, x1);
  g_idx[t] = (int)((x0 ^ x1) & (unsigned)mask);
}

// ------------------- weight split ------------------------------------------
__global__ void wsplit_kernel(const float* __restrict__ w,
                              unsigned* __restrict__ hi, unsigned* __restrict__ lo, int n)
{
  int i = blockIdx.x * 256 + threadIdx.x;
  if (i >= n) return;
  unsigned h, l;
  split_tf32(w[i], h, l);
  hi[i] = h; lo[i] = l;
}

// ------------------- M = max_s qk - sum_s qk / L ----------------------------
__global__ __launch_bounds__(256) void prob_m_kernel(
    const float* __restrict__ h, int L, int u, float invL)
{
  __shared__ float qs[8][64];
  int bh = blockIdx.y; int b = bh >> 3, hh = bh & 7;
  int warp = threadIdx.x >> 5, lane = threadIdx.x & 31;
  int l = blockIdx.x * 8 + warp;
  const float* base = h + (size_t)b * L * DD + hh * 64;
  const float* qrow = base + (size_t)l * DD;
  qs[warp][lane]      = qrow[lane];
  qs[warp][lane + 32] = qrow[lane + 32];
  __syncwarp();
  float mx = -INFINITY, sm = 0.f;
  for (int s = lane; s < u; s += 32) {
    int kl = g_idx[l * u + s];
    const float4* krow = (const float4*)(base + (size_t)kl * DD);
    float dot = 0.f;
    #pragma unroll
    for (int q4 = 0; q4 < 16; q4++) {
      float4 kv = krow[q4];
      dot += qs[warp][q4*4+0]*kv.x + qs[warp][q4*4+1]*kv.y
           + qs[warp][q4*4+2]*kv.z + qs[warp][q4*4+3]*kv.w;
    }
    mx = fmaxf(mx, dot); sm += dot;
  }
  #pragma unroll
  for (int o = 16; o; o >>= 1) {
    mx = fmaxf(mx, __shfl_xor_sync(0xffffffffu, mx, o));
    sm += __shfl_xor_sync(0xffffffffu, sm, o);
  }
  if (lane == 0) g_M[(size_t)bh * L + l] = mx - sm * invL;
}

// ------------------- top-k (iterative argmax, lower-index tiebreak) --------
__global__ __launch_bounds__(256) void topk_kernel(int L, int u)
{
  __shared__ float sM[L0];
  __shared__ float sval[256];
  __shared__ int   sidx[256];
  int bh = blockIdx.x;
  int tid = threadIdx.x;
  for (int l = tid; l < L; l += 256) {
    sM[l] = g_M[(size_t)bh * L + l];
    g_rowmap[(size_t)bh * L + l] = -1;
  }
  __syncthreads();
  for (int r = 0; r < u; r++) {
    float bv = -INFINITY; int bi = 0x7fffffff;
    for (int l = tid; l < L; l += 256) {
      float v = sM[l];
      if (v > bv || (v == bv && l < bi)) { bv = v; bi = l; }
    }
    sval[tid] = bv; sidx[tid] = bi;
    __syncthreads();
    for (int st = 128; st > 0; st >>= 1) {
      if (tid < st) {
        float v2 = sval[tid + st]; int i2 = sidx[tid + st];
        if (v2 > sval[tid] || (v2 == sval[tid] && i2 < sidx[tid])) {
          sval[tid] = v2; sidx[tid] = i2;
        }
      }
      __syncthreads();
    }
    if (tid == 0) {
      int sel = sidx[0];
      g_top[bh * u + r] = sel;
      g_rowmap[(size_t)bh * L + sel] = r;
      sM[sel] = -INFINITY;
    }
    __syncthreads();
  }
}

// ------------------- qmean over L per (b,h,d) -------------------------------
__global__ __launch_bounds__(512) void qmean_kernel(const float* __restrict__ h, int L)
{
  __shared__ float part[512];
  int bh = blockIdx.x; int b = bh >> 3, hh = bh & 7;
  int tid = threadIdx.x; int d = tid & 63; int p = tid >> 6;
  const float* base = h + (size_t)b * L * DD + hh * 64;
  float s = 0.f;
  for (int l = p; l < L; l += 8) s += base[(size_t)l * DD + d];
  part[tid] = s;
  __syncthreads();
  if (p == 0) {
    float t = 0.f;
    #pragma unroll
    for (int q = 0; q < 8; q++) t += part[q * 64 + d];
    g_qmean[bh * 64 + d] = t / (float)L;
  }
}

// ------------------- batched ctx: one CTA per (b,h), single key sweep ------
// dyn smem layout (floats):
//   qs  [48][64]   @ 0
//   kt  [64][68]   @ 3072
//   sc  [48][64]   @ 7424
//   ctx [48][64]   @ 10496
//   rm[48] rs[48] rscale[48] @ 13568
#define CTX_SMEM_FLOATS (13568 + 144)

__global__ __launch_bounds__(256) void ctx_batched_kernel(
    const float* __restrict__ h, int L, int u)
{
  extern __shared__ float dsm[];
  float* qs   = dsm;            // stride 64
  float* kt   = dsm + 3072;     // stride 68
  float* sc   = dsm + 7424;     // stride 64
  float* ctxs = dsm + 10496;    // stride 64
  float* rm   = dsm + 13568;
  float* rs   = dsm + 13616;
  float* rsc  = dsm + 13664;

  int bh = blockIdx.x; int b = bh >> 3, hh = bh & 7;
  const float* base = h + (size_t)b * L * DD + hh * 64;
  int tid = threadIdx.x;

  for (int e = tid; e < u * 64; e += 256) {
    int r = e >> 6, d = e & 63;
    qs[r * 64 + d] = base[(size_t)g_top[bh * u + r] * DD + d];
    ctxs[e] = 0.f;
  }
  if (tid < u) { rm[tid] = -INFINITY; rs[tid] = 0.f; }
  __syncthreads();

  const int j  = tid & 63;
  const int rg = tid >> 6;
  const int w  = tid >> 5, lane = tid & 31;

  for (int t0 = 0; t0 < L; t0 += 64) {
    // load 64-key tile
    for (int e = tid; e < 64 * 16; e += 256) {
      int r = e >> 4, c4 = e & 15;
      float4 v = *(const float4*)(base + (size_t)(t0 + r) * DD + c4 * 4);
      float* kr = kt + r * 68 + c4 * 4;
      kr[0] = v.x; kr[1] = v.y; kr[2] = v.z; kr[3] = v.w;
    }
    __syncthreads();

    // scores: thread (j, rg) -> rows rg, rg+4, ...
    {
      float kreg[64];
      #pragma unroll
      for (int d = 0; d < 64; d++) kreg[d] = kt[j * 68 + d];
      for (int r = rg; r < u; r += 4) {
        const float* qr = qs + r * 64;
        float dot = 0.f;
        #pragma unroll
        for (int d = 0; d < 64; d++) dot += qr[d] * kreg[d];
        sc[r * 64 + j] = dot * 0.125f;
      }
    }
    __syncthreads();

    // per-row online softmax update: warp w handles rows w, w+8, ...
    for (int r = w; r < u; r += 8) {
      float v0 = sc[r * 64 + lane], v1 = sc[r * 64 + lane + 32];
      float mx = fmaxf(v0, v1);
      #pragma unroll
      for (int o = 16; o; o >>= 1) mx = fmaxf(mx, __shfl_xor_sync(0xffffffffu, mx, o));
      float mold = rm[r];
      float mnew = fmaxf(mold, mx);
      float p0 = __expf(v0 - mnew), p1 = __expf(v1 - mnew);
      float ps = p0 + p1;
      #pragma unroll
      for (int o = 16; o; o >>= 1) ps += __shfl_xor_sync(0xffffffffu, ps, o);
      if (lane == 0) {
        float cold = __expf(mold - mnew);
        rsc[r] = cold;
        rs[r] = rs[r] * cold + ps;
        rm[r] = mnew;
      }
      sc[r * 64 + lane] = p0; sc[r * 64 + lane + 32] = p1;
    }
    __syncthreads();

    // ctx update: thread (d=j, rg)
    for (int r = rg; r < u; r += 4) {
      const float* pr = sc + r * 64;
      float a = 0.f;
      #pragma unroll
      for (int jj = 0; jj < 64; jj++) a += pr[jj] * kt[jj * 68 + j];
      ctxs[r * 64 + j] = ctxs[r * 64 + j] * rsc[r] + a;
    }
    __syncthreads();
  }

  for (int e = tid; e < u * 64; e += 256) {
    int r = e >> 6, d = e & 63;
    g_ctx[((size_t)(bh * u + r)) * 64 + d] = ctxs[r * 64 + d] / rs[r];
  }
}

// ------------------- block reduce helper (128 threads) ---------------------
__device__ __forceinline__ float blocksum128(float v, float* sred)
{
  #pragma unroll
  for (int o = 16; o; o >>= 1) v += __shfl_xor_sync(0xffffffffu, v, o);
  if ((threadIdx.x & 31) == 0) sred[threadIdx.x >> 5] = v;
  __syncthreads();
  float t = sred[0] + sred[1] + sred[2] + sred[3];
  __syncthreads();
  return t;
}

// ------------------- assemble attention out + residual + LN1 + tf32 split --
__global__ __launch_bounds__(128) void assemble_ln1_kernel(
    const float* __restrict__ hin, float* __restrict__ xout,
    unsigned* __restrict__ xhi, unsigned* __restrict__ xlo,
    const float* __restrict__ gamma, const float* __restrict__ beta,
    int L, int u)
{
  __shared__ float sred[4];
  int row = blockIdx.x;
  int b = row / L, l = row - b * L;
  int tid = threadIdx.x;
  float v[4];
  #pragma unroll
  for (int i = 0; i < 4; i++) {
    int e = i * 128 + tid;
    int hh = e >> 6, dd = e & 63;
    int bh = b * 8 + hh;
    int r = g_rowmap[(size_t)bh * L + l];
    float nv = (r >= 0) ? g_ctx[((size_t)(bh * u + r)) * 64 + dd]
                        : g_qmean[bh * 64 + dd];
    v[i] = hin[(size_t)row * DD + e] + nv;
  }
  float s = blocksum128(v[0] + v[1] + v[2] + v[3], sred);
  float mu = s * (1.0f / 512.0f);
  float vs = 0.f;
  #pragma unroll
  for (int i = 0; i < 4; i++) { float d = v[i] - mu; vs += d * d; }
  vs = blocksum128(vs, sred);
  float rstd = rsqrtf(vs * (1.0f / 512.0f) + LN_EPS);
  #pragma unroll
  for (int i = 0; i < 4; i++) {
    int e = i * 128 + tid;
    float o = (v[i] - mu) * rstd * gamma[e] + beta[e];
    xout[(size_t)row * DD + e] = o;
    unsigned h32, l32;
    split_tf32(o, h32, l32);
    xhi[(size_t)row * DD + e] = h32;
    xlo[(size_t)row * DD + e] = l32;
  }
}

// ------------------- residual + LN2 (optional tf32 split) ------------------
__global__ __launch_bounds__(128) void ln2_kernel(
    const float* __restrict__ xin, const float* __restrict__ zin,
    float* __restrict__ outp,
    unsigned* __restrict__ ohi, unsigned* __restrict__ olo,
    const float* __restrict__ gamma, const float* __restrict__ beta)
{
  __shared__ float sred[4];
  size_t row = blockIdx.x;
  int tid = threadIdx.x;
  float v[4];
  #pragma unroll
  for (int i = 0; i < 4; i++) {
    int e = i * 128 + tid;
    v[i] = xin[row * DD + e] + zin[row * DD + e];
  }
  float s = blocksum128(v[0] + v[1] + v[2] + v[3], sred);
  float mu = s * (1.0f / 512.0f);
  float vs = 0.f;
  #pragma unroll
  for (int i = 0; i < 4; i++) { float d = v[i] - mu; vs += d * d; }
  vs = blocksum128(vs, sred);
  float rstd = rsqrtf(vs * (1.0f / 512.0f) + LN_EPS);
  #pragma unroll
  for (int i = 0; i < 4; i++) {
    int e = i * 128 + tid;
    float o = (v[i] - mu) * rstd * gamma[e] + beta[e];
    outp[row * DD + e] = o;
    if (ohi) {
      unsigned h32, l32;
      split_tf32(o, h32, l32);
      ohi[row * DD + e] = h32;
      olo[row * DD + e] = l32;
    }
  }
}

// ------------------- distil: mean of row pairs ------------------------------
__global__ void distil_kernel(const float* __restrict__ in, float* __restrict__ outp, int L2)
{
  int o = blockIdx.x * 256 + threadIdx.x;
  int total = BB * L2 * DD;
  if (o >= total) return;
  int e = o & 511; int rest = o >> 9;
  int l2 = rest % L2; int b = rest / L2;
  size_t base = ((size_t)b * (2 * L2) + 2 * l2) * DD + e;
  outp[o] = 0.5f * (in[base] + in[base + DD]);
}

// ------------------- SIMT SGEMM (embed only): C = A*B^T + bias + PE --------
__global__ __launch_bounds__(256, 2) void sgemm_embed(
    const float* __restrict__ A, const float* __restrict__ Bm,
    const float* __restrict__ bias, float* __restrict__ C,
    int M, int N, int K, int Lmask)
{
  __shared__ float As[16][132];
  __shared__ float Bs[16][132];
  const int bm = blockIdx.y * 128, bn = blockIdx.x * 128;
  const int t = threadIdx.x;
  const int lr = t >> 2;
  const int lc = (t & 3) << 2;
  const int tx = t & 15, ty = t >> 4;
  float acc[8][8];
  #pragma unroll
  for (int i = 0; i < 8; i++)
    #pragma unroll
    for (int j = 0; j < 8; j++) acc[i][j] = 0.f;

  const float* Ap = A + (size_t)(bm + lr) * K + lc;
  const float* Bp = Bm + (size_t)(bn + lr) * K + lc;

  for (int k0 = 0; k0 < K; k0 += 16) {
    float4 a0 = *(const float4*)(Ap + k0);
    float4 a1 = *(const float4*)(Ap + (size_t)64 * K + k0);
    float4 b0 = *(const float4*)(Bp + k0);
    float4 b1 = *(const float4*)(Bp + (size_t)64 * K + k0);
    __syncthreads();
    As[lc+0][lr] = a0.x; As[lc+1][lr] = a0.y; As[lc+2][lr] = a0.z; As[lc+3][lr] = a0.w;
    As[lc+0][lr+64] = a1.x; As[lc+1][lr+64] = a1.y; As[lc+2][lr+64] = a1.z; As[lc+3][lr+64] = a1.w;
    Bs[lc+0][lr] = b0.x; Bs[lc+1][lr] = b0.y; Bs[lc+2][lr] = b0.z; Bs[lc+3][lr] = b0.w;
    Bs[lc+0][lr+64] = b1.x; Bs[lc+1][lr+64] = b1.y; Bs[lc+2][lr+64] = b1.z; Bs[lc+3][lr+64] = b1.w;
    __syncthreads();
    #pragma unroll
    for (int kk = 0; kk < 16; kk++) {
      float4 av0 = *(const float4*)&As[kk][ty * 8];
      float4 av1 = *(const float4*)&As[kk][ty * 8 + 4];
      float4 bv0 = *(const float4*)&Bs[kk][tx * 8];
      float4 bv1 = *(const float4*)&Bs[kk][tx * 8 + 4];
      float a[8] = {av0.x, av0.y, av0.z, av0.w, av1.x, av1.y, av1.z, av1.w};
      float bb[8] = {bv0.x, bv0.y, bv0.z, bv0.w, bv1.x, bv1.y, bv1.z, bv1.w};
      #pragma unroll
      for (int i = 0; i < 8; i++)
        #pragma unroll
        for (int j = 0; j < 8; j++) acc[i][j] += a[i] * bb[j];
    }
  }

  #pragma unroll
  for (int i = 0; i < 8; i++) {
    int row = bm + ty * 8 + i;
    #pragma unroll
    for (int j = 0; j < 8; j++) {
      int col = bn + tx * 8 + j;
      float v = acc[i][j] + bias[col];
      int l = row & Lmask;
      float df = expf((float)(col & ~1) * (-0.017988946039015984f));
      float arg = (float)l * df;
      v += (col & 1) ? cosf(arg) : sinf(arg);
      C[(size_t)row * N + col] = v;
    }
  }
}

// ------------------- 3xTF32 tensor-core GEMM with ldmatrix ------------------
#define KC 16
#define LDP 20                  // padded k stride (floats)
#define PLANE_U32 (128*LDP)     // 2560
#define STG_U32 (4*PLANE_U32)   // 10240 (40KB)

__device__ __forceinline__ void mma_tf32(float* c, const unsigned* a, const unsigned* b)
{
  asm volatile(
    "mma.sync.aligned.m16n8k8.row.col.f32.tf32.tf32.f32 "
    "{%0,%1,%2,%3},{%4,%5,%6,%7},{%8,%9},{%0,%1,%2,%3};\n"
    : "+f"(c[0]), "+f"(c[1]), "+f"(c[2]), "+f"(c[3])
    : "r"(a[0]), "r"(a[1]), "r"(a[2]), "r"(a[3]), "r"(b[0]), "r"(b[1]));
}

__device__ __forceinline__ void ldsm4(unsigned* r, const unsigned* sptr)
{
  unsigned addr = (unsigned)__cvta_generic_to_shared(sptr);
  asm volatile("ldmatrix.sync.aligned.m8n8.x4.shared.b16 {%0,%1,%2,%3}, [%4];\n"
    : "=r"(r[0]), "=r"(r[1]), "=r"(r[2]), "=r"(r[3]) : "r"(addr));
}

template<int EPI>
__global__ __launch_bounds__(256, 2) void mma_gemm(
    const unsigned* __restrict__ Ahi, const unsigned* __restrict__ Alo,
    const unsigned* __restrict__ Bhi, const unsigned* __restrict__ Blo,
    const float* __restrict__ bias,
    float* __restrict__ Cf, unsigned* __restrict__ Chi, unsigned* __restrict__ Clo,
    int M, int N, int K)
{
  extern __shared__ unsigned smu[];
  const int tid = threadIdx.x;
  const int bm = blockIdx.y * 128, bn = blockIdx.x * 128;
  const int lane = tid & 31;
  const int g = lane >> 2, t4 = lane & 3;
  const int warp = tid >> 5;
  const int wm = warp >> 2, wn = warp & 3;      // warps 2(m) x 4(n)
  const int moff = wm * 64, noff = wn * 32;

  // ldmatrix per-lane offsets (in u32 elements)
  const int aoff = (lane & 15) * LDP + ((lane & 16) ? 4 : 0);
  const int boff = ((lane & 7) + ((lane & 16) ? 8 : 0)) * LDP + ((lane & 8) ? 4 : 0);

  float acc[4][4][4];
  #pragma unroll
  for (int i = 0; i < 4; i++)
    #pragma unroll
    for (int j = 0; j < 4; j++)
      #pragma unroll
      for (int q = 0; q < 4; q++) acc[i][j][q] = 0.f;

  const unsigned* gp0 = Ahi; const unsigned* gp1 = Alo;
  const unsigned* gp2 = Bhi; const unsigned* gp3 = Blo;

  const int KT = K / KC;

  #define PREFETCH(kt, s) do {                                                   \
    int k0_ = (kt) * KC;                                                         \
    const unsigned* srcs_[4] = {                                                 \
      gp0 + (size_t)bm * K + k0_, gp1 + (size_t)bm * K + k0_,                    \
      gp2 + (size_t)bn * K + k0_, gp3 + (size_t)bn * K + k0_ };                  \
    _Pragma("unroll")                                                            \
    for (int p_ = 0; p_ < 4; p_++) {                                             \
      unsigned* dstp_ = smu + (s) * STG_U32 + p_ * PLANE_U32;                    \
      _Pragma("unroll")                                                          \
      for (int j_ = 0; j_ < 2; j_++) {                                           \
        int idx_ = j_ * 256 + tid;                                               \
        int row_ = idx_ >> 2, kq_ = (idx_ & 3) << 2;                             \
        unsigned sa_ = (unsigned)__cvta_generic_to_shared(dstp_ + row_ * LDP + kq_); \
        const unsigned* ga_ = srcs_[p_] + (size_t)row_ * K + kq_;                \
        asm volatile("cp.async.ca.shared.global [%0], [%1], 16;\n"               \
                     :: "r"(sa_), "l"(ga_));                                     \
      }                                                                          \
    }                                                                            \
    asm volatile("cp.async.commit_group;\n");                                    \
  } while (0)

  PREFETCH(0, 0);

  for (int kt = 0; kt < KT; kt++) {
    asm volatile("cp.async.wait_group 0;\n");
    __syncthreads();
    if (kt + 1 < KT) PREFETCH(kt + 1, (kt + 1) & 1);

    const unsigned* Sahi = smu + (kt & 1) * STG_U32;
    const unsigned* Salo = Sahi + PLANE_U32;
    const unsigned* Sbhi = Sahi + 2 * PLANE_U32;
    const unsigned* Sblo = Sahi + 3 * PLANE_U32;

    #pragma unroll
    for (int ks = 0; ks < 2; ks++) {
      int kb = ks * 8;
      // B fragments: 2 ldsm.x4 per plane, each covering two n-tiles
      unsigned bh_[2][4], bl_[2][4];
      #pragma unroll
      for (int pp = 0; pp < 2; pp++) {
        ldsm4(bh_[pp], Sbhi + (noff + pp * 16) * LDP + kb + boff);
        ldsm4(bl_[pp], Sblo + (noff + pp * 16) * LDP + kb + boff);
      }
      #pragma unroll
      for (int tm = 0; tm < 4; tm++) {
        unsigned ah[4], al[4];
        ldsm4(ah, Sahi + (moff + tm * 16) * LDP + kb + aoff);
        ldsm4(al, Salo + (moff + tm * 16) * LDP + kb + aoff);
        #pragma unroll
        for (int tn = 0; tn < 4; tn++) {
          const unsigned* bhp = &bh_[tn >> 1][(tn & 1) * 2];
          const unsigned* blp = &bl_[tn >> 1][(tn & 1) * 2];
          mma_tf32(acc[tm][tn], ah, bhp);
          mma_tf32(acc[tm][tn], ah, blp);
          mma_tf32(acc[tm][tn], al, bhp);
        }
      }
    }
    __syncthreads();
  }

  // ---- epilogue ----
  #pragma unroll
  for (int tm = 0; tm < 4; tm++) {
    int r0 = bm + moff + tm * 16 + g;
    int r1 = r0 + 8;
    #pragma unroll
    for (int tn = 0; tn < 4; tn++) {
      int c0 = bn + noff + tn * 8 + 2 * t4;
      float b0 = bias[c0], b1 = bias[c0 + 1];
      float v00 = acc[tm][tn][0] + b0;
      float v01 = acc[tm][tn][1] + b1;
      float v10 = acc[tm][tn][2] + b0;
      float v11 = acc[tm][tn][3] + b1;
      if (EPI == 1) {
        v00 = 0.5f * v00 * (1.f + erff(v00 * 0.70710678118654752f));
        v01 = 0.5f * v01 * (1.f + erff(v01 * 0.70710678118654752f));
        v10 = 0.5f * v10 * (1.f + erff(v10 * 0.70710678118654752f));
        v11 = 0.5f * v11 * (1.f + erff(v11 * 0.70710678118654752f));
        uint2 h0, l0, h1, l1;
        split_tf32(v00, h0.x, l0.x); split_tf32(v01, h0.y, l0.y);
        split_tf32(v10, h1.x, l1.x); split_tf32(v11, h1.y, l1.y);
        *(uint2*)(Chi + (size_t)r0 * N + c0) = h0;
        *(uint2*)(Clo + (size_t)r0 * N + c0) = l0;
        *(uint2*)(Chi + (size_t)r1 * N + c0) = h1;
        *(uint2*)(Clo + (size_t)r1 * N + c0) = l1;
      } else {
        *(float2*)(Cf + (size_t)r0 * N + c0) = make_float2(v00, v01);
        *(float2*)(Cf + (size_t)r1 * N + c0) = make_float2(v10, v11);
      }
    }
  }
  #undef PREFETCH
}

// ------------------- host: layer key derivation ----------------------------
static void layer_key(int i, unsigned &k0, unsigned &k1)
{
  unsigned a = 0u, b = (unsigned)i;
  threefry2x32(0u, 42u, a, b);               // fold_in(key(42), i)
  unsigned c = 0u, d = 1u;
  threefry2x32(a, b, c, d);                  // partitionable split
  k0 = c; k1 = d;
}

extern "C" void kernel_launch(void* const* d_in, const int* in_sizes, int n_in,
                              void* d_out, int out_size)
{
  const float* x     = (const float*)d_in[0];
  const float* emb_w = (const float*)d_in[1];
  const float* emb_b = (const float*)d_in[2];
  const float* ln1_s = (const float*)d_in[3];
  const float* ln1_b = (const float*)d_in[4];
  const float* w1    = (const float*)d_in[5];
  const float* b1    = (const float*)d_in[6];
  const float* w2    = (const float*)d_in[7];
  const float* b2    = (const float*)d_in[8];
  const float* ln2_s = (const float*)d_in[9];
  const float* ln2_b = (const float*)d_in[10];
  const float* out_w = (const float*)d_in[11];
  const float* out_b = (const float*)d_in[12];
  float* out = (float*)d_out;

  float *ph, *poth, *px, *pz;
  unsigned *pxhi, *pxlo, *pyhi, *pylo;
  unsigned *pw1hi, *pw1lo, *pw2hi, *pw2lo, *powhi, *powlo;
  cudaGetSymbolAddress((void**)&ph,   g_h);
  cudaGetSymbolAddress((void**)&poth, g_h2);
  cudaGetSymbolAddress((void**)&px,   g_x);
  cudaGetSymbolAddress((void**)&pz,   g_z);
  cudaGetSymbolAddress((void**)&pxhi, g_xhi);
  cudaGetSymbolAddress((void**)&pxlo, g_xlo);
  cudaGetSymbolAddress((void**)&pyhi, g_yhi);
  cudaGetSymbolAddress((void**)&pylo, g_ylo);
  cudaGetSymbolAddress((void**)&pw1hi, g_w1hi);
  cudaGetSymbolAddress((void**)&pw1lo, g_w1lo);
  cudaGetSymbolAddress((void**)&pw2hi, g_w2hi);
  cudaGetSymbolAddress((void**)&pw2lo, g_w2lo);
  cudaGetSymbolAddress((void**)&powhi, g_owhi);
  cudaGetSymbolAddress((void**)&powlo, g_owlo);

  static int smem_set = 0;
  if (!smem_set) {
    cudaFuncSetAttribute(mma_gemm<0>, cudaFuncAttributeMaxDynamicSharedMemorySize, 2 * STG_U32 * 4);
    cudaFuncSetAttribute(mma_gemm<1>, cudaFuncAttributeMaxDynamicSharedMemorySize, 2 * STG_U32 * 4);
    cudaFuncSetAttribute(ctx_batched_kernel, cudaFuncAttributeMaxDynamicSharedMemorySize, CTX_SMEM_FLOATS * 4);
    smem_set = 1;
  }
  const int smem_bytes = 2 * STG_U32 * 4;   // 80KB
  const int ctx_smem   = CTX_SMEM_FLOATS * 4;

  // Split weights into tf32 hi/lo
  {
    int n1 = 3 * DFF * DD;
    wsplit_kernel<<<(n1 + 255) / 256, 256>>>(w1, pw1hi, pw1lo, n1);
    wsplit_kernel<<<(n1 + 255) / 256, 256>>>(w2, pw2hi, pw2lo, n1);
    int n2 = DD * DD;
    wsplit_kernel<<<(n2 + 255) / 256, 256>>>(out_w, powhi, powlo, n2);
  }

  // Embed: h = x @ emb_w^T + emb_b + PE   (M=32768, N=512, K=64)
  {
    int M = BB * L0;
    sgemm_embed<<<dim3(DD / 128, M / 128), 256>>>(x, emb_w, emb_b, ph, M, DD, 64, L0 - 1);
  }

  int L = L0;
  float* cur = ph;
  for (int i = 0; i < 3; i++) {
    int u = (i == 0) ? 45 : (i == 1) ? 40 : 35;
    int M = BB * L;
    unsigned k0, k1; layer_key(i, k0, k1);
    int total = L * u;
    idx_part<<<(total + 255) / 256, 256>>>(k0, k1, total, L - 1);
    prob_m_kernel<<<dim3(L / 8, 64), 256>>>(cur, L, u, 1.0f / (float)L);
    topk_kernel<<<64, 256>>>(L, u);
    qmean_kernel<<<64, 512>>>(cur, L);
    ctx_batched_kernel<<<64, 256, ctx_smem>>>(cur, L, u);
    assemble_ln1_kernel<<<M, 128>>>(cur, px, pxhi, pxlo,
                                    ln1_s + i * DD, ln1_b + i * DD, L, u);

    // FFN1: y = gelu(x @ w1^T + b1)  -> tf32 split
    mma_gemm<1><<<dim3(DFF / 128, M / 128), 256, smem_bytes>>>(
        pxhi, pxlo, pw1hi + (size_t)i * DFF * DD, pw1lo + (size_t)i * DFF * DD,
        b1 + i * DFF, nullptr, pyhi, pylo, M, DFF, DD);
    // FFN2: z = y @ w2^T + b2  (fp32 out)
    mma_gemm<0><<<dim3(DD / 128, M / 128), 256, smem_bytes>>>(
        pyhi, pylo, pw2hi + (size_t)i * DD * DFF, pw2lo + (size_t)i * DD * DFF,
        b2 + i * DD, pz, nullptr, nullptr, M, DD, DFF);

    ln2_kernel<<<M, 128>>>(px, pz, poth,
                           (i == 2) ? pxhi : nullptr, (i == 2) ? pxlo : nullptr,
                           ln2_s + i * DD, ln2_b + i * DD);

    if (i < 2) {
      int L2 = L / 2;
      int tot = BB * L2 * DD;
      distil_kernel<<<(tot + 255) / 256, 256>>>(poth, cur, L2);
      L = L2;
    }
  }

  // Final projection: out = h @ out_w^T + out_b  (M=8192, N=512, K=512)
  {
    int M = BB * L;   // L = 1024
    mma_gemm<0><<<dim3(DD / 128, M / 128), 256, smem_bytes>>>(
        pxhi, pxlo, powhi, powlo, out_b, out, nullptr, nullptr, M, DD, DD);
  }
}

// round 6
// speedup vs baseline: 1.9273x; 1.4095x over previous
#include <cuda_runtime.h>
#include <cuda_bf16.h>
#include <math.h>
#include <stdint.h>

#define BB 8
#define DD 512
#define DFF 2048
#define L0 4096
#define UMAX 45
#define LN_EPS 1e-5f

// ------------------- scratch (device globals; no allocs) -------------------
__device__ __align__(16) float g_h  [BB*L0*DD];
__device__ __align__(16) float g_h2 [BB*L0*DD];
__device__ __align__(16) float g_x  [BB*L0*DD];
__device__ __align__(16) float g_z  [BB*L0*DD];
__device__ __align__(16) __nv_bfloat16 g_xhi[BB*L0*DD];
__device__ __align__(16) __nv_bfloat16 g_xlo[BB*L0*DD];
__device__ __align__(16) __nv_bfloat16 g_yhi[BB*L0*DFF];
__device__ __align__(16) __nv_bfloat16 g_ylo[BB*L0*DFF];
__device__ __align__(16) __nv_bfloat16 g_w1hi[3*DFF*DD];
__device__ __align__(16) __nv_bfloat16 g_w1lo[3*DFF*DD];
__device__ __align__(16) __nv_bfloat16 g_w2hi[3*DD*DFF];
__device__ __align__(16) __nv_bfloat16 g_w2lo[3*DD*DFF];
__device__ __align__(16) __nv_bfloat16 g_owhi[DD*DD];
__device__ __align__(16) __nv_bfloat16 g_owlo[DD*DD];
__device__ __align__(16) float g_M  [BB*8*L0];
__device__ __align__(16) int   g_idx[L0*UMAX];
__device__ __align__(16) int   g_top[BB*8*UMAX];
__device__ __align__(16) int   g_rowmap[BB*8*L0];
__device__ __align__(16) float g_ctx[BB*8*UMAX*64];
__device__ __align__(16) float g_qmean[BB*8*64];

// ------------------- bf16 split helpers -------------------------------------
__device__ __forceinline__ void split_bf16(float v, __nv_bfloat16 &hi, __nv_bfloat16 &lo)
{
  hi = __float2bfloat16_rn(v);
  lo = __float2bfloat16_rn(v - __bfloat162float(hi));
}

// ------------------- threefry2x32 (JAX-compatible) -------------------------
#define TF_R(x0,x1,r) { x0 += x1; x1 = ((x1 << (r)) | (x1 >> (32-(r)))); x1 ^= x0; }
__host__ __device__ inline void threefry2x32(unsigned ks0, unsigned ks1,
                                             unsigned &x0, unsigned &x1)
{
  unsigned ks2 = ks0 ^ ks1 ^ 0x1BD11BDAu;
  x0 += ks0; x1 += ks1;
  TF_R(x0,x1,13) TF_R(x0,x1,15) TF_R(x0,x1,26) TF_R(x0,x1,6)
  x0 += ks1; x1 += ks2 + 1u;
  TF_R(x0,x1,17) TF_R(x0,x1,29) TF_R(x0,x1,16) TF_R(x0,x1,24)
  x0 += ks2; x1 += ks0 + 2u;
  TF_R(x0,x1,13) TF_R(x0,x1,15) TF_R(x0,x1,26) TF_R(x0,x1,6)
  x0 += ks0; x1 += ks1 + 3u;
  TF_R(x0,x1,17) TF_R(x0,x1,29) TF_R(x0,x1,16) TF_R(x0,x1,24)
  x0 += ks1; x1 += ks2 + 4u;
  TF_R(x0,x1,13) TF_R(x0,x1,15) TF_R(x0,x1,26) TF_R(x0,x1,6)
  x0 += ks2; x1 += ks0 + 5u;
}

__global__ void idx_part(unsigned k0, unsigned k1, int total, int mask)
{
  int t = blockIdx.x * 256 + threadIdx.x;
  if (t >= total) return;
  unsigned x0 = 0u, x1 = (unsigned)t;
  threefry2x32(k0, k1, x0, x1);
  g_idx[t] = (int)((x0 ^ x1) & (unsigned)mask);
}

// ------------------- weight split (fp32 -> bf16 hi/lo) ----------------------
__global__ void wsplit_kernel(const float* __restrict__ w,
                              __nv_bfloat16* __restrict__ hi,
                              __nv_bfloat16* __restrict__ lo, int n)
{
  int i = blockIdx.x * 256 + threadIdx.x;
  if (i >= n) return;
  __nv_bfloat16 h, l;
  split_bf16(w[i], h, l);
  hi[i] = h; lo[i] = l;
}

// ------------------- M = max_s qk - sum_s qk / L ----------------------------
__global__ __launch_bounds__(256) void prob_m_kernel(
    const float* __restrict__ h, int L, int u, float invL)
{
  __shared__ float qs[8][64];
  int bh = blockIdx.y; int b = bh >> 3, hh = bh & 7;
  int warp = threadIdx.x >> 5, lane = threadIdx.x & 31;
  int l = blockIdx.x * 8 + warp;
  const float* base = h + (size_t)b * L * DD + hh * 64;
  const float* qrow = base + (size_t)l * DD;
  qs[warp][lane]      = qrow[lane];
  qs[warp][lane + 32] = qrow[lane + 32];
  __syncwarp();
  float mx = -INFINITY, sm = 0.f;
  for (int s = lane; s < u; s += 32) {
    int kl = g_idx[l * u + s];
    const float4* krow = (const float4*)(base + (size_t)kl * DD);
    float dot = 0.f;
    #pragma unroll
    for (int q4 = 0; q4 < 16; q4++) {
      float4 kv = krow[q4];
      dot += qs[warp][q4*4+0]*kv.x + qs[warp][q4*4+1]*kv.y
           + qs[warp][q4*4+2]*kv.z + qs[warp][q4*4+3]*kv.w;
    }
    mx = fmaxf(mx, dot); sm += dot;
  }
  #pragma unroll
  for (int o = 16; o; o >>= 1) {
    mx = fmaxf(mx, __shfl_xor_sync(0xffffffffu, mx, o));
    sm += __shfl_xor_sync(0xffffffffu, sm, o);
  }
  if (lane == 0) g_M[(size_t)bh * L + l] = mx - sm * invL;
}

// ------------------- top-k (iterative argmax, lower-index tiebreak) --------
__global__ __launch_bounds__(256) void topk_kernel(int L, int u)
{
  __shared__ float sM[L0];
  __shared__ float sval[256];
  __shared__ int   sidx[256];
  int bh = blockIdx.x;
  int tid = threadIdx.x;
  for (int l = tid; l < L; l += 256) {
    sM[l] = g_M[(size_t)bh * L + l];
    g_rowmap[(size_t)bh * L + l] = -1;
  }
  __syncthreads();
  for (int r = 0; r < u; r++) {
    float bv = -INFINITY; int bi = 0x7fffffff;
    for (int l = tid; l < L; l += 256) {
      float v = sM[l];
      if (v > bv || (v == bv && l < bi)) { bv = v; bi = l; }
    }
    sval[tid] = bv; sidx[tid] = bi;
    __syncthreads();
    for (int st = 128; st > 0; st >>= 1) {
      if (tid < st) {
        float v2 = sval[tid + st]; int i2 = sidx[tid + st];
        if (v2 > sval[tid] || (v2 == sval[tid] && i2 < sidx[tid])) {
          sval[tid] = v2; sidx[tid] = i2;
        }
      }
      __syncthreads();
    }
    if (tid == 0) {
      int sel = sidx[0];
      g_top[bh * u + r] = sel;
      g_rowmap[(size_t)bh * L + sel] = r;
      sM[sel] = -INFINITY;
    }
    __syncthreads();
  }
}

// ------------------- qmean over L per (b,h,d) -------------------------------
__global__ __launch_bounds__(512) void qmean_kernel(const float* __restrict__ h, int L)
{
  __shared__ float part[512];
  int bh = blockIdx.x; int b = bh >> 3, hh = bh & 7;
  int tid = threadIdx.x; int d = tid & 63; int p = tid >> 6;
  const float* base = h + (size_t)b * L * DD + hh * 64;
  float s = 0.f;
  for (int l = p; l < L; l += 8) s += base[(size_t)l * DD + d];
  part[tid] = s;
  __syncthreads();
  if (p == 0) {
    float t = 0.f;
    #pragma unroll
    for (int q = 0; q < 8; q++) t += part[q * 64 + d];
    g_qmean[bh * 64 + d] = t / (float)L;
  }
}

// ------------------- batched ctx: one CTA per (b,h), single key sweep ------
#define CTX_SMEM_FLOATS (13568 + 144)
__global__ __launch_bounds__(256) void ctx_batched_kernel(
    const float* __restrict__ h, int L, int u)
{
  extern __shared__ float dsm[];
  float* qs   = dsm;            // stride 64
  float* kt   = dsm + 3072;     // stride 68
  float* sc   = dsm + 7424;     // stride 64
  float* ctxs = dsm + 10496;    // stride 64
  float* rm   = dsm + 13568;
  float* rs   = dsm + 13616;
  float* rsc  = dsm + 13664;

  int bh = blockIdx.x; int b = bh >> 3, hh = bh & 7;
  const float* base = h + (size_t)b * L * DD + hh * 64;
  int tid = threadIdx.x;

  for (int e = tid; e < u * 64; e += 256) {
    int r = e >> 6, d = e & 63;
    qs[r * 64 + d] = base[(size_t)g_top[bh * u + r] * DD + d];
    ctxs[e] = 0.f;
  }
  if (tid < u) { rm[tid] = -INFINITY; rs[tid] = 0.f; }
  __syncthreads();

  const int j  = tid & 63;
  const int rg = tid >> 6;
  const int w  = tid >> 5, lane = tid & 31;

  for (int t0 = 0; t0 < L; t0 += 64) {
    for (int e = tid; e < 64 * 16; e += 256) {
      int r = e >> 4, c4 = e & 15;
      float4 v = *(const float4*)(base + (size_t)(t0 + r) * DD + c4 * 4);
      float* kr = kt + r * 68 + c4 * 4;
      kr[0] = v.x; kr[1] = v.y; kr[2] = v.z; kr[3] = v.w;
    }
    __syncthreads();
    {
      float kreg[64];
      #pragma unroll
      for (int d = 0; d < 64; d++) kreg[d] = kt[j * 68 + d];
      for (int r = rg; r < u; r += 4) {
        const float* qr = qs + r * 64;
        float dot = 0.f;
        #pragma unroll
        for (int d = 0; d < 64; d++) dot += qr[d] * kreg[d];
        sc[r * 64 + j] = dot * 0.125f;
      }
    }
    __syncthreads();
    for (int r = w; r < u; r += 8) {
      float v0 = sc[r * 64 + lane], v1 = sc[r * 64 + lane + 32];
      float mx = fmaxf(v0, v1);
      #pragma unroll
      for (int o = 16; o; o >>= 1) mx = fmaxf(mx, __shfl_xor_sync(0xffffffffu, mx, o));
      float mold = rm[r];
      float mnew = fmaxf(mold, mx);
      float p0 = __expf(v0 - mnew), p1 = __expf(v1 - mnew);
      float ps = p0 + p1;
      #pragma unroll
      for (int o = 16; o; o >>= 1) ps += __shfl_xor_sync(0xffffffffu, ps, o);
      if (lane == 0) {
        float cold = __expf(mold - mnew);
        rsc[r] = cold;
        rs[r] = rs[r] * cold + ps;
        rm[r] = mnew;
      }
      sc[r * 64 + lane] = p0; sc[r * 64 + lane + 32] = p1;
    }
    __syncthreads();
    for (int r = rg; r < u; r += 4) {
      const float* pr = sc + r * 64;
      float a = 0.f;
      #pragma unroll
      for (int jj = 0; jj < 64; jj++) a += pr[jj] * kt[jj * 68 + j];
      ctxs[r * 64 + j] = ctxs[r * 64 + j] * rsc[r] + a;
    }
    __syncthreads();
  }

  for (int e = tid; e < u * 64; e += 256) {
    int r = e >> 6, d = e & 63;
    g_ctx[((size_t)(bh * u + r)) * 64 + d] = ctxs[r * 64 + d] / rs[r];
  }
}

// ------------------- block reduce helper (128 threads) ---------------------
__device__ __forceinline__ float blocksum128(float v, float* sred)
{
  #pragma unroll
  for (int o = 16; o; o >>= 1) v += __shfl_xor_sync(0xffffffffu, v, o);
  if ((threadIdx.x & 31) == 0) sred[threadIdx.x >> 5] = v;
  __syncthreads();
  float t = sred[0] + sred[1] + sred[2] + sred[3];
  __syncthreads();
  return t;
}

// ------------------- assemble attention out + residual + LN1 + bf16 split --
__global__ __launch_bounds__(128) void assemble_ln1_kernel(
    const float* __restrict__ hin, float* __restrict__ xout,
    __nv_bfloat16* __restrict__ xhi, __nv_bfloat16* __restrict__ xlo,
    const float* __restrict__ gamma, const float* __restrict__ beta,
    int L, int u)
{
  __shared__ float sred[4];
  int row = blockIdx.x;
  int b = row / L, l = row - b * L;
  int tid = threadIdx.x;
  float v[4];
  #pragma unroll
  for (int i = 0; i < 4; i++) {
    int e = i * 128 + tid;
    int hh = e >> 6, dd = e & 63;
    int bh = b * 8 + hh;
    int r = g_rowmap[(size_t)bh * L + l];
    float nv = (r >= 0) ? g_ctx[((size_t)(bh * u + r)) * 64 + dd]
                        : g_qmean[bh * 64 + dd];
    v[i] = hin[(size_t)row * DD + e] + nv;
  }
  float s = blocksum128(v[0] + v[1] + v[2] + v[3], sred);
  float mu = s * (1.0f / 512.0f);
  float vs = 0.f;
  #pragma unroll
  for (int i = 0; i < 4; i++) { float d = v[i] - mu; vs += d * d; }
  vs = blocksum128(vs, sred);
  float rstd = rsqrtf(vs * (1.0f / 512.0f) + LN_EPS);
  #pragma unroll
  for (int i = 0; i < 4; i++) {
    int e = i * 128 + tid;
    float o = (v[i] - mu) * rstd * gamma[e] + beta[e];
    xout[(size_t)row * DD + e] = o;
    __nv_bfloat16 h32, l32;
    split_bf16(o, h32, l32);
    xhi[(size_t)row * DD + e] = h32;
    xlo[(size_t)row * DD + e] = l32;
  }
}

// ------------------- residual + LN2 (optional bf16 split) ------------------
__global__ __launch_bounds__(128) void ln2_kernel(
    const float* __restrict__ xin, const float* __restrict__ zin,
    float* __restrict__ outp,
    __nv_bfloat16* __restrict__ ohi, __nv_bfloat16* __restrict__ olo,
    const float* __restrict__ gamma, const float* __restrict__ beta)
{
  __shared__ float sred[4];
  size_t row = blockIdx.x;
  int tid = threadIdx.x;
  float v[4];
  #pragma unroll
  for (int i = 0; i < 4; i++) {
    int e = i * 128 + tid;
    v[i] = xin[row * DD + e] + zin[row * DD + e];
  }
  float s = blocksum128(v[0] + v[1] + v[2] + v[3], sred);
  float mu = s * (1.0f / 512.0f);
  float vs = 0.f;
  #pragma unroll
  for (int i = 0; i < 4; i++) { float d = v[i] - mu; vs += d * d; }
  vs = blocksum128(vs, sred);
  float rstd = rsqrtf(vs * (1.0f / 512.0f) + LN_EPS);
  #pragma unroll
  for (int i = 0; i < 4; i++) {
    int e = i * 128 + tid;
    float o = (v[i] - mu) * rstd * gamma[e] + beta[e];
    outp[row * DD + e] = o;
    if (ohi) {
      __nv_bfloat16 h32, l32;
      split_bf16(o, h32, l32);
      ohi[row * DD + e] = h32;
      olo[row * DD + e] = l32;
    }
  }
}

// ------------------- distil: mean of row pairs ------------------------------
__global__ void distil_kernel(const float* __restrict__ in, float* __restrict__ outp, int L2)
{
  int o = blockIdx.x * 256 + threadIdx.x;
  int total = BB * L2 * DD;
  if (o >= total) return;
  int e = o & 511; int rest = o >> 9;
  int l2 = rest % L2; int b = rest / L2;
  size_t base = ((size_t)b * (2 * L2) + 2 * l2) * DD + e;
  outp[o] = 0.5f * (in[base] + in[base + DD]);
}

// ------------------- SIMT SGEMM (embed only): C = A*B^T + bias + PE --------
__global__ __launch_bounds__(256, 2) void sgemm_embed(
    const float* __restrict__ A, const float* __restrict__ Bm,
    const float* __restrict__ bias, float* __restrict__ C,
    int M, int N, int K, int Lmask)
{
  __shared__ float As[16][132];
  __shared__ float Bs[16][132];
  const int bm = blockIdx.y * 128, bn = blockIdx.x * 128;
  const int t = threadIdx.x;
  const int lr = t >> 2;
  const int lc = (t & 3) << 2;
  const int tx = t & 15, ty = t >> 4;
  float acc[8][8];
  #pragma unroll
  for (int i = 0; i < 8; i++)
    #pragma unroll
    for (int j = 0; j < 8; j++) acc[i][j] = 0.f;

  const float* Ap = A + (size_t)(bm + lr) * K + lc;
  const float* Bp = Bm + (size_t)(bn + lr) * K + lc;

  for (int k0 = 0; k0 < K; k0 += 16) {
    float4 a0 = *(const float4*)(Ap + k0);
    float4 a1 = *(const float4*)(Ap + (size_t)64 * K + k0);
    float4 b0 = *(const float4*)(Bp + k0);
    float4 b1 = *(const float4*)(Bp + (size_t)64 * K + k0);
    __syncthreads();
    As[lc+0][lr] = a0.x; As[lc+1][lr] = a0.y; As[lc+2][lr] = a0.z; As[lc+3][lr] = a0.w;
    As[lc+0][lr+64] = a1.x; As[lc+1][lr+64] = a1.y; As[lc+2][lr+64] = a1.z; As[lc+3][lr+64] = a1.w;
    Bs[lc+0][lr] = b0.x; Bs[lc+1][lr] = b0.y; Bs[lc+2][lr] = b0.z; Bs[lc+3][lr] = b0.w;
    Bs[lc+0][lr+64] = b1.x; Bs[lc+1][lr+64] = b1.y; Bs[lc+2][lr+64] = b1.z; Bs[lc+3][lr+64] = b1.w;
    __syncthreads();
    #pragma unroll
    for (int kk = 0; kk < 16; kk++) {
      float4 av0 = *(const float4*)&As[kk][ty * 8];
      float4 av1 = *(const float4*)&As[kk][ty * 8 + 4];
      float4 bv0 = *(const float4*)&Bs[kk][tx * 8];
      float4 bv1 = *(const float4*)&Bs[kk][tx * 8 + 4];
      float a[8] = {av0.x, av0.y, av0.z, av0.w, av1.x, av1.y, av1.z, av1.w};
      float bb[8] = {bv0.x, bv0.y, bv0.z, bv0.w, bv1.x, bv1.y, bv1.z, bv1.w};
      #pragma unroll
      for (int i = 0; i < 8; i++)
        #pragma unroll
        for (int j = 0; j < 8; j++) acc[i][j] += a[i] * bb[j];
    }
  }

  #pragma unroll
  for (int i = 0; i < 8; i++) {
    int row = bm + ty * 8 + i;
    #pragma unroll
    for (int j = 0; j < 8; j++) {
      int col = bn + tx * 8 + j;
      float v = acc[i][j] + bias[col];
      int l = row & Lmask;
      float df = expf((float)(col & ~1) * (-0.017988946039015984f));
      float arg = (float)l * df;
      v += (col & 1) ? cosf(arg) : sinf(arg);
      C[(size_t)row * N + col] = v;
    }
  }
}

// ------------------- 3xBF16 tensor-core GEMM (m16n8k16 + ldmatrix) ---------
#define KC 32                     // k elems per stage
#define LDPB 80                   // padded row stride in BYTES (40 bf16)
#define PLANE_B (128*LDPB)        // 10240 bytes per plane
#define STG_B (4*PLANE_B)         // 40960 bytes per stage

__device__ __forceinline__ void mma_bf16(float* c, const unsigned* a, const unsigned* b)
{
  asm volatile(
    "mma.sync.aligned.m16n8k16.row.col.f32.bf16.bf16.f32 "
    "{%0,%1,%2,%3},{%4,%5,%6,%7},{%8,%9},{%0,%1,%2,%3};\n"
    : "+f"(c[0]), "+f"(c[1]), "+f"(c[2]), "+f"(c[3])
    : "r"(a[0]), "r"(a[1]), "r"(a[2]), "r"(a[3]), "r"(b[0]), "r"(b[1]));
}

__device__ __forceinline__ void ldsm4(unsigned* r, const char* sptr)
{
  unsigned addr = (unsigned)__cvta_generic_to_shared(sptr);
  asm volatile("ldmatrix.sync.aligned.m8n8.x4.shared.b16 {%0,%1,%2,%3}, [%4];\n"
    : "=r"(r[0]), "=r"(r[1]), "=r"(r[2]), "=r"(r[3]) : "r"(addr));
}

// EPI 0: Cf = acc + bias (fp32)
// EPI 1: v = gelu(acc + bias); write bf16 split planes Chi/Clo
template<int EPI>
__global__ __launch_bounds__(256, 2) void mma_gemm(
    const __nv_bfloat16* __restrict__ Ahi, const __nv_bfloat16* __restrict__ Alo,
    const __nv_bfloat16* __restrict__ Bhi, const __nv_bfloat16* __restrict__ Blo,
    const float* __restrict__ bias,
    float* __restrict__ Cf, __nv_bfloat16* __restrict__ Chi,
    __nv_bfloat16* __restrict__ Clo, int M, int N, int K)
{
  extern __shared__ char smc[];
  const int tid = threadIdx.x;
  const int bm = blockIdx.y * 128, bn = blockIdx.x * 128;
  const int lane = tid & 31;
  const int g = lane >> 2, t4 = lane & 3;
  const int warp = tid >> 5;
  const int wm = warp >> 2, wn = warp & 3;      // warps 2(m) x 4(n)
  const int moff = wm * 64, noff = wn * 32;

  // ldmatrix per-lane byte offsets
  const int aoff = (lane & 15) * LDPB + ((lane & 16) ? 16 : 0);
  const int boff = ((lane & 7) + ((lane & 16) ? 8 : 0)) * LDPB + ((lane & 8) ? 16 : 0);

  float acc[4][4][4];
  #pragma unroll
  for (int i = 0; i < 4; i++)
    #pragma unroll
    for (int j = 0; j < 4; j++)
      #pragma unroll
      for (int q = 0; q < 4; q++) acc[i][j][q] = 0.f;

  const int KT = K / KC;

  // stage s <- k-tile kt: 4 planes, each 128 rows x 64B, padded to 80B rows
  #define PREFETCH(kt, s) do {                                                   \
    int k0_ = (kt) * KC;                                                         \
    const char* srcs_[4] = {                                                     \
      (const char*)(Ahi + (size_t)bm * K + k0_),                                 \
      (const char*)(Alo + (size_t)bm * K + k0_),                                 \
      (const char*)(Bhi + (size_t)bn * K + k0_),                                 \
      (const char*)(Blo + (size_t)bn * K + k0_) };                               \
    _Pragma("unroll")                                                            \
    for (int p_ = 0; p_ < 4; p_++) {                                             \
      char* dstp_ = smc + (s) * STG_B + p_ * PLANE_B;                            \
      _Pragma("unroll")                                                          \
      for (int j_ = 0; j_ < 2; j_++) {                                           \
        int idx_ = j_ * 256 + tid;                                               \
        int row_ = idx_ >> 2, ch_ = idx_ & 3;                                    \
        unsigned sa_ = (unsigned)__cvta_generic_to_shared(dstp_ + row_ * LDPB + ch_ * 16); \
        const char* ga_ = srcs_[p_] + (size_t)row_ * K * 2 + ch_ * 16;           \
        asm volatile("cp.async.ca.shared.global [%0], [%1], 16;\n"               \
                     :: "r"(sa_), "l"(ga_));                                     \
      }                                                                          \
    }                                                                            \
    asm volatile("cp.async.commit_group;\n");                                    \
  } while (0)

  PREFETCH(0, 0);

  for (int kt = 0; kt < KT; kt++) {
    asm volatile("cp.async.wait_group 0;\n");
    __syncthreads();
    if (kt + 1 < KT) PREFETCH(kt + 1, (kt + 1) & 1);

    const char* Sahi = smc + (kt & 1) * STG_B;
    const char* Salo = Sahi + PLANE_B;
    const char* Sbhi = Sahi + 2 * PLANE_B;
    const char* Sblo = Sahi + 3 * PLANE_B;

    #pragma unroll
    for (int ks = 0; ks < 2; ks++) {
      int kb = ks * 32;   // 16 bf16 = 32 bytes
      unsigned bh_[2][4], bl_[2][4];
      #pragma unroll
      for (int pp = 0; pp < 2; pp++) {
        ldsm4(bh_[pp], Sbhi + (noff + pp * 16) * LDPB + kb + boff);
        ldsm4(bl_[pp], Sblo + (noff + pp * 16) * LDPB + kb + boff);
      }
      #pragma unroll
      for (int tm = 0; tm < 4; tm++) {
        unsigned ah[4], al[4];
        ldsm4(ah, Sahi + (moff + tm * 16) * LDPB + kb + aoff);
        ldsm4(al, Salo + (moff + tm * 16) * LDPB + kb + aoff);
        #pragma unroll
        for (int tn = 0; tn < 4; tn++) {
          const unsigned* bhp = &bh_[tn >> 1][(tn & 1) * 2];
          const unsigned* blp = &bl_[tn >> 1][(tn & 1) * 2];
          mma_bf16(acc[tm][tn], ah, bhp);
          mma_bf16(acc[tm][tn], ah, blp);
          mma_bf16(acc[tm][tn], al, bhp);
        }
      }
    }
    __syncthreads();
  }

  // ---- epilogue ----
  #pragma unroll
  for (int tm = 0; tm < 4; tm++) {
    int r0 = bm + moff + tm * 16 + g;
    int r1 = r0 + 8;
    #pragma unroll
    for (int tn = 0; tn < 4; tn++) {
      int c0 = bn + noff + tn * 8 + 2 * t4;
      float b0 = bias[c0], b1 = bias[c0 + 1];
      float v00 = acc[tm][tn][0] + b0;
      float v01 = acc[tm][tn][1] + b1;
      float v10 = acc[tm][tn][2] + b0;
      float v11 = acc[tm][tn][3] + b1;
      if (EPI == 1) {
        v00 = 0.5f * v00 * (1.f + erff(v00 * 0.70710678118654752f));
        v01 = 0.5f * v01 * (1.f + erff(v01 * 0.70710678118654752f));
        v10 = 0.5f * v10 * (1.f + erff(v10 * 0.70710678118654752f));
        v11 = 0.5f * v11 * (1.f + erff(v11 * 0.70710678118654752f));
        __nv_bfloat16 h00, l00, h01, l01, h10, l10, h11, l11;
        split_bf16(v00, h00, l00); split_bf16(v01, h01, l01);
        split_bf16(v10, h10, l10); split_bf16(v11, h11, l11);
        *(__nv_bfloat162*)(Chi + (size_t)r0 * N + c0) = __nv_bfloat162(h00, h01);
        *(__nv_bfloat162*)(Clo + (size_t)r0 * N + c0) = __nv_bfloat162(l00, l01);
        *(__nv_bfloat162*)(Chi + (size_t)r1 * N + c0) = __nv_bfloat162(h10, h11);
        *(__nv_bfloat162*)(Clo + (size_t)r1 * N + c0) = __nv_bfloat162(l10, l11);
      } else {
        *(float2*)(Cf + (size_t)r0 * N + c0) = make_float2(v00, v01);
        *(float2*)(Cf + (size_t)r1 * N + c0) = make_float2(v10, v11);
      }
    }
  }
  #undef PREFETCH
}

// ------------------- host: layer key derivation ----------------------------
static void layer_key(int i, unsigned &k0, unsigned &k1)
{
  unsigned a = 0u, b = (unsigned)i;
  threefry2x32(0u, 42u, a, b);
  unsigned c = 0u, d = 1u;
  threefry2x32(a, b, c, d);
  k0 = c; k1 = d;
}

extern "C" void kernel_launch(void* const* d_in, const int* in_sizes, int n_in,
                              void* d_out, int out_size)
{
  const float* x     = (const float*)d_in[0];
  const float* emb_w = (const float*)d_in[1];
  const float* emb_b = (const float*)d_in[2];
  const float* ln1_s = (const float*)d_in[3];
  const float* ln1_b = (const float*)d_in[4];
  const float* w1    = (const float*)d_in[5];
  const float* b1    = (const float*)d_in[6];
  const float* w2    = (const float*)d_in[7];
  const float* b2    = (const float*)d_in[8];
  const float* ln2_s = (const float*)d_in[9];
  const float* ln2_b = (const float*)d_in[10];
  const float* out_w = (const float*)d_in[11];
  const float* out_b = (const float*)d_in[12];
  float* out = (float*)d_out;

  float *ph, *poth, *px, *pz;
  __nv_bfloat16 *pxhi, *pxlo, *pyhi, *pylo;
  __nv_bfloat16 *pw1hi, *pw1lo, *pw2hi, *pw2lo, *powhi, *powlo;
  cudaGetSymbolAddress((void**)&ph,   g_h);
  cudaGetSymbolAddress((void**)&poth, g_h2);
  cudaGetSymbolAddress((void**)&px,   g_x);
  cudaGetSymbolAddress((void**)&pz,   g_z);
  cudaGetSymbolAddress((void**)&pxhi, g_xhi);
  cudaGetSymbolAddress((void**)&pxlo, g_xlo);
  cudaGetSymbolAddress((void**)&pyhi, g_yhi);
  cudaGetSymbolAddress((void**)&pylo, g_ylo);
  cudaGetSymbolAddress((void**)&pw1hi, g_w1hi);
  cudaGetSymbolAddress((void**)&pw1lo, g_w1lo);
  cudaGetSymbolAddress((void**)&pw2hi, g_w2hi);
  cudaGetSymbolAddress((void**)&pw2lo, g_w2lo);
  cudaGetSymbolAddress((void**)&powhi, g_owhi);
  cudaGetSymbolAddress((void**)&powlo, g_owlo);

  static int smem_set = 0;
  if (!smem_set) {
    cudaFuncSetAttribute(mma_gemm<0>, cudaFuncAttributeMaxDynamicSharedMemorySize, 2 * STG_B);
    cudaFuncSetAttribute(mma_gemm<1>, cudaFuncAttributeMaxDynamicSharedMemorySize, 2 * STG_B);
    cudaFuncSetAttribute(ctx_batched_kernel, cudaFuncAttributeMaxDynamicSharedMemorySize, CTX_SMEM_FLOATS * 4);
    smem_set = 1;
  }
  const int smem_bytes = 2 * STG_B;   // 80KB
  const int ctx_smem = CTX_SMEM_FLOATS * 4;

  // Split weights into bf16 hi/lo
  {
    int n1 = 3 * DFF * DD;
    wsplit_kernel<<<(n1 + 255) / 256, 256>>>(w1, pw1hi, pw1lo, n1);
    wsplit_kernel<<<(n1 + 255) / 256, 256>>>(w2, pw2hi, pw2lo, n1);
    int n2 = DD * DD;
    wsplit_kernel<<<(n2 + 255) / 256, 256>>>(out_w, powhi, powlo, n2);
  }

  // Embed: h = x @ emb_w^T + emb_b + PE   (M=32768, N=512, K=64)
  {
    int M = BB * L0;
    sgemm_embed<<<dim3(DD / 128, M / 128), 256>>>(x, emb_w, emb_b, ph, M, DD, 64, L0 - 1);
  }

  int L = L0;
  float* cur = ph;
  for (int i = 0; i < 3; i++) {
    int u = (i == 0) ? 45 : (i == 1) ? 40 : 35;
    int M = BB * L;
    unsigned k0, k1; layer_key(i, k0, k1);
    int total = L * u;
    idx_part<<<(total + 255) / 256, 256>>>(k0, k1, total, L - 1);
    prob_m_kernel<<<dim3(L / 8, 64), 256>>>(cur, L, u, 1.0f / (float)L);
    topk_kernel<<<64, 256>>>(L, u);
    qmean_kernel<<<64, 512>>>(cur, L);
    ctx_batched_kernel<<<64, 256, ctx_smem>>>(cur, L, u);
    assemble_ln1_kernel<<<M, 128>>>(cur, px, pxhi, pxlo,
                                    ln1_s + i * DD, ln1_b + i * DD, L, u);

    // FFN1: y = gelu(x @ w1^T + b1)  -> bf16 split planes
    mma_gemm<1><<<dim3(DFF / 128, M / 128), 256, smem_bytes>>>(
        pxhi, pxlo, pw1hi + (size_t)i * DFF * DD, pw1lo + (size_t)i * DFF * DD,
        b1 + i * DFF, nullptr, pyhi, pylo, M, DFF, DD);
    // FFN2: z = y @ w2^T + b2  (fp32 out)
    mma_gemm<0><<<dim3(DD / 128, M / 128), 256, smem_bytes>>>(
        pyhi, pylo, pw2hi + (size_t)i * DD * DFF, pw2lo + (size_t)i * DD * DFF,
        b2 + i * DD, pz, nullptr, nullptr, M, DD, DFF);

    ln2_kernel<<<M, 128>>>(px, pz, poth,
                           (i == 2) ? pxhi : (__nv_bfloat16*)nullptr,
                           (i == 2) ? pxlo : (__nv_bfloat16*)nullptr,
                           ln2_s + i * DD, ln2_b + i * DD);

    if (i < 2) {
      int L2 = L / 2;
      int tot = BB * L2 * DD;
      distil_kernel<<<(tot + 255) / 256, 256>>>(poth, cur, L2);
      L = L2;
    }
  }

  // Final projection: out = h @ out_w^T + out_b  (M=8192, N=512, K=512)
  {
    int M = BB * L;   // L = 1024
    mma_gemm<0><<<dim3(DD / 128, M / 128), 256, smem_bytes>>>(
        pxhi, pxlo, powhi, powlo, out_b, out, nullptr, nullptr, M, DD, DD);
  }
}

// round 7
// speedup vs baseline: 2.2006x; 1.1418x over previous
#include <cuda_runtime.h>
#include <cuda_fp16.h>
#include <math.h>
#include <stdint.h>

#define BB 8
#define DD 512
#define DFF 2048
#define L0 4096
#define UMAX 45
#define LN_EPS 1e-5f

// ------------------- scratch (device globals; no allocs) -------------------
__device__ __align__(16) float g_h  [BB*L0*DD];
__device__ __align__(16) float g_x  [BB*L0*DD];
__device__ __align__(16) float g_z  [BB*L0*DD];
__device__ __align__(16) __half g_xhi[BB*L0*DD];
__device__ __align__(16) __half g_xlo[BB*L0*DD];
__device__ __align__(16) __half g_yhi[BB*L0*DFF];
__device__ __align__(16) __half g_ylo[BB*L0*DFF];
__device__ __align__(16) __half g_w1hi[3*DFF*DD];
__device__ __align__(16) __half g_w2hi[3*DD*DFF];
__device__ __align__(16) __half g_owhi[DD*DD];
__device__ __align__(16) float g_M  [BB*8*L0];
__device__ __align__(16) int   g_idx[L0*UMAX];
__device__ __align__(16) int   g_top[BB*8*UMAX];
__device__ __align__(16) int   g_rowmap[BB*8*L0];
__device__ __align__(16) float g_ctx[BB*8*UMAX*64];
__device__ __align__(16) float g_qmean[BB*8*64];

// ------------------- fp16 split helpers -------------------------------------
__device__ __forceinline__ void split_fp16(float v, __half &hi, __half &lo)
{
  hi = __float2half_rn(v);
  lo = __float2half_rn(v - __half2float(hi));
}

// ------------------- threefry2x32 (JAX-compatible) -------------------------
#define TF_R(x0,x1,r) { x0 += x1; x1 = ((x1 << (r)) | (x1 >> (32-(r)))); x1 ^= x0; }
__host__ __device__ inline void threefry2x32(unsigned ks0, unsigned ks1,
                                             unsigned &x0, unsigned &x1)
{
  unsigned ks2 = ks0 ^ ks1 ^ 0x1BD11BDAu;
  x0 += ks0; x1 += ks1;
  TF_R(x0,x1,13) TF_R(x0,x1,15) TF_R(x0,x1,26) TF_R(x0,x1,6)
  x0 += ks1; x1 += ks2 + 1u;
  TF_R(x0,x1,17) TF_R(x0,x1,29) TF_R(x0,x1,16) TF_R(x0,x1,24)
  x0 += ks2; x1 += ks0 + 2u;
  TF_R(x0,x1,13) TF_R(x0,x1,15) TF_R(x0,x1,26) TF_R(x0,x1,6)
  x0 += ks0; x1 += ks1 + 3u;
  TF_R(x0,x1,17) TF_R(x0,x1,29) TF_R(x0,x1,16) TF_R(x0,x1,24)
  x0 += ks1; x1 += ks2 + 4u;
  TF_R(x0,x1,13) TF_R(x0,x1,15) TF_R(x0,x1,26) TF_R(x0,x1,6)
  x0 += ks2; x1 += ks0 + 5u;
}

__global__ void idx_part(unsigned k0, unsigned k1, int total, int mask)
{
  int t = blockIdx.x * 256 + threadIdx.x;
  if (t >= total) return;
  unsigned x0 = 0u, x1 = (unsigned)t;
  threefry2x32(k0, k1, x0, x1);
  g_idx[t] = (int)((x0 ^ x1) & (unsigned)mask);
}

// ------------------- weight -> fp16 hi only ----------------------------------
__global__ void whalf_kernel(const float* __restrict__ w,
                             __half* __restrict__ hi, int n)
{
  int i = blockIdx.x * 256 + threadIdx.x;
  if (i >= n) return;
  hi[i] = __float2half_rn(w[i]);
}

// ------------------- M = max_s qk - sum_s qk / L ----------------------------
__global__ __launch_bounds__(256) void prob_m_kernel(
    const float* __restrict__ h, int L, int u, float invL)
{
  __shared__ float qs[8][64];
  int bh = blockIdx.y; int b = bh >> 3, hh = bh & 7;
  int warp = threadIdx.x >> 5, lane = threadIdx.x & 31;
  int l = blockIdx.x * 8 + warp;
  const float* base = h + (size_t)b * L * DD + hh * 64;
  const float* qrow = base + (size_t)l * DD;
  qs[warp][lane]      = qrow[lane];
  qs[warp][lane + 32] = qrow[lane + 32];
  __syncwarp();
  float mx = -INFINITY, sm = 0.f;
  for (int s = lane; s < u; s += 32) {
    int kl = g_idx[l * u + s];
    const float4* krow = (const float4*)(base + (size_t)kl * DD);
    float dot = 0.f;
    #pragma unroll
    for (int q4 = 0; q4 < 16; q4++) {
      float4 kv = krow[q4];
      dot += qs[warp][q4*4+0]*kv.x + qs[warp][q4*4+1]*kv.y
           + qs[warp][q4*4+2]*kv.z + qs[warp][q4*4+3]*kv.w;
    }
    mx = fmaxf(mx, dot); sm += dot;
  }
  #pragma unroll
  for (int o = 16; o; o >>= 1) {
    mx = fmaxf(mx, __shfl_xor_sync(0xffffffffu, mx, o));
    sm += __shfl_xor_sync(0xffffffffu, sm, o);
  }
  if (lane == 0) g_M[(size_t)bh * L + l] = mx - sm * invL;
}

// ------------------- top-k (iterative argmax, lower-index tiebreak) --------
__global__ __launch_bounds__(256) void topk_kernel(int L, int u)
{
  __shared__ float sM[L0];
  __shared__ float sval[256];
  __shared__ int   sidx[256];
  int bh = blockIdx.x;
  int tid = threadIdx.x;
  for (int l = tid; l < L; l += 256) {
    sM[l] = g_M[(size_t)bh * L + l];
    g_rowmap[(size_t)bh * L + l] = -1;
  }
  __syncthreads();
  for (int r = 0; r < u; r++) {
    float bv = -INFINITY; int bi = 0x7fffffff;
    for (int l = tid; l < L; l += 256) {
      float v = sM[l];
      if (v > bv || (v == bv && l < bi)) { bv = v; bi = l; }
    }
    sval[tid] = bv; sidx[tid] = bi;
    __syncthreads();
    for (int st = 128; st > 0; st >>= 1) {
      if (tid < st) {
        float v2 = sval[tid + st]; int i2 = sidx[tid + st];
        if (v2 > sval[tid] || (v2 == sval[tid] && i2 < sidx[tid])) {
          sval[tid] = v2; sidx[tid] = i2;
        }
      }
      __syncthreads();
    }
    if (tid == 0) {
      int sel = sidx[0];
      g_top[bh * u + r] = sel;
      g_rowmap[(size_t)bh * L + sel] = r;
      sM[sel] = -INFINITY;
    }
    __syncthreads();
  }
}

// ------------------- qmean over L per (b,h,d) -------------------------------
__global__ __launch_bounds__(512) void qmean_kernel(const float* __restrict__ h, int L)
{
  __shared__ float part[512];
  int bh = blockIdx.x; int b = bh >> 3, hh = bh & 7;
  int tid = threadIdx.x; int d = tid & 63; int p = tid >> 6;
  const float* base = h + (size_t)b * L * DD + hh * 64;
  float s = 0.f;
  for (int l = p; l < L; l += 8) s += base[(size_t)l * DD + d];
  part[tid] = s;
  __syncthreads();
  if (p == 0) {
    float t = 0.f;
    #pragma unroll
    for (int q = 0; q < 8; q++) t += part[q * 64 + d];
    g_qmean[bh * 64 + d] = t / (float)L;
  }
}

// ------------------- batched ctx: one CTA per (b,h), single key sweep ------
#define CTX_SMEM_FLOATS (13568 + 144)
__global__ __launch_bounds__(256) void ctx_batched_kernel(
    const float* __restrict__ h, int L, int u)
{
  extern __shared__ float dsm[];
  float* qs   = dsm;            // stride 64
  float* kt   = dsm + 3072;     // stride 68
  float* sc   = dsm + 7424;     // stride 64
  float* ctxs = dsm + 10496;    // stride 64
  float* rm   = dsm + 13568;
  float* rs   = dsm + 13616;
  float* rsc  = dsm + 13664;

  int bh = blockIdx.x; int b = bh >> 3, hh = bh & 7;
  const float* base = h + (size_t)b * L * DD + hh * 64;
  int tid = threadIdx.x;

  for (int e = tid; e < u * 64; e += 256) {
    int r = e >> 6, d = e & 63;
    qs[r * 64 + d] = base[(size_t)g_top[bh * u + r] * DD + d];
    ctxs[e] = 0.f;
  }
  if (tid < u) { rm[tid] = -INFINITY; rs[tid] = 0.f; }
  __syncthreads();

  const int j  = tid & 63;
  const int rg = tid >> 6;
  const int w  = tid >> 5, lane = tid & 31;

  for (int t0 = 0; t0 < L; t0 += 64) {
    for (int e = tid; e < 64 * 16; e += 256) {
      int r = e >> 4, c4 = e & 15;
      float4 v = *(const float4*)(base + (size_t)(t0 + r) * DD + c4 * 4);
      float* kr = kt + r * 68 + c4 * 4;
      kr[0] = v.x; kr[1] = v.y; kr[2] = v.z; kr[3] = v.w;
    }
    __syncthreads();
    {
      float kreg[64];
      #pragma unroll
      for (int d = 0; d < 64; d++) kreg[d] = kt[j * 68 + d];
      for (int r = rg; r < u; r += 4) {
        const float* qr = qs + r * 64;
        float dot = 0.f;
        #pragma unroll
        for (int d = 0; d < 64; d++) dot += qr[d] * kreg[d];
        sc[r * 64 + j] = dot * 0.125f;
      }
    }
    __syncthreads();
    for (int r = w; r < u; r += 8) {
      float v0 = sc[r * 64 + lane], v1 = sc[r * 64 + lane + 32];
      float mx = fmaxf(v0, v1);
      #pragma unroll
      for (int o = 16; o; o >>= 1) mx = fmaxf(mx, __shfl_xor_sync(0xffffffffu, mx, o));
      float mold = rm[r];
      float mnew = fmaxf(mold, mx);
      float p0 = __expf(v0 - mnew), p1 = __expf(v1 - mnew);
      float ps = p0 + p1;
      #pragma unroll
      for (int o = 16; o; o >>= 1) ps += __shfl_xor_sync(0xffffffffu, ps, o);
      if (lane == 0) {
        float cold = __expf(mold - mnew);
        rsc[r] = cold;
        rs[r] = rs[r] * cold + ps;
        rm[r] = mnew;
      }
      sc[r * 64 + lane] = p0; sc[r * 64 + lane + 32] = p1;
    }
    __syncthreads();
    for (int r = rg; r < u; r += 4) {
      const float* pr = sc + r * 64;
      float a = 0.f;
      #pragma unroll
      for (int jj = 0; jj < 64; jj++) a += pr[jj] * kt[jj * 68 + j];
      ctxs[r * 64 + j] = ctxs[r * 64 + j] * rsc[r] + a;
    }
    __syncthreads();
  }

  for (int e = tid; e < u * 64; e += 256) {
    int r = e >> 6, d = e & 63;
    g_ctx[((size_t)(bh * u + r)) * 64 + d] = ctxs[r * 64 + d] / rs[r];
  }
}

// ------------------- block reduce helper (128 threads) ---------------------
__device__ __forceinline__ float blocksum128(float v, float* sred)
{
  #pragma unroll
  for (int o = 16; o; o >>= 1) v += __shfl_xor_sync(0xffffffffu, v, o);
  if ((threadIdx.x & 31) == 0) sred[threadIdx.x >> 5] = v;
  __syncthreads();
  float t = sred[0] + sred[1] + sred[2] + sred[3];
  __syncthreads();
  return t;
}

// ------------------- assemble attention out + residual + LN1 + fp16 split --
__global__ __launch_bounds__(128) void assemble_ln1_kernel(
    const float* __restrict__ hin, float* __restrict__ xout,
    __half* __restrict__ xhi, __half* __restrict__ xlo,
    const float* __restrict__ gamma, const float* __restrict__ beta,
    int L, int u)
{
  __shared__ float sred[4];
  int row = blockIdx.x;
  int b = row / L, l = row - b * L;
  int tid = threadIdx.x;
  float v[4];
  #pragma unroll
  for (int i = 0; i < 4; i++) {
    int e = i * 128 + tid;
    int hh = e >> 6, dd = e & 63;
    int bh = b * 8 + hh;
    int r = g_rowmap[(size_t)bh * L + l];
    float nv = (r >= 0) ? g_ctx[((size_t)(bh * u + r)) * 64 + dd]
                        : g_qmean[bh * 64 + dd];
    v[i] = hin[(size_t)row * DD + e] + nv;
  }
  float s = blocksum128(v[0] + v[1] + v[2] + v[3], sred);
  float mu = s * (1.0f / 512.0f);
  float vs = 0.f;
  #pragma unroll
  for (int i = 0; i < 4; i++) { float d = v[i] - mu; vs += d * d; }
  vs = blocksum128(vs, sred);
  float rstd = rsqrtf(vs * (1.0f / 512.0f) + LN_EPS);
  #pragma unroll
  for (int i = 0; i < 4; i++) {
    int e = i * 128 + tid;
    float o = (v[i] - mu) * rstd * gamma[e] + beta[e];
    xout[(size_t)row * DD + e] = o;
    __half h16, l16;
    split_fp16(o, h16, l16);
    xhi[(size_t)row * DD + e] = h16;
    xlo[(size_t)row * DD + e] = l16;
  }
}

// ------------------- fused residual+LN2+distil (layers 0,1) ----------------
// one block per OUTPUT row (b,l2): LN rows 2*l2, 2*l2+1 then average
__global__ __launch_bounds__(128) void ln2_distil_kernel(
    const float* __restrict__ xin, const float* __restrict__ zin,
    float* __restrict__ outp,
    const float* __restrict__ gamma, const float* __restrict__ beta, int L2)
{
  __shared__ float sred[4];
  int rowo = blockIdx.x;
  int b = rowo / L2, l2 = rowo - b * L2;
  size_t r0 = ((size_t)b * (2 * L2) + 2 * l2);
  int tid = threadIdx.x;
  float o01[4];
  #pragma unroll
  for (int half = 0; half < 2; half++) {
    size_t row = r0 + half;
    float v[4];
    #pragma unroll
    for (int i = 0; i < 4; i++) {
      int e = i * 128 + tid;
      v[i] = xin[row * DD + e] + zin[row * DD + e];
    }
    float s = blocksum128(v[0] + v[1] + v[2] + v[3], sred);
    float mu = s * (1.0f / 512.0f);
    float vs = 0.f;
    #pragma unroll
    for (int i = 0; i < 4; i++) { float d = v[i] - mu; vs += d * d; }
    vs = blocksum128(vs, sred);
    float rstd = rsqrtf(vs * (1.0f / 512.0f) + LN_EPS);
    #pragma unroll
    for (int i = 0; i < 4; i++) {
      int e = i * 128 + tid;
      float o = (v[i] - mu) * rstd * gamma[e] + beta[e];
      if (half == 0) o01[i] = o; else o01[i] = 0.5f * (o01[i] + o);
    }
  }
  #pragma unroll
  for (int i = 0; i < 4; i++) {
    int e = i * 128 + tid;
    outp[(size_t)rowo * DD + e] = o01[i];
  }
}

// ------------------- residual + LN2 -> fp16 split only (last layer) --------
__global__ __launch_bounds__(128) void ln2_split_kernel(
    const float* __restrict__ xin, const float* __restrict__ zin,
    __half* __restrict__ ohi, __half* __restrict__ olo,
    const float* __restrict__ gamma, const float* __restrict__ beta)
{
  __shared__ float sred[4];
  size_t row = blockIdx.x;
  int tid = threadIdx.x;
  float v[4];
  #pragma unroll
  for (int i = 0; i < 4; i++) {
    int e = i * 128 + tid;
    v[i] = xin[row * DD + e] + zin[row * DD + e];
  }
  float s = blocksum128(v[0] + v[1] + v[2] + v[3], sred);
  float mu = s * (1.0f / 512.0f);
  float vs = 0.f;
  #pragma unroll
  for (int i = 0; i < 4; i++) { float d = v[i] - mu; vs += d * d; }
  vs = blocksum128(vs, sred);
  float rstd = rsqrtf(vs * (1.0f / 512.0f) + LN_EPS);
  #pragma unroll
  for (int i = 0; i < 4; i++) {
    int e = i * 128 + tid;
    float o = (v[i] - mu) * rstd * gamma[e] + beta[e];
    __half h16, l16;
    split_fp16(o, h16, l16);
    ohi[row * DD + e] = h16;
    olo[row * DD + e] = l16;
  }
}

// ------------------- SIMT SGEMM (embed only): C = A*B^T + bias + PE --------
__global__ __launch_bounds__(256, 2) void sgemm_embed(
    const float* __restrict__ A, const float* __restrict__ Bm,
    const float* __restrict__ bias, float* __restrict__ C,
    int M, int N, int K, int Lmask)
{
  __shared__ float As[16][132];
  __shared__ float Bs[16][132];
  const int bm = blockIdx.y * 128, bn = blockIdx.x * 128;
  const int t = threadIdx.x;
  const int lr = t >> 2;
  const int lc = (t & 3) << 2;
  const int tx = t & 15, ty = t >> 4;
  float acc[8][8];
  #pragma unroll
  for (int i = 0; i < 8; i++)
    #pragma unroll
    for (int j = 0; j < 8; j++) acc[i][j] = 0.f;

  const float* Ap = A + (size_t)(bm + lr) * K + lc;
  const float* Bp = Bm + (size_t)(bn + lr) * K + lc;

  for (int k0 = 0; k0 < K; k0 += 16) {
    float4 a0 = *(const float4*)(Ap + k0);
    float4 a1 = *(const float4*)(Ap + (size_t)64 * K + k0);
    float4 b0 = *(const float4*)(Bp + k0);
    float4 b1 = *(const float4*)(Bp + (size_t)64 * K + k0);
    __syncthreads();
    As[lc+0][lr] = a0.x; As[lc+1][lr] = a0.y; As[lc+2][lr] = a0.z; As[lc+3][lr] = a0.w;
    As[lc+0][lr+64] = a1.x; As[lc+1][lr+64] = a1.y; As[lc+2][lr+64] = a1.z; As[lc+3][lr+64] = a1.w;
    Bs[lc+0][lr] = b0.x; Bs[lc+1][lr] = b0.y; Bs[lc+2][lr] = b0.z; Bs[lc+3][lr] = b0.w;
    Bs[lc+0][lr+64] = b1.x; Bs[lc+1][lr+64] = b1.y; Bs[lc+2][lr+64] = b1.z; Bs[lc+3][lr+64] = b1.w;
    __syncthreads();
    #pragma unroll
    for (int kk = 0; kk < 16; kk++) {
      float4 av0 = *(const float4*)&As[kk][ty * 8];
      float4 av1 = *(const float4*)&As[kk][ty * 8 + 4];
      float4 bv0 = *(const float4*)&Bs[kk][tx * 8];
      float4 bv1 = *(const float4*)&Bs[kk][tx * 8 + 4];
      float a[8] = {av0.x, av0.y, av0.z, av0.w, av1.x, av1.y, av1.z, av1.w};
      float bb[8] = {bv0.x, bv0.y, bv0.z, bv0.w, bv1.x, bv1.y, bv1.z, bv1.w};
      #pragma unroll
      for (int i = 0; i < 8; i++)
        #pragma unroll
        for (int j = 0; j < 8; j++) acc[i][j] += a[i] * bb[j];
    }
  }

  #pragma unroll
  for (int i = 0; i < 8; i++) {
    int row = bm + ty * 8 + i;
    #pragma unroll
    for (int j = 0; j < 8; j++) {
      int col = bn + tx * 8 + j;
      float v = acc[i][j] + bias[col];
      int l = row & Lmask;
      float df = expf((float)(col & ~1) * (-0.017988946039015984f));
      float arg = (float)l * df;
      v += (col & 1) ? cosf(arg) : sinf(arg);
      C[(size_t)row * N + col] = v;
    }
  }
}

// ------------------- 2-pass fp16 tensor-core GEMM (m16n8k16 + ldmatrix) ----
// C = (Ahi+Alo) * Bhi^T : A carried to ~22 bits, B rounded once to fp16.
#define KC 32                     // k elems per stage
#define LDPB 80                   // padded row stride in BYTES (40 fp16)
#define PLANE_B (128*LDPB)        // 10240 bytes per plane
#define STG_B (3*PLANE_B)         // 30720 bytes per stage (A_hi, A_lo, B_hi)

__device__ __forceinline__ void mma_fp16(float* c, const unsigned* a, const unsigned* b)
{
  asm volatile(
    "mma.sync.aligned.m16n8k16.row.col.f32.f16.f16.f32 "
    "{%0,%1,%2,%3},{%4,%5,%6,%7},{%8,%9},{%0,%1,%2,%3};\n"
    : "+f"(c[0]), "+f"(c[1]), "+f"(c[2]), "+f"(c[3])
    : "r"(a[0]), "r"(a[1]), "r"(a[2]), "r"(a[3]), "r"(b[0]), "r"(b[1]));
}

__device__ __forceinline__ void ldsm4(unsigned* r, const char* sptr)
{
  unsigned addr = (unsigned)__cvta_generic_to_shared(sptr);
  asm volatile("ldmatrix.sync.aligned.m8n8.x4.shared.b16 {%0,%1,%2,%3}, [%4];\n"
    : "=r"(r[0]), "=r"(r[1]), "=r"(r[2]), "=r"(r[3]) : "r"(addr));
}

// EPI 0: Cf = acc + bias (fp32)
// EPI 1: v = gelu(acc + bias); write fp16 split planes Chi/Clo
template<int EPI>
__global__ __launch_bounds__(256, 2) void mma_gemm(
    const __half* __restrict__ Ahi, const __half* __restrict__ Alo,
    const __half* __restrict__ Bhi,
    const float* __restrict__ bias,
    float* __restrict__ Cf, __half* __restrict__ Chi,
    __half* __restrict__ Clo, int M, int N, int K)
{
  extern __shared__ char smc[];
  const int tid = threadIdx.x;
  const int bm = blockIdx.y * 128, bn = blockIdx.x * 128;
  const int lane = tid & 31;
  const int g = lane >> 2, t4 = lane & 3;
  const int warp = tid >> 5;
  const int wm = warp >> 2, wn = warp & 3;      // warps 2(m) x 4(n)
  const int moff = wm * 64, noff = wn * 32;

  // ldmatrix per-lane byte offsets
  const int aoff = (lane & 15) * LDPB + ((lane & 16) ? 16 : 0);
  const int boff = ((lane & 7) + ((lane & 16) ? 8 : 0)) * LDPB + ((lane & 8) ? 16 : 0);

  float acc[4][4][4];
  #pragma unroll
  for (int i = 0; i < 4; i++)
    #pragma unroll
    for (int j = 0; j < 4; j++)
      #pragma unroll
      for (int q = 0; q < 4; q++) acc[i][j][q] = 0.f;

  const int KT = K / KC;

  // stage s <- k-tile kt: 3 planes, each 128 rows x 64B data, padded to 80B
  #define PREFETCH(kt, s) do {                                                   \
    int k0_ = (kt) * KC;                                                         \
    const char* srcs_[3] = {                                                     \
      (const char*)(Ahi + (size_t)bm * K + k0_),                                 \
      (const char*)(Alo + (size_t)bm * K + k0_),                                 \
      (const char*)(Bhi + (size_t)bn * K + k0_) };                               \
    _Pragma("unroll")                                                            \
    for (int p_ = 0; p_ < 3; p_++) {                                             \
      char* dstp_ = smc + (s) * STG_B + p_ * PLANE_B;                            \
      _Pragma("unroll")                                                          \
      for (int j_ = 0; j_ < 2; j_++) {                                           \
        int idx_ = j_ * 256 + tid;                                               \
        int row_ = idx_ >> 2, ch_ = idx_ & 3;                                    \
        unsigned sa_ = (unsigned)__cvta_generic_to_shared(dstp_ + row_ * LDPB + ch_ * 16); \
        const char* ga_ = srcs_[p_] + (size_t)row_ * K * 2 + ch_ * 16;           \
        asm volatile("cp.async.ca.shared.global [%0], [%1], 16;\n"               \
                     :: "r"(sa_), "l"(ga_));                                     \
      }                                                                          \
    }                                                                            \
    asm volatile("cp.async.commit_group;\n");                                    \
  } while (0)

  PREFETCH(0, 0);

  for (int kt = 0; kt < KT; kt++) {
    asm volatile("cp.async.wait_group 0;\n");
    __syncthreads();
    if (kt + 1 < KT) PREFETCH(kt + 1, (kt + 1) & 1);

    const char* Sahi = smc + (kt & 1) * STG_B;
    const char* Salo = Sahi + PLANE_B;
    const char* Sbhi = Sahi + 2 * PLANE_B;

    #pragma unroll
    for (int ks = 0; ks < 2; ks++) {
      int kb = ks * 32;   // 16 fp16 = 32 bytes
      unsigned bh_[2][4];
      #pragma unroll
      for (int pp = 0; pp < 2; pp++)
        ldsm4(bh_[pp], Sbhi + (noff + pp * 16) * LDPB + kb + boff);
      #pragma unroll
      for (int tm = 0; tm < 4; tm++) {
        unsigned ah[4], al[4];
        ldsm4(ah, Sahi + (moff + tm * 16) * LDPB + kb + aoff);
        ldsm4(al, Salo + (moff + tm * 16) * LDPB + kb + aoff);
        #pragma unroll
        for (int tn = 0; tn < 4; tn++) {
          const unsigned* bhp = &bh_[tn >> 1][(tn & 1) * 2];
          mma_fp16(acc[tm][tn], ah, bhp);
          mma_fp16(acc[tm][tn], al, bhp);
        }
      }
    }
    __syncthreads();
  }

  // ---- epilogue ----
  #pragma unroll
  for (int tm = 0; tm < 4; tm++) {
    int r0 = bm + moff + tm * 16 + g;
    int r1 = r0 + 8;
    #pragma unroll
    for (int tn = 0; tn < 4; tn++) {
      int c0 = bn + noff + tn * 8 + 2 * t4;
      float b0 = bias[c0], b1 = bias[c0 + 1];
      float v00 = acc[tm][tn][0] + b0;
      float v01 = acc[tm][tn][1] + b1;
      float v10 = acc[tm][tn][2] + b0;
      float v11 = acc[tm][tn][3] + b1;
      if (EPI == 1) {
        v00 = 0.5f * v00 * (1.f + erff(v00 * 0.70710678118654752f));
        v01 = 0.5f * v01 * (1.f + erff(v01 * 0.70710678118654752f));
        v10 = 0.5f * v10 * (1.f + erff(v10 * 0.70710678118654752f));
        v11 = 0.5f * v11 * (1.f + erff(v11 * 0.70710678118654752f));
        __half h00, l00, h01, l01, h10, l10, h11, l11;
        split_fp16(v00, h00, l00); split_fp16(v01, h01, l01);
        split_fp16(v10, h10, l10); split_fp16(v11, h11, l11);
        *(__half2*)(Chi + (size_t)r0 * N + c0) = __halves2half2(h00, h01);
        *(__half2*)(Clo + (size_t)r0 * N + c0) = __halves2half2(l00, l01);
        *(__half2*)(Chi + (size_t)r1 * N + c0) = __halves2half2(h10, h11);
        *(__half2*)(Clo + (size_t)r1 * N + c0) = __halves2half2(l10, l11);
      } else {
        *(float2*)(Cf + (size_t)r0 * N + c0) = make_float2(v00, v01);
        *(float2*)(Cf + (size_t)r1 * N + c0) = make_float2(v10, v11);
      }
    }
  }
  #undef PREFETCH
}

// ------------------- host: layer key derivation ----------------------------
static void layer_key(int i, unsigned &k0, unsigned &k1)
{
  unsigned a = 0u, b = (unsigned)i;
  threefry2x32(0u, 42u, a, b);
  unsigned c = 0u, d = 1u;
  threefry2x32(a, b, c, d);
  k0 = c; k1 = d;
}

extern "C" void kernel_launch(void* const* d_in, const int* in_sizes, int n_in,
                              void* d_out, int out_size)
{
  const float* x     = (const float*)d_in[0];
  const float* emb_w = (const float*)d_in[1];
  const float* emb_b = (const float*)d_in[2];
  const float* ln1_s = (const float*)d_in[3];
  const float* ln1_b = (const float*)d_in[4];
  const float* w1    = (const float*)d_in[5];
  const float* b1    = (const float*)d_in[6];
  const float* w2    = (const float*)d_in[7];
  const float* b2    = (const float*)d_in[8];
  const float* ln2_s = (const float*)d_in[9];
  const float* ln2_b = (const float*)d_in[10];
  const float* out_w = (const float*)d_in[11];
  const float* out_b = (const float*)d_in[12];
  float* out = (float*)d_out;

  float *ph, *px, *pz;
  __half *pxhi, *pxlo, *pyhi, *pylo;
  __half *pw1hi, *pw2hi, *powhi;
  cudaGetSymbolAddress((void**)&ph,   g_h);
  cudaGetSymbolAddress((void**)&px,   g_x);
  cudaGetSymbolAddress((void**)&pz,   g_z);
  cudaGetSymbolAddress((void**)&pxhi, g_xhi);
  cudaGetSymbolAddress((void**)&pxlo, g_xlo);
  cudaGetSymbolAddress((void**)&pyhi, g_yhi);
  cudaGetSymbolAddress((void**)&pylo, g_ylo);
  cudaGetSymbolAddress((void**)&pw1hi, g_w1hi);
  cudaGetSymbolAddress((void**)&pw2hi, g_w2hi);
  cudaGetSymbolAddress((void**)&powhi, g_owhi);

  static int smem_set = 0;
  if (!smem_set) {
    cudaFuncSetAttribute(mma_gemm<0>, cudaFuncAttributeMaxDynamicSharedMemorySize, 2 * STG_B);
    cudaFuncSetAttribute(mma_gemm<1>, cudaFuncAttributeMaxDynamicSharedMemorySize, 2 * STG_B);
    cudaFuncSetAttribute(ctx_batched_kernel, cudaFuncAttributeMaxDynamicSharedMemorySize, CTX_SMEM_FLOATS * 4);
    smem_set = 1;
  }
  const int smem_bytes = 2 * STG_B;   // 60KB
  const int ctx_smem = CTX_SMEM_FLOATS * 4;

  // Round weights to fp16 (hi only — 2-pass scheme)
  {
    int n1 = 3 * DFF * DD;
    whalf_kernel<<<(n1 + 255) / 256, 256>>>(w1, pw1hi, n1);
    whalf_kernel<<<(n1 + 255) / 256, 256>>>(w2, pw2hi, n1);
    int n2 = DD * DD;
    whalf_kernel<<<(n2 + 255) / 256, 256>>>(out_w, powhi, n2);
  }

  // Embed: h = x @ emb_w^T + emb_b + PE   (M=32768, N=512, K=64)
  {
    int M = BB * L0;
    sgemm_embed<<<dim3(DD / 128, M / 128), 256>>>(x, emb_w, emb_b, ph, M, DD, 64, L0 - 1);
  }

  int L = L0;
  float* cur = ph;
  for (int i = 0; i < 3; i++) {
    int u = (i == 0) ? 45 : (i == 1) ? 40 : 35;
    int M = BB * L;
    unsigned k0, k1; layer_key(i, k0, k1);
    int total = L * u;
    idx_part<<<(total + 255) / 256, 256>>>(k0, k1, total, L - 1);
    prob_m_kernel<<<dim3(L / 8, 64), 256>>>(cur, L, u, 1.0f / (float)L);
    topk_kernel<<<64, 256>>>(L, u);
    qmean_kernel<<<64, 512>>>(cur, L);
    ctx_batched_kernel<<<64, 256, ctx_smem>>>(cur, L, u);
    assemble_ln1_kernel<<<M, 128>>>(cur, px, pxhi, pxlo,
                                    ln1_s + i * DD, ln1_b + i * DD, L, u);

    // FFN1: y = gelu(x @ w1^T + b1)  -> fp16 split planes
    mma_gemm<1><<<dim3(DFF / 128, M / 128), 256, smem_bytes>>>(
        pxhi, pxlo, pw1hi + (size_t)i * DFF * DD,
        b1 + i * DFF, nullptr, pyhi, pylo, M, DFF, DD);
    // FFN2: z = y @ w2^T + b2  (fp32 out)
    mma_gemm<0><<<dim3(DD / 128, M / 128), 256, smem_bytes>>>(
        pyhi, pylo, pw2hi + (size_t)i * DD * DFF,
        b2 + i * DD, pz, nullptr, nullptr, M, DD, DFF);

    if (i < 2) {
      int L2 = L / 2;
      // fused residual+LN2+distil, writes next-layer input directly
      ln2_distil_kernel<<<BB * L2, 128>>>(px, pz, cur,
                                          ln2_s + i * DD, ln2_b + i * DD, L2);
      L = L2;
    } else {
      // last layer: LN2 -> fp16 split planes only (final GEMM input)
      ln2_split_kernel<<<M, 128>>>(px, pz, pxhi, pxlo,
                                   ln2_s + i * DD, ln2_b + i * DD);
    }
  }

  // Final projection: out = h @ out_w^T + out_b  (M=8192, N=512, K=512)
  {
    int M = BB * L;   // L = 1024
    mma_gemm<0><<<dim3(DD / 128, M / 128), 256, smem_bytes>>>(
        pxhi, pxlo, powhi, out_b, out, nullptr, nullptr, M, DD, DD);
  }
}

// round 8
// speedup vs baseline: 2.8963x; 1.3162x over previous
#include <cuda_runtime.h>
#include <cuda_fp16.h>
#include <math.h>
#include <stdint.h>

#define BB 8
#define DD 512
#define DFF 2048
#define L0 4096
#define UMAX 45
#define LN_EPS 1e-5f

// ------------------- scratch (device globals; no allocs) -------------------
__device__ __align__(16) float g_h  [BB*L0*DD];
__device__ __align__(16) float g_x  [BB*L0*DD];
__device__ __align__(16) float g_z  [BB*L0*DD];
__device__ __align__(16) __half g_xhi[BB*L0*DD];
__device__ __align__(16) __half g_xlo[BB*L0*DD];
__device__ __align__(16) __half g_yhi[BB*L0*DFF];
__device__ __align__(16) __half g_w1hi[3*DFF*DD];
__device__ __align__(16) __half g_w2hi[3*DD*DFF];
__device__ __align__(16) __half g_owhi[DD*DD];
__device__ __align__(16) float g_M  [BB*8*L0];
__device__ __align__(16) int   g_idx[L0*UMAX];
__device__ __align__(16) int   g_top[BB*8*UMAX];
__device__ __align__(16) int   g_rowmap[BB*8*L0];
__device__ __align__(16) float g_ctx[BB*8*UMAX*64];
__device__ __align__(16) float g_qmean[BB*8*64];

// ------------------- fp16 split helpers -------------------------------------
__device__ __forceinline__ void split_fp16(float v, __half &hi, __half &lo)
{
  hi = __float2half_rn(v);
  lo = __float2half_rn(v - __half2float(hi));
}

// ------------------- threefry2x32 (JAX-compatible) -------------------------
#define TF_R(x0,x1,r) { x0 += x1; x1 = ((x1 << (r)) | (x1 >> (32-(r)))); x1 ^= x0; }
__host__ __device__ inline void threefry2x32(unsigned ks0, unsigned ks1,
                                             unsigned &x0, unsigned &x1)
{
  unsigned ks2 = ks0 ^ ks1 ^ 0x1BD11BDAu;
  x0 += ks0; x1 += ks1;
  TF_R(x0,x1,13) TF_R(x0,x1,15) TF_R(x0,x1,26) TF_R(x0,x1,6)
  x0 += ks1; x1 += ks2 + 1u;
  TF_R(x0,x1,17) TF_R(x0,x1,29) TF_R(x0,x1,16) TF_R(x0,x1,24)
  x0 += ks2; x1 += ks0 + 2u;
  TF_R(x0,x1,13) TF_R(x0,x1,15) TF_R(x0,x1,26) TF_R(x0,x1,6)
  x0 += ks0; x1 += ks1 + 3u;
  TF_R(x0,x1,17) TF_R(x0,x1,29) TF_R(x0,x1,16) TF_R(x0,x1,24)
  x0 += ks1; x1 += ks2 + 4u;
  TF_R(x0,x1,13) TF_R(x0,x1,15) TF_R(x0,x1,26) TF_R(x0,x1,6)
  x0 += ks2; x1 += ks0 + 5u;
}

__global__ void idx_part(unsigned k0, unsigned k1, int total, int mask)
{
  int t = blockIdx.x * 256 + threadIdx.x;
  if (t >= total) return;
  unsigned x0 = 0u, x1 = (unsigned)t;
  threefry2x32(k0, k1, x0, x1);
  g_idx[t] = (int)((x0 ^ x1) & (unsigned)mask);
}

// ------------------- weight -> fp16 hi only ----------------------------------
__global__ void whalf_kernel(const float* __restrict__ w,
                             __half* __restrict__ hi, int n)
{
  int i = blockIdx.x * 256 + threadIdx.x;
  if (i >= n) return;
  hi[i] = __float2half_rn(w[i]);
}

// ------------------- M = max_s qk - sum_s qk / L (coalesced) ----------------
// one warp per (b,h,l): lanes cooperate per sample; 256B coalesced row reads.
__global__ __launch_bounds__(256) void prob_m_kernel(
    const float* __restrict__ h, int L, int u, float invL)
{
  int bh = blockIdx.y; int b = bh >> 3, hh = bh & 7;
  int warp = threadIdx.x >> 5, lane = threadIdx.x & 31;
  int l = blockIdx.x * 8 + warp;
  const float* base = h + (size_t)b * L * DD + hh * 64;
  const float2 q2 = *(const float2*)(base + (size_t)l * DD + 2 * lane);

  int idxA = (lane < u)      ? g_idx[l * u + lane]      : 0;
  int idxB = (lane + 32 < u) ? g_idx[l * u + lane + 32] : 0;

  float mx = -INFINITY, sm = 0.f;
  for (int s = 0; s < u; s++) {
    int kl = __shfl_sync(0xffffffffu, (s < 32) ? idxA : idxB, s & 31);
    const float2 k2 = *(const float2*)(base + (size_t)kl * DD + 2 * lane);
    float p = q2.x * k2.x + q2.y * k2.y;
    #pragma unroll
    for (int o = 16; o; o >>= 1) p += __shfl_xor_sync(0xffffffffu, p, o);
    mx = fmaxf(mx, p); sm += p;
  }
  if (lane == 0) g_M[(size_t)bh * L + l] = mx - sm * invL;
}

// ------------------- top-k (iterative argmax, lower-index tiebreak) --------
__global__ __launch_bounds__(256) void topk_kernel(int L, int u)
{
  __shared__ float sM[L0];
  __shared__ float sval[256];
  __shared__ int   sidx[256];
  int bh = blockIdx.x;
  int tid = threadIdx.x;
  for (int l = tid; l < L; l += 256) {
    sM[l] = g_M[(size_t)bh * L + l];
    g_rowmap[(size_t)bh * L + l] = -1;
  }
  __syncthreads();
  for (int r = 0; r < u; r++) {
    float bv = -INFINITY; int bi = 0x7fffffff;
    for (int l = tid; l < L; l += 256) {
      float v = sM[l];
      if (v > bv || (v == bv && l < bi)) { bv = v; bi = l; }
    }
    sval[tid] = bv; sidx[tid] = bi;
    __syncthreads();
    for (int st = 128; st > 0; st >>= 1) {
      if (tid < st) {
        float v2 = sval[tid + st]; int i2 = sidx[tid + st];
        if (v2 > sval[tid] || (v2 == sval[tid] && i2 < sidx[tid])) {
          sval[tid] = v2; sidx[tid] = i2;
        }
      }
      __syncthreads();
    }
    if (tid == 0) {
      int sel = sidx[0];
      g_top[bh * u + r] = sel;
      g_rowmap[(size_t)bh * L + sel] = r;
      sM[sel] = -INFINITY;
    }
    __syncthreads();
  }
}

// ------------------- batched ctx + fused qmean ------------------------------
// smem floats: qs 3072 | kt 4352 | sc 3072 | ctxs 3072 | rm/rs/rsc 144 | qred 256
#define CTX_SMEM_FLOATS (13568 + 144 + 256)
__global__ __launch_bounds__(256) void ctx_batched_kernel(
    const float* __restrict__ h, int L, int u)
{
  extern __shared__ float dsm[];
  float* qs   = dsm;            // stride 64
  float* kt   = dsm + 3072;     // stride 68
  float* sc   = dsm + 7424;     // stride 64
  float* ctxs = dsm + 10496;    // stride 64
  float* rm   = dsm + 13568;
  float* rs   = dsm + 13616;
  float* rsc  = dsm + 13664;
  float* qred = dsm + 13712;    // [4][64]

  int bh = blockIdx.x; int b = bh >> 3, hh = bh & 7;
  const float* base = h + (size_t)b * L * DD + hh * 64;
  int tid = threadIdx.x;

  for (int e = tid; e < u * 64; e += 256) {
    int r = e >> 6, d = e & 63;
    qs[r * 64 + d] = base[(size_t)g_top[bh * u + r] * DD + d];
    ctxs[e] = 0.f;
  }
  if (tid < u) { rm[tid] = -INFINITY; rs[tid] = 0.f; }
  __syncthreads();

  const int j  = tid & 63;
  const int rg = tid >> 6;
  const int w  = tid >> 5, lane = tid & 31;
  float qacc = 0.f;   // fused qmean partial: sum over keys of column j

  for (int t0 = 0; t0 < L; t0 += 64) {
    for (int e = tid; e < 64 * 16; e += 256) {
      int r = e >> 4, c4 = e & 15;
      float4 v = *(const float4*)(base + (size_t)(t0 + r) * DD + c4 * 4);
      float* kr = kt + r * 68 + c4 * 4;
      kr[0] = v.x; kr[1] = v.y; kr[2] = v.z; kr[3] = v.w;
    }
    __syncthreads();

    // fused qmean accumulation: thread (j, rg) sums rows rg,rg+4,.. of col j
    #pragma unroll
    for (int r = 0; r < 16; r++) qacc += kt[(rg + r * 4) * 68 + j];

    {
      float kreg[64];
      #pragma unroll
      for (int d = 0; d < 64; d++) kreg[d] = kt[j * 68 + d];
      for (int r = rg; r < u; r += 4) {
        const float* qr = qs + r * 64;
        float dot = 0.f;
        #pragma unroll
        for (int d = 0; d < 64; d++) dot += qr[d] * kreg[d];
        sc[r * 64 + j] = dot * 0.125f;
      }
    }
    __syncthreads();
    for (int r = w; r < u; r += 8) {
      float v0 = sc[r * 64 + lane], v1 = sc[r * 64 + lane + 32];
      float mx = fmaxf(v0, v1);
      #pragma unroll
      for (int o = 16; o; o >>= 1) mx = fmaxf(mx, __shfl_xor_sync(0xffffffffu, mx, o));
      float mold = rm[r];
      float mnew = fmaxf(mold, mx);
      float p0 = __expf(v0 - mnew), p1 = __expf(v1 - mnew);
      float ps = p0 + p1;
      #pragma unroll
      for (int o = 16; o; o >>= 1) ps += __shfl_xor_sync(0xffffffffu, ps, o);
      if (lane == 0) {
        float cold = __expf(mold - mnew);
        rsc[r] = cold;
        rs[r] = rs[r] * cold + ps;
        rm[r] = mnew;
      }
      sc[r * 64 + lane] = p0; sc[r * 64 + lane + 32] = p1;
    }
    __syncthreads();
    for (int r = rg; r < u; r += 4) {
      const float* pr = sc + r * 64;
      float a = 0.f;
      #pragma unroll
      for (int jj = 0; jj < 64; jj++) a += pr[jj] * kt[jj * 68 + j];
      ctxs[r * 64 + j] = ctxs[r * 64 + j] * rsc[r] + a;
    }
    __syncthreads();
  }

  // finalize qmean
  qred[rg * 64 + j] = qacc;
  __syncthreads();
  if (rg == 0)
    g_qmean[bh * 64 + j] =
      (qred[j] + qred[64 + j] + qred[128 + j] + qred[192 + j]) / (float)L;

  for (int e = tid; e < u * 64; e += 256) {
    int r = e >> 6, d = e & 63;
    g_ctx[((size_t)(bh * u + r)) * 64 + d] = ctxs[r * 64 + d] / rs[r];
  }
}

// ------------------- block reduce helper (128 threads) ---------------------
__device__ __forceinline__ float blocksum128(float v, float* sred)
{
  #pragma unroll
  for (int o = 16; o; o >>= 1) v += __shfl_xor_sync(0xffffffffu, v, o);
  if ((threadIdx.x & 31) == 0) sred[threadIdx.x >> 5] = v;
  __syncthreads();
  float t = sred[0] + sred[1] + sred[2] + sred[3];
  __syncthreads();
  return t;
}

// ------------------- assemble attention out + residual + LN1 + fp16 split --
__global__ __launch_bounds__(128) void assemble_ln1_kernel(
    const float* __restrict__ hin, float* __restrict__ xout,
    __half* __restrict__ xhi, __half* __restrict__ xlo,
    const float* __restrict__ gamma, const float* __restrict__ beta,
    int L, int u)
{
  __shared__ float sred[4];
  int row = blockIdx.x;
  int b = row / L, l = row - b * L;
  int tid = threadIdx.x;
  float v[4];
  #pragma unroll
  for (int i = 0; i < 4; i++) {
    int e = i * 128 + tid;
    int hh = e >> 6, dd = e & 63;
    int bh = b * 8 + hh;
    int r = g_rowmap[(size_t)bh * L + l];
    float nv = (r >= 0) ? g_ctx[((size_t)(bh * u + r)) * 64 + dd]
                        : g_qmean[bh * 64 + dd];
    v[i] = hin[(size_t)row * DD + e] + nv;
  }
  float s = blocksum128(v[0] + v[1] + v[2] + v[3], sred);
  float mu = s * (1.0f / 512.0f);
  float vs = 0.f;
  #pragma unroll
  for (int i = 0; i < 4; i++) { float d = v[i] - mu; vs += d * d; }
  vs = blocksum128(vs, sred);
  float rstd = rsqrtf(vs * (1.0f / 512.0f) + LN_EPS);
  #pragma unroll
  for (int i = 0; i < 4; i++) {
    int e = i * 128 + tid;
    float o = (v[i] - mu) * rstd * gamma[e] + beta[e];
    xout[(size_t)row * DD + e] = o;
    __half h16, l16;
    split_fp16(o, h16, l16);
    xhi[(size_t)row * DD + e] = h16;
    xlo[(size_t)row * DD + e] = l16;
  }
}

// ------------------- fused residual+LN2+distil (layers 0,1) ----------------
__global__ __launch_bounds__(128) void ln2_distil_kernel(
    const float* __restrict__ xin, const float* __restrict__ zin,
    float* __restrict__ outp,
    const float* __restrict__ gamma, const float* __restrict__ beta, int L2)
{
  __shared__ float sred[4];
  int rowo = blockIdx.x;
  int b = rowo / L2, l2 = rowo - b * L2;
  size_t r0 = ((size_t)b * (2 * L2) + 2 * l2);
  int tid = threadIdx.x;
  float o01[4];
  #pragma unroll
  for (int half = 0; half < 2; half++) {
    size_t row = r0 + half;
    float v[4];
    #pragma unroll
    for (int i = 0; i < 4; i++) {
      int e = i * 128 + tid;
      v[i] = xin[row * DD + e] + zin[row * DD + e];
    }
    float s = blocksum128(v[0] + v[1] + v[2] + v[3], sred);
    float mu = s * (1.0f / 512.0f);
    float vs = 0.f;
    #pragma unroll
    for (int i = 0; i < 4; i++) { float d = v[i] - mu; vs += d * d; }
    vs = blocksum128(vs, sred);
    float rstd = rsqrtf(vs * (1.0f / 512.0f) + LN_EPS);
    #pragma unroll
    for (int i = 0; i < 4; i++) {
      int e = i * 128 + tid;
      float o = (v[i] - mu) * rstd * gamma[e] + beta[e];
      if (half == 0) o01[i] = o; else o01[i] = 0.5f * (o01[i] + o);
    }
  }
  #pragma unroll
  for (int i = 0; i < 4; i++) {
    int e = i * 128 + tid;
    outp[(size_t)rowo * DD + e] = o01[i];
  }
}

// ------------------- residual + LN2 -> fp16 split only (last layer) --------
__global__ __launch_bounds__(128) void ln2_split_kernel(
    const float* __restrict__ xin, const float* __restrict__ zin,
    __half* __restrict__ ohi, __half* __restrict__ olo,
    const float* __restrict__ gamma, const float* __restrict__ beta)
{
  __shared__ float sred[4];
  size_t row = blockIdx.x;
  int tid = threadIdx.x;
  float v[4];
  #pragma unroll
  for (int i = 0; i < 4; i++) {
    int e = i * 128 + tid;
    v[i] = xin[row * DD + e] + zin[row * DD + e];
  }
  float s = blocksum128(v[0] + v[1] + v[2] + v[3], sred);
  float mu = s * (1.0f / 512.0f);
  float vs = 0.f;
  #pragma unroll
  for (int i = 0; i < 4; i++) { float d = v[i] - mu; vs += d * d; }
  vs = blocksum128(vs, sred);
  float rstd = rsqrtf(vs * (1.0f / 512.0f) + LN_EPS);
  #pragma unroll
  for (int i = 0; i < 4; i++) {
    int e = i * 128 + tid;
    float o = (v[i] - mu) * rstd * gamma[e] + beta[e];
    __half h16, l16;
    split_fp16(o, h16, l16);
    ohi[row * DD + e] = h16;
    olo[row * DD + e] = l16;
  }
}

// ------------------- SIMT SGEMM (embed only): C = A*B^T + bias + PE --------
__global__ __launch_bounds__(256, 2) void sgemm_embed(
    const float* __restrict__ A, const float* __restrict__ Bm,
    const float* __restrict__ bias, float* __restrict__ C,
    int M, int N, int K, int Lmask)
{
  __shared__ float As[16][132];
  __shared__ float Bs[16][132];
  const int bm = blockIdx.y * 128, bn = blockIdx.x * 128;
  const int t = threadIdx.x;
  const int lr = t >> 2;
  const int lc = (t & 3) << 2;
  const int tx = t & 15, ty = t >> 4;
  float acc[8][8];
  #pragma unroll
  for (int i = 0; i < 8; i++)
    #pragma unroll
    for (int j = 0; j < 8; j++) acc[i][j] = 0.f;

  const float* Ap = A + (size_t)(bm + lr) * K + lc;
  const float* Bp = Bm + (size_t)(bn + lr) * K + lc;

  for (int k0 = 0; k0 < K; k0 += 16) {
    float4 a0 = *(const float4*)(Ap + k0);
    float4 a1 = *(const float4*)(Ap + (size_t)64 * K + k0);
    float4 b0 = *(const float4*)(Bp + k0);
    float4 b1 = *(const float4*)(Bp + (size_t)64 * K + k0);
    __syncthreads();
    As[lc+0][lr] = a0.x; As[lc+1][lr] = a0.y; As[lc+2][lr] = a0.z; As[lc+3][lr] = a0.w;
    As[lc+0][lr+64] = a1.x; As[lc+1][lr+64] = a1.y; As[lc+2][lr+64] = a1.z; As[lc+3][lr+64] = a1.w;
    Bs[lc+0][lr] = b0.x; Bs[lc+1][lr] = b0.y; Bs[lc+2][lr] = b0.z; Bs[lc+3][lr] = b0.w;
    Bs[lc+0][lr+64] = b1.x; Bs[lc+1][lr+64] = b1.y; Bs[lc+2][lr+64] = b1.z; Bs[lc+3][lr+64] = b1.w;
    __syncthreads();
    #pragma unroll
    for (int kk = 0; kk < 16; kk++) {
      float4 av0 = *(const float4*)&As[kk][ty * 8];
      float4 av1 = *(const float4*)&As[kk][ty * 8 + 4];
      float4 bv0 = *(const float4*)&Bs[kk][tx * 8];
      float4 bv1 = *(const float4*)&Bs[kk][tx * 8 + 4];
      float a[8] = {av0.x, av0.y, av0.z, av0.w, av1.x, av1.y, av1.z, av1.w};
      float bb[8] = {bv0.x, bv0.y, bv0.z, bv0.w, bv1.x, bv1.y, bv1.z, bv1.w};
      #pragma unroll
      for (int i = 0; i < 8; i++)
        #pragma unroll
        for (int j = 0; j < 8; j++) acc[i][j] += a[i] * bb[j];
    }
  }

  #pragma unroll
  for (int i = 0; i < 8; i++) {
    int row = bm + ty * 8 + i;
    #pragma unroll
    for (int j = 0; j < 8; j++) {
      int col = bn + tx * 8 + j;
      float v = acc[i][j] + bias[col];
      int l = row & Lmask;
      float df = expf((float)(col & ~1) * (-0.017988946039015984f));
      float arg = (float)l * df;
      v += (col & 1) ? cosf(arg) : sinf(arg);
      C[(size_t)row * N + col] = v;
    }
  }
}

// ------------------- fp16 tensor-core GEMM (1- or 2-pass on A) -------------
#define KC 32                     // k elems per stage
#define LDPB 80                   // padded row stride in BYTES (40 fp16)
#define PLANE_B (128*LDPB)        // 10240 bytes per plane

__device__ __forceinline__ void mma_fp16(float* c, const unsigned* a, const unsigned* b)
{
  asm volatile(
    "mma.sync.aligned.m16n8k16.row.col.f32.f16.f16.f32 "
    "{%0,%1,%2,%3},{%4,%5,%6,%7},{%8,%9},{%0,%1,%2,%3};\n"
    : "+f"(c[0]), "+f"(c[1]), "+f"(c[2]), "+f"(c[3])
    : "r"(a[0]), "r"(a[1]), "r"(a[2]), "r"(a[3]), "r"(b[0]), "r"(b[1]));
}

__device__ __forceinline__ void ldsm4(unsigned* r, const char* sptr)
{
  unsigned addr = (unsigned)__cvta_generic_to_shared(sptr);
  asm volatile("ldmatrix.sync.aligned.m8n8.x4.shared.b16 {%0,%1,%2,%3}, [%4];\n"
    : "=r"(r[0]), "=r"(r[1]), "=r"(r[2]), "=r"(r[3]) : "r"(addr));
}

// EPI 0: Cf = acc + bias (fp32) | EPI 1: Chi = fp16(gelu(acc + bias))
// NPASS 2: A = Ahi + Alo (compensated) | NPASS 1: A = Ahi only
template<int EPI, int NPASS>
__global__ __launch_bounds__(256, 2) void mma_gemm(
    const __half* __restrict__ Ahi, const __half* __restrict__ Alo,
    const __half* __restrict__ Bhi,
    const float* __restrict__ bias,
    float* __restrict__ Cf, __half* __restrict__ Chi,
    int M, int N, int K)
{
  const int STGB = (NPASS + 1) * PLANE_B;
  extern __shared__ char smc[];
  const int tid = threadIdx.x;
  const int bm = blockIdx.y * 128, bn = blockIdx.x * 128;
  const int lane = tid & 31;
  const int g = lane >> 2, t4 = lane & 3;
  const int warp = tid >> 5;
  const int wm = warp >> 2, wn = warp & 3;      // warps 2(m) x 4(n)
  const int moff = wm * 64, noff = wn * 32;

  const int aoff = (lane & 15) * LDPB + ((lane & 16) ? 16 : 0);
  const int boff = ((lane & 7) + ((lane & 16) ? 8 : 0)) * LDPB + ((lane & 8) ? 16 : 0);

  float acc[4][4][4];
  #pragma unroll
  for (int i = 0; i < 4; i++)
    #pragma unroll
    for (int j = 0; j < 4; j++)
      #pragma unroll
      for (int q = 0; q < 4; q++) acc[i][j][q] = 0.f;

  const int KT = K / KC;

  #define PREFETCH(kt, s) do {                                                   \
    int k0_ = (kt) * KC;                                                         \
    const char* srcs_[3];                                                        \
    srcs_[0] = (const char*)(Ahi + (size_t)bm * K + k0_);                        \
    if (NPASS == 2) {                                                            \
      srcs_[1] = (const char*)(Alo + (size_t)bm * K + k0_);                      \
      srcs_[2] = (const char*)(Bhi + (size_t)bn * K + k0_);                      \
    } else {                                                                     \
      srcs_[1] = (const char*)(Bhi + (size_t)bn * K + k0_);                      \
    }                                                                            \
    _Pragma("unroll")                                                            \
    for (int p_ = 0; p_ < NPASS + 1; p_++) {                                     \
      char* dstp_ = smc + (s) * STGB + p_ * PLANE_B;                             \
      _Pragma("unroll")                                                          \
      for (int j_ = 0; j_ < 2; j_++) {                                           \
        int idx_ = j_ * 256 + tid;                                               \
        int row_ = idx_ >> 2, ch_ = idx_ & 3;                                    \
        unsigned sa_ = (unsigned)__cvta_generic_to_shared(dstp_ + row_ * LDPB + ch_ * 16); \
        const char* ga_ = srcs_[p_] + (size_t)row_ * K * 2 + ch_ * 16;           \
        asm volatile("cp.async.ca.shared.global [%0], [%1], 16;\n"               \
                     :: "r"(sa_), "l"(ga_));                                     \
      }                                                                          \
    }                                                                            \
    asm volatile("cp.async.commit_group;\n");                                    \
  } while (0)

  PREFETCH(0, 0);

  for (int kt = 0; kt < KT; kt++) {
    asm volatile("cp.async.wait_group 0;\n");
    __syncthreads();
    if (kt + 1 < KT) PREFETCH(kt + 1, (kt + 1) & 1);

    const char* Sahi = smc + (kt & 1) * STGB;
    const char* Salo = Sahi + PLANE_B;                 // valid only NPASS==2
    const char* Sbhi = Sahi + NPASS * PLANE_B;

    #pragma unroll
    for (int ks = 0; ks < 2; ks++) {
      int kb = ks * 32;   // 16 fp16 = 32 bytes
      unsigned bh_[2][4];
      #pragma unroll
      for (int pp = 0; pp < 2; pp++)
        ldsm4(bh_[pp], Sbhi + (noff + pp * 16) * LDPB + kb + boff);
      #pragma unroll
      for (int tm = 0; tm < 4; tm++) {
        unsigned ah[4], al[4];
        ldsm4(ah, Sahi + (moff + tm * 16) * LDPB + kb + aoff);
        if (NPASS == 2)
          ldsm4(al, Salo + (moff + tm * 16) * LDPB + kb + aoff);
        #pragma unroll
        for (int tn = 0; tn < 4; tn++) {
          const unsigned* bhp = &bh_[tn >> 1][(tn & 1) * 2];
          mma_fp16(acc[tm][tn], ah, bhp);
          if (NPASS == 2) mma_fp16(acc[tm][tn], al, bhp);
        }
      }
    }
    __syncthreads();
  }

  // ---- epilogue ----
  #pragma unroll
  for (int tm = 0; tm < 4; tm++) {
    int r0 = bm + moff + tm * 16 + g;
    int r1 = r0 + 8;
    #pragma unroll
    for (int tn = 0; tn < 4; tn++) {
      int c0 = bn + noff + tn * 8 + 2 * t4;
      float b0 = bias[c0], b1 = bias[c0 + 1];
      float v00 = acc[tm][tn][0] + b0;
      float v01 = acc[tm][tn][1] + b1;
      float v10 = acc[tm][tn][2] + b0;
      float v11 = acc[tm][tn][3] + b1;
      if (EPI == 1) {
        v00 = 0.5f * v00 * (1.f + erff(v00 * 0.70710678118654752f));
        v01 = 0.5f * v01 * (1.f + erff(v01 * 0.70710678118654752f));
        v10 = 0.5f * v10 * (1.f + erff(v10 * 0.70710678118654752f));
        v11 = 0.5f * v11 * (1.f + erff(v11 * 0.70710678118654752f));
        *(__half2*)(Chi + (size_t)r0 * N + c0) =
          __halves2half2(__float2half_rn(v00), __float2half_rn(v01));
        *(__half2*)(Chi + (size_t)r1 * N + c0) =
          __halves2half2(__float2half_rn(v10), __float2half_rn(v11));
      } else {
        *(float2*)(Cf + (size_t)r0 * N + c0) = make_float2(v00, v01);
        *(float2*)(Cf + (size_t)r1 * N + c0) = make_float2(v10, v11);
      }
    }
  }
  #undef PREFETCH
}

// ------------------- host: layer key derivation ----------------------------
static void layer_key(int i, unsigned &k0, unsigned &k1)
{
  unsigned a = 0u, b = (unsigned)i;
  threefry2x32(0u, 42u, a, b);
  unsigned c = 0u, d = 1u;
  threefry2x32(a, b, c, d);
  k0 = c; k1 = d;
}

extern "C" void kernel_launch(void* const* d_in, const int* in_sizes, int n_in,
                              void* d_out, int out_size)
{
  const float* x     = (const float*)d_in[0];
  const float* emb_w = (const float*)d_in[1];
  const float* emb_b = (const float*)d_in[2];
  const float* ln1_s = (const float*)d_in[3];
  const float* ln1_b = (const float*)d_in[4];
  const float* w1    = (const float*)d_in[5];
  const float* b1    = (const float*)d_in[6];
  const float* w2    = (const float*)d_in[7];
  const float* b2    = (const float*)d_in[8];
  const float* ln2_s = (const float*)d_in[9];
  const float* ln2_b = (const float*)d_in[10];
  const float* out_w = (const float*)d_in[11];
  const float* out_b = (const float*)d_in[12];
  float* out = (float*)d_out;

  float *ph, *px, *pz;
  __half *pxhi, *pxlo, *pyhi;
  __half *pw1hi, *pw2hi, *powhi;
  cudaGetSymbolAddress((void**)&ph,   g_h);
  cudaGetSymbolAddress((void**)&px,   g_x);
  cudaGetSymbolAddress((void**)&pz,   g_z);
  cudaGetSymbolAddress((void**)&pxhi, g_xhi);
  cudaGetSymbolAddress((void**)&pxlo, g_xlo);
  cudaGetSymbolAddress((void**)&pyhi, g_yhi);
  cudaGetSymbolAddress((void**)&pw1hi, g_w1hi);
  cudaGetSymbolAddress((void**)&pw2hi, g_w2hi);
  cudaGetSymbolAddress((void**)&powhi, g_owhi);

  static int smem_set = 0;
  if (!smem_set) {
    cudaFuncSetAttribute(mma_gemm<1,2>, cudaFuncAttributeMaxDynamicSharedMemorySize, 2 * 3 * PLANE_B);
    cudaFuncSetAttribute(mma_gemm<0,1>, cudaFuncAttributeMaxDynamicSharedMemorySize, 2 * 2 * PLANE_B);
    cudaFuncSetAttribute(mma_gemm<0,2>, cudaFuncAttributeMaxDynamicSharedMemorySize, 2 * 3 * PLANE_B);
    cudaFuncSetAttribute(ctx_batched_kernel, cudaFuncAttributeMaxDynamicSharedMemorySize, CTX_SMEM_FLOATS * 4);
    smem_set = 1;
  }
  const int ctx_smem = CTX_SMEM_FLOATS * 4;

  // Round weights to fp16 (hi only)
  {
    int n1 = 3 * DFF * DD;
    whalf_kernel<<<(n1 + 255) / 256, 256>>>(w1, pw1hi, n1);
    whalf_kernel<<<(n1 + 255) / 256, 256>>>(w2, pw2hi, n1);
    int n2 = DD * DD;
    whalf_kernel<<<(n2 + 255) / 256, 256>>>(out_w, powhi, n2);
  }

  // Embed: h = x @ emb_w^T + emb_b + PE   (M=32768, N=512, K=64)
  {
    int M = BB * L0;
    sgemm_embed<<<dim3(DD / 128, M / 128), 256>>>(x, emb_w, emb_b, ph, M, DD, 64, L0 - 1);
  }

  int L = L0;
  float* cur = ph;
  for (int i = 0; i < 3; i++) {
    int u = (i == 0) ? 45 : (i == 1) ? 40 : 35;
    int M = BB * L;
    unsigned k0, k1; layer_key(i, k0, k1);
    int total = L * u;
    idx_part<<<(total + 255) / 256, 256>>>(k0, k1, total, L - 1);
    prob_m_kernel<<<dim3(L / 8, 64), 256>>>(cur, L, u, 1.0f / (float)L);
    topk_kernel<<<64, 256>>>(L, u);
    ctx_batched_kernel<<<64, 256, ctx_smem>>>(cur, L, u);   // also writes qmean
    assemble_ln1_kernel<<<M, 128>>>(cur, px, pxhi, pxlo,
                                    ln1_s + i * DD, ln1_b + i * DD, L, u);

    // FFN1: y = gelu(x @ w1^T + b1), 2-pass A, fp16 out
    mma_gemm<1,2><<<dim3(DFF / 128, M / 128), 256, 2 * 3 * PLANE_B>>>(
        pxhi, pxlo, pw1hi + (size_t)i * DFF * DD,
        b1 + i * DFF, nullptr, pyhi, M, DFF, DD);
    // FFN2: z = y @ w2^T + b2, 1-pass A, fp32 out
    mma_gemm<0,1><<<dim3(DD / 128, M / 128), 256, 2 * 2 * PLANE_B>>>(
        pyhi, nullptr, pw2hi + (size_t)i * DD * DFF,
        b2 + i * DD, pz, nullptr, M, DD, DFF);

    if (i < 2) {
      int L2 = L / 2;
      ln2_distil_kernel<<<BB * L2, 128>>>(px, pz, cur,
                                          ln2_s + i * DD, ln2_b + i * DD, L2);
      L = L2;
    } else {
      ln2_split_kernel<<<M, 128>>>(px, pz, pxhi, pxlo,
                                   ln2_s + i * DD, ln2_b + i * DD);
    }
  }

  // Final projection: out = h @ out_w^T + out_b, 2-pass A (M=8192, N=512, K=512)
  {
    int M = BB * L;   // L = 1024
    mma_gemm<0,2><<<dim3(DD / 128, M / 128), 256, 2 * 3 * PLANE_B>>>(
        pxhi, pxlo, powhi, out_b, out, nullptr, M, DD, DD);
  }
}

// round 9
// speedup vs baseline: 3.7834x; 1.3063x over previous
#include <cuda_runtime.h>
#include <cuda_fp16.h>
#include <math.h>
#include <stdint.h>

#define BB 8
#define DD 512
#define DFF 2048
#define L0 4096
#define UMAX 45
#define LN_EPS 1e-5f

// ------------------- scratch (device globals; no allocs) -------------------
__device__ __align__(16) float g_h  [BB*L0*DD];
__device__ __align__(16) float g_x  [BB*L0*DD];
__device__ __align__(16) float g_z  [BB*L0*DD];
__device__ __align__(16) __half g_xhi[BB*L0*DD];
__device__ __align__(16) __half g_xlo[BB*L0*DD];
__device__ __align__(16) __half g_yhi[BB*L0*DFF];
__device__ __align__(16) __half g_w1hi[3*DFF*DD];
__device__ __align__(16) __half g_w2hi[3*DD*DFF];
__device__ __align__(16) __half g_owhi[DD*DD];
__device__ __align__(16) __half g_exhi[BB*L0*64];
__device__ __align__(16) __half g_exlo[BB*L0*64];
__device__ __align__(16) __half g_ewhi[DD*64];
__device__ __align__(16) __half g_ewlo[DD*64];
__device__ __align__(16) float g_M  [BB*8*L0];
__device__ __align__(16) int   g_idx[L0*UMAX];
__device__ __align__(16) int   g_top[BB*8*UMAX];
__device__ __align__(16) int   g_rowmap[BB*8*L0];
__device__ __align__(16) float g_ctx[BB*8*UMAX*64];
__device__ __align__(16) float g_qmean[BB*8*64];
// split-L ctx partials (max 4 splits)
__device__ __align__(16) float g_pm  [64*4*UMAX];
__device__ __align__(16) float g_ps  [64*4*UMAX];
__device__ __align__(16) float g_pctx[64*4*UMAX*64];
__device__ __align__(16) float g_pq  [64*4*64];

// ------------------- fp16 split helpers -------------------------------------
__device__ __forceinline__ void split_fp16(float v, __half &hi, __half &lo)
{
  hi = __float2half_rn(v);
  lo = __float2half_rn(v - __half2float(hi));
}

// ------------------- threefry2x32 (JAX-compatible) -------------------------
#define TF_R(x0,x1,r) { x0 += x1; x1 = ((x1 << (r)) | (x1 >> (32-(r)))); x1 ^= x0; }
__host__ __device__ inline void threefry2x32(unsigned ks0, unsigned ks1,
                                             unsigned &x0, unsigned &x1)
{
  unsigned ks2 = ks0 ^ ks1 ^ 0x1BD11BDAu;
  x0 += ks0; x1 += ks1;
  TF_R(x0,x1,13) TF_R(x0,x1,15) TF_R(x0,x1,26) TF_R(x0,x1,6)
  x0 += ks1; x1 += ks2 + 1u;
  TF_R(x0,x1,17) TF_R(x0,x1,29) TF_R(x0,x1,16) TF_R(x0,x1,24)
  x0 += ks2; x1 += ks0 + 2u;
  TF_R(x0,x1,13) TF_R(x0,x1,15) TF_R(x0,x1,26) TF_R(x0,x1,6)
  x0 += ks0; x1 += ks1 + 3u;
  TF_R(x0,x1,17) TF_R(x0,x1,29) TF_R(x0,x1,16) TF_R(x0,x1,24)
  x0 += ks1; x1 += ks2 + 4u;
  TF_R(x0,x1,13) TF_R(x0,x1,15) TF_R(x0,x1,26) TF_R(x0,x1,6)
  x0 += ks2; x1 += ks0 + 5u;
}

__global__ void idx_part(unsigned k0, unsigned k1, int total, int mask)
{
  int t = blockIdx.x * 256 + threadIdx.x;
  if (t >= total) return;
  unsigned x0 = 0u, x1 = (unsigned)t;
  threefry2x32(k0, k1, x0, x1);
  g_idx[t] = (int)((x0 ^ x1) & (unsigned)mask);
}

// ------------------- splits -------------------------------------------------
__global__ void whalf_kernel(const float* __restrict__ w,
                             __half* __restrict__ hi, int n)
{
  int i = blockIdx.x * 256 + threadIdx.x;
  if (i >= n) return;
  hi[i] = __float2half_rn(w[i]);
}

__global__ void xsplit_kernel(const float* __restrict__ w,
                              __half* __restrict__ hi, __half* __restrict__ lo, int n)
{
  int i = blockIdx.x * 256 + threadIdx.x;
  if (i >= n) return;
  __half h, l;
  split_fp16(w[i], h, l);
  hi[i] = h; lo[i] = l;
}

// ------------------- M = max_s qk - sum_s qk / L (coalesced) ----------------
__global__ __launch_bounds__(256) void prob_m_kernel(
    const float* __restrict__ h, int L, int u, float invL)
{
  int bh = blockIdx.y; int b = bh >> 3, hh = bh & 7;
  int warp = threadIdx.x >> 5, lane = threadIdx.x & 31;
  int l = blockIdx.x * 8 + warp;
  const float* base = h + (size_t)b * L * DD + hh * 64;
  const float2 q2 = *(const float2*)(base + (size_t)l * DD + 2 * lane);

  int idxA = (lane < u)      ? g_idx[l * u + lane]      : 0;
  int idxB = (lane + 32 < u) ? g_idx[l * u + lane + 32] : 0;

  float mx = -INFINITY, sm = 0.f;
  for (int s = 0; s < u; s++) {
    int kl = __shfl_sync(0xffffffffu, (s < 32) ? idxA : idxB, s & 31);
    const float2 k2 = *(const float2*)(base + (size_t)kl * DD + 2 * lane);
    float p = q2.x * k2.x + q2.y * k2.y;
    #pragma unroll
    for (int o = 16; o; o >>= 1) p += __shfl_xor_sync(0xffffffffu, p, o);
    mx = fmaxf(mx, p); sm += p;
  }
  if (lane == 0) g_M[(size_t)bh * L + l] = mx - sm * invL;
}

// ------------------- top-k (iterative argmax, lower-index tiebreak) --------
__global__ __launch_bounds__(256) void topk_kernel(int L, int u)
{
  __shared__ float sM[L0];
  __shared__ float sval[256];
  __shared__ int   sidx[256];
  int bh = blockIdx.x;
  int tid = threadIdx.x;
  for (int l = tid; l < L; l += 256) {
    sM[l] = g_M[(size_t)bh * L + l];
    g_rowmap[(size_t)bh * L + l] = -1;
  }
  __syncthreads();
  for (int r = 0; r < u; r++) {
    float bv = -INFINITY; int bi = 0x7fffffff;
    for (int l = tid; l < L; l += 256) {
      float v = sM[l];
      if (v > bv || (v == bv && l < bi)) { bv = v; bi = l; }
    }
    sval[tid] = bv; sidx[tid] = bi;
    __syncthreads();
    for (int st = 128; st > 0; st >>= 1) {
      if (tid < st) {
        float v2 = sval[tid + st]; int i2 = sidx[tid + st];
        if (v2 > sval[tid] || (v2 == sval[tid] && i2 < sidx[tid])) {
          sval[tid] = v2; sidx[tid] = i2;
        }
      }
      __syncthreads();
    }
    if (tid == 0) {
      int sel = sidx[0];
      g_top[bh * u + r] = sel;
      g_rowmap[(size_t)bh * L + sel] = r;
      sM[sel] = -INFINITY;
    }
    __syncthreads();
  }
}

// ------------------- split-L ctx: partial online softmax over key range ----
// smem floats: qs 3072 | kt 4352 | sc 3072 | ctxs 3072 | rm/rs/rsc 144 | qred 256
#define CTX_SMEM_FLOATS (13568 + 144 + 256)
__global__ __launch_bounds__(256) void ctx_split_kernel(
    const float* __restrict__ h, int L, int u, int klen)
{
  extern __shared__ float dsm[];
  float* qs   = dsm;            // stride 64
  float* kt   = dsm + 3072;     // stride 68
  float* sc   = dsm + 7424;     // stride 64
  float* ctxs = dsm + 10496;    // stride 64
  float* rm   = dsm + 13568;
  float* rs   = dsm + 13616;
  float* rsc  = dsm + 13664;
  float* qred = dsm + 13712;    // [4][64]

  int split = blockIdx.x;
  int bh = blockIdx.y; int b = bh >> 3, hh = bh & 7;
  const float* base = h + (size_t)b * L * DD + hh * 64;
  int tid = threadIdx.x;
  int kbeg = split * klen;

  for (int e = tid; e < u * 64; e += 256) {
    int r = e >> 6, d = e & 63;
    qs[r * 64 + d] = base[(size_t)g_top[bh * u + r] * DD + d];
    ctxs[e] = 0.f;
  }
  if (tid < u) { rm[tid] = -INFINITY; rs[tid] = 0.f; }
  __syncthreads();

  const int j  = tid & 63;
  const int rg = tid >> 6;
  const int w  = tid >> 5, lane = tid & 31;
  float qacc = 0.f;

  for (int t0 = kbeg; t0 < kbeg + klen; t0 += 64) {
    for (int e = tid; e < 64 * 16; e += 256) {
      int r = e >> 4, c4 = e & 15;
      float4 v = *(const float4*)(base + (size_t)(t0 + r) * DD + c4 * 4);
      float* kr = kt + r * 68 + c4 * 4;
      kr[0] = v.x; kr[1] = v.y; kr[2] = v.z; kr[3] = v.w;
    }
    __syncthreads();

    #pragma unroll
    for (int r = 0; r < 16; r++) qacc += kt[(rg + r * 4) * 68 + j];

    {
      float kreg[64];
      #pragma unroll
      for (int d = 0; d < 64; d++) kreg[d] = kt[j * 68 + d];
      for (int r = rg; r < u; r += 4) {
        const float* qr = qs + r * 64;
        float dot = 0.f;
        #pragma unroll
        for (int d = 0; d < 64; d++) dot += qr[d] * kreg[d];
        sc[r * 64 + j] = dot * 0.125f;
      }
    }
    __syncthreads();
    for (int r = w; r < u; r += 8) {
      float v0 = sc[r * 64 + lane], v1 = sc[r * 64 + lane + 32];
      float mx = fmaxf(v0, v1);
      #pragma unroll
      for (int o = 16; o; o >>= 1) mx = fmaxf(mx, __shfl_xor_sync(0xffffffffu, mx, o));
      float mold = rm[r];
      float mnew = fmaxf(mold, mx);
      float p0 = __expf(v0 - mnew), p1 = __expf(v1 - mnew);
      float ps = p0 + p1;
      #pragma unroll
      for (int o = 16; o; o >>= 1) ps += __shfl_xor_sync(0xffffffffu, ps, o);
      if (lane == 0) {
        float cold = __expf(mold - mnew);
        rsc[r] = cold;
        rs[r] = rs[r] * cold + ps;
        rm[r] = mnew;
      }
      sc[r * 64 + lane] = p0; sc[r * 64 + lane + 32] = p1;
    }
    __syncthreads();
    for (int r = rg; r < u; r += 4) {
      const float* pr = sc + r * 64;
      float a = 0.f;
      #pragma unroll
      for (int jj = 0; jj < 64; jj++) a += pr[jj] * kt[jj * 68 + j];
      ctxs[r * 64 + j] = ctxs[r * 64 + j] * rsc[r] + a;
    }
    __syncthreads();
  }

  // write partials
  qred[rg * 64 + j] = qacc;
  __syncthreads();
  if (rg == 0)
    g_pq[(bh * 4 + split) * 64 + j] =
      qred[j] + qred[64 + j] + qred[128 + j] + qred[192 + j];
  if (tid < u) {
    g_pm[(bh * 4 + split) * UMAX + tid] = rm[tid];
    g_ps[(bh * 4 + split) * UMAX + tid] = rs[tid];
  }
  for (int e = tid; e < u * 64; e += 256) {
    int r = e >> 6, d = e & 63;
    g_pctx[((size_t)((bh * 4 + split) * UMAX + r)) * 64 + d] = ctxs[r * 64 + d];
  }
}

// ------------------- merge split-L partials ---------------------------------
__global__ __launch_bounds__(256) void ctx_merge_kernel(int L, int u, int nsplit)
{
  int bh = blockIdx.x;
  int tid = threadIdx.x;
  if (tid < 64) {
    float q = 0.f;
    for (int s = 0; s < nsplit; s++) q += g_pq[(bh * 4 + s) * 64 + tid];
    g_qmean[bh * 64 + tid] = q / (float)L;
  }
  for (int e = tid; e < u * 64; e += 256) {
    int r = e >> 6, d = e & 63;
    float M0 = -INFINITY;
    for (int s = 0; s < nsplit; s++)
      M0 = fmaxf(M0, g_pm[(bh * 4 + s) * UMAX + r]);
    float num = 0.f, den = 0.f;
    for (int s = 0; s < nsplit; s++) {
      float c = __expf(g_pm[(bh * 4 + s) * UMAX + r] - M0);
      num += g_pctx[((size_t)((bh * 4 + s) * UMAX + r)) * 64 + d] * c;
      den += g_ps[(bh * 4 + s) * UMAX + r] * c;
    }
    g_ctx[((size_t)(bh * u + r)) * 64 + d] = num / den;
  }
}

// ------------------- block reduce helper (128 threads) ---------------------
__device__ __forceinline__ float blocksum128(float v, float* sred)
{
  #pragma unroll
  for (int o = 16; o; o >>= 1) v += __shfl_xor_sync(0xffffffffu, v, o);
  if ((threadIdx.x & 31) == 0) sred[threadIdx.x >> 5] = v;
  __syncthreads();
  float t = sred[0] + sred[1] + sred[2] + sred[3];
  __syncthreads();
  return t;
}

// ------------------- assemble attention out + residual + LN1 + fp16 hi -----
__global__ __launch_bounds__(128) void assemble_ln1_kernel(
    const float* __restrict__ hin, float* __restrict__ xout,
    __half* __restrict__ xhi,
    const float* __restrict__ gamma, const float* __restrict__ beta,
    int L, int u)
{
  __shared__ float sred[4];
  int row = blockIdx.x;
  int b = row / L, l = row - b * L;
  int tid = threadIdx.x;
  float v[4];
  #pragma unroll
  for (int i = 0; i < 4; i++) {
    int e = i * 128 + tid;
    int hh = e >> 6, dd = e & 63;
    int bh = b * 8 + hh;
    int r = g_rowmap[(size_t)bh * L + l];
    float nv = (r >= 0) ? g_ctx[((size_t)(bh * u + r)) * 64 + dd]
                        : g_qmean[bh * 64 + dd];
    v[i] = hin[(size_t)row * DD + e] + nv;
  }
  float s = blocksum128(v[0] + v[1] + v[2] + v[3], sred);
  float mu = s * (1.0f / 512.0f);
  float vs = 0.f;
  #pragma unroll
  for (int i = 0; i < 4; i++) { float d = v[i] - mu; vs += d * d; }
  vs = blocksum128(vs, sred);
  float rstd = rsqrtf(vs * (1.0f / 512.0f) + LN_EPS);
  #pragma unroll
  for (int i = 0; i < 4; i++) {
    int e = i * 128 + tid;
    float o = (v[i] - mu) * rstd * gamma[e] + beta[e];
    xout[(size_t)row * DD + e] = o;
    xhi[(size_t)row * DD + e] = __float2half_rn(o);
  }
}

// ------------------- fused residual+LN2+distil (layers 0,1) ----------------
__global__ __launch_bounds__(128) void ln2_distil_kernel(
    const float* __restrict__ xin, const float* __restrict__ zin,
    float* __restrict__ outp,
    const float* __restrict__ gamma, const float* __restrict__ beta, int L2)
{
  __shared__ float sred[4];
  int rowo = blockIdx.x;
  int b = rowo / L2, l2 = rowo - b * L2;
  size_t r0 = ((size_t)b * (2 * L2) + 2 * l2);
  int tid = threadIdx.x;
  float o01[4];
  #pragma unroll
  for (int half = 0; half < 2; half++) {
    size_t row = r0 + half;
    float v[4];
    #pragma unroll
    for (int i = 0; i < 4; i++) {
      int e = i * 128 + tid;
      v[i] = xin[row * DD + e] + zin[row * DD + e];
    }
    float s = blocksum128(v[0] + v[1] + v[2] + v[3], sred);
    float mu = s * (1.0f / 512.0f);
    float vs = 0.f;
    #pragma unroll
    for (int i = 0; i < 4; i++) { float d = v[i] - mu; vs += d * d; }
    vs = blocksum128(vs, sred);
    float rstd = rsqrtf(vs * (1.0f / 512.0f) + LN_EPS);
    #pragma unroll
    for (int i = 0; i < 4; i++) {
      int e = i * 128 + tid;
      float o = (v[i] - mu) * rstd * gamma[e] + beta[e];
      if (half == 0) o01[i] = o; else o01[i] = 0.5f * (o01[i] + o);
    }
  }
  #pragma unroll
  for (int i = 0; i < 4; i++) {
    int e = i * 128 + tid;
    outp[(size_t)rowo * DD + e] = o01[i];
  }
}

// ------------------- residual + LN2 -> fp16 split only (last layer) --------
__global__ __launch_bounds__(128) void ln2_split_kernel(
    const float* __restrict__ xin, const float* __restrict__ zin,
    __half* __restrict__ ohi, __half* __restrict__ olo,
    const float* __restrict__ gamma, const float* __restrict__ beta)
{
  __shared__ float sred[4];
  size_t row = blockIdx.x;
  int tid = threadIdx.x;
  float v[4];
  #pragma unroll
  for (int i = 0; i < 4; i++) {
    int e = i * 128 + tid;
    v[i] = xin[row * DD + e] + zin[row * DD + e];
  }
  float s = blocksum128(v[0] + v[1] + v[2] + v[3], sred);
  float mu = s * (1.0f / 512.0f);
  float vs = 0.f;
  #pragma unroll
  for (int i = 0; i < 4; i++) { float d = v[i] - mu; vs += d * d; }
  vs = blocksum128(vs, sred);
  float rstd = rsqrtf(vs * (1.0f / 512.0f) + LN_EPS);
  #pragma unroll
  for (int i = 0; i < 4; i++) {
    int e = i * 128 + tid;
    float o = (v[i] - mu) * rstd * gamma[e] + beta[e];
    __half h16, l16;
    split_fp16(o, h16, l16);
    ohi[row * DD + e] = h16;
    olo[row * DD + e] = l16;
  }
}

// ------------------- fp16 tensor-core GEMM (1/2/3-pass) ---------------------
#define KC 32                     // k elems per stage
#define LDPB 80                   // padded row stride in BYTES (40 fp16)
#define PLANE_B (128*LDPB)        // 10240 bytes per plane

__device__ __forceinline__ void mma_fp16(float* c, const unsigned* a, const unsigned* b)
{
  asm volatile(
    "mma.sync.aligned.m16n8k16.row.col.f32.f16.f16.f32 "
    "{%0,%1,%2,%3},{%4,%5,%6,%7},{%8,%9},{%0,%1,%2,%3};\n"
    : "+f"(c[0]), "+f"(c[1]), "+f"(c[2]), "+f"(c[3])
    : "r"(a[0]), "r"(a[1]), "r"(a[2]), "r"(a[3]), "r"(b[0]), "r"(b[1]));
}

__device__ __forceinline__ void ldsm4(unsigned* r, const char* sptr)
{
  unsigned addr = (unsigned)__cvta_generic_to_shared(sptr);
  asm volatile("ldmatrix.sync.aligned.m8n8.x4.shared.b16 {%0,%1,%2,%3}, [%4];\n"
    : "=r"(r[0]), "=r"(r[1]), "=r"(r[2]), "=r"(r[3]) : "r"(addr));
}

// EPI 0: Cf = acc + bias (fp32)
// EPI 1: Chi = fp16(gelu(acc + bias))
// EPI 2: Cf = acc + bias + positional encoding (fp32; uses Lmask)
// NPASS 1: A_hi x B_hi | NPASS 2: (A_hi+A_lo) x B_hi | NPASS 3: + A_hi x B_lo
template<int EPI, int NPASS>
__global__ __launch_bounds__(256, 2) void mma_gemm(
    const __half* __restrict__ Ahi, const __half* __restrict__ Alo,
    const __half* __restrict__ Bhi, const __half* __restrict__ Blo,
    const float* __restrict__ bias,
    float* __restrict__ Cf, __half* __restrict__ Chi,
    int M, int N, int K, int Lmask)
{
  constexpr int NPLANES = (NPASS == 3) ? 4 : (NPASS + 1);
  const int STGB = NPLANES * PLANE_B;
  extern __shared__ char smc[];
  const int tid = threadIdx.x;
  const int bm = blockIdx.y * 128, bn = blockIdx.x * 128;
  const int lane = tid & 31;
  const int g = lane >> 2, t4 = lane & 3;
  const int warp = tid >> 5;
  const int wm = warp >> 2, wn = warp & 3;      // warps 2(m) x 4(n)
  const int moff = wm * 64, noff = wn * 32;

  const int aoff = (lane & 15) * LDPB + ((lane & 16) ? 16 : 0);
  const int boff = ((lane & 7) + ((lane & 16) ? 8 : 0)) * LDPB + ((lane & 8) ? 16 : 0);

  float acc[4][4][4];
  #pragma unroll
  for (int i = 0; i < 4; i++)
    #pragma unroll
    for (int j = 0; j < 4; j++)
      #pragma unroll
      for (int q = 0; q < 4; q++) acc[i][j][q] = 0.f;

  const int KT = K / KC;

  #define PREFETCH(kt, s) do {                                                   \
    int k0_ = (kt) * KC;                                                         \
    const char* srcs_[NPLANES];                                                  \
    int np_ = 0;                                                                 \
    srcs_[np_++] = (const char*)(Ahi + (size_t)bm * K + k0_);                    \
    if (NPASS >= 2) srcs_[np_++] = (const char*)(Alo + (size_t)bm * K + k0_);    \
    srcs_[np_++] = (const char*)(Bhi + (size_t)bn * K + k0_);                    \
    if (NPASS == 3) srcs_[np_++] = (const char*)(Blo + (size_t)bn * K + k0_);    \
    _Pragma("unroll")                                                            \
    for (int p_ = 0; p_ < NPLANES; p_++) {                                       \
      char* dstp_ = smc + (s) * STGB + p_ * PLANE_B;                             \
      _Pragma("unroll")                                                          \
      for (int j_ = 0; j_ < 2; j_++) {                                           \
        int idx_ = j_ * 256 + tid;                                               \
        int row_ = idx_ >> 2, ch_ = idx_ & 3;                                    \
        unsigned sa_ = (unsigned)__cvta_generic_to_shared(dstp_ + row_ * LDPB + ch_ * 16); \
        const char* ga_ = srcs_[p_] + (size_t)row_ * K * 2 + ch_ * 16;           \
        asm volatile("cp.async.ca.shared.global [%0], [%1], 16;\n"               \
                     :: "r"(sa_), "l"(ga_));                                     \
      }                                                                          \
    }                                                                            \
    asm volatile("cp.async.commit_group;\n");                                    \
  } while (0)

  PREFETCH(0, 0);

  for (int kt = 0; kt < KT; kt++) {
    asm volatile("cp.async.wait_group 0;\n");
    __syncthreads();
    if (kt + 1 < KT) PREFETCH(kt + 1, (kt + 1) & 1);

    const char* Sahi = smc + (kt & 1) * STGB;
    const char* Salo = Sahi + PLANE_B;                         // NPASS>=2
    const char* Sbhi = Sahi + ((NPASS >= 2) ? 2 : 1) * PLANE_B;
    const char* Sblo = Sbhi + PLANE_B;                         // NPASS==3

    #pragma unroll
    for (int ks = 0; ks < 2; ks++) {
      int kb = ks * 32;   // 16 fp16 = 32 bytes
      unsigned bh_[2][4], bl_[2][4];
      #pragma unroll
      for (int pp = 0; pp < 2; pp++) {
        ldsm4(bh_[pp], Sbhi + (noff + pp * 16) * LDPB + kb + boff);
        if (NPASS == 3)
          ldsm4(bl_[pp], Sblo + (noff + pp * 16) * LDPB + kb + boff);
      }
      #pragma unroll
      for (int tm = 0; tm < 4; tm++) {
        unsigned ah[4], al[4];
        ldsm4(ah, Sahi + (moff + tm * 16) * LDPB + kb + aoff);
        if (NPASS >= 2)
          ldsm4(al, Salo + (moff + tm * 16) * LDPB + kb + aoff);
        #pragma unroll
        for (int tn = 0; tn < 4; tn++) {
          const unsigned* bhp = &bh_[tn >> 1][(tn & 1) * 2];
          mma_fp16(acc[tm][tn], ah, bhp);
          if (NPASS >= 2) mma_fp16(acc[tm][tn], al, bhp);
          if (NPASS == 3) {
            const unsigned* blp = &bl_[tn >> 1][(tn & 1) * 2];
            mma_fp16(acc[tm][tn], ah, blp);
          }
        }
      }
    }
    __syncthreads();
  }

  // ---- epilogue ----
  #pragma unroll
  for (int tm = 0; tm < 4; tm++) {
    int r0 = bm + moff + tm * 16 + g;
    int r1 = r0 + 8;
    #pragma unroll
    for (int tn = 0; tn < 4; tn++) {
      int c0 = bn + noff + tn * 8 + 2 * t4;   // even column
      float b0 = bias[c0], b1 = bias[c0 + 1];
      float v00 = acc[tm][tn][0] + b0;
      float v01 = acc[tm][tn][1] + b1;
      float v10 = acc[tm][tn][2] + b0;
      float v11 = acc[tm][tn][3] + b1;
      if (EPI == 1) {
        v00 = 0.5f * v00 * (1.f + erff(v00 * 0.70710678118654752f));
        v01 = 0.5f * v01 * (1.f + erff(v01 * 0.70710678118654752f));
        v10 = 0.5f * v10 * (1.f + erff(v10 * 0.70710678118654752f));
        v11 = 0.5f * v11 * (1.f + erff(v11 * 0.70710678118654752f));
        *(__half2*)(Chi + (size_t)r0 * N + c0) =
          __halves2half2(__float2half_rn(v00), __float2half_rn(v01));
        *(__half2*)(Chi + (size_t)r1 * N + c0) =
          __halves2half2(__float2half_rn(v10), __float2half_rn(v11));
      } else {
        if (EPI == 2) {
          float df = expf((float)c0 * (-0.017988946039015984f));
          float a0 = (float)(r0 & Lmask) * df;
          float a1 = (float)(r1 & Lmask) * df;
          v00 += sinf(a0); v01 += cosf(a0);
          v10 += sinf(a1); v11 += cosf(a1);
        }
        *(float2*)(Cf + (size_t)r0 * N + c0) = make_float2(v00, v01);
        *(float2*)(Cf + (size_t)r1 * N + c0) = make_float2(v10, v11);
      }
    }
  }
  #undef PREFETCH
}

// ------------------- host: layer key derivation ----------------------------
static void layer_key(int i, unsigned &k0, unsigned &k1)
{
  unsigned a = 0u, b = (unsigned)i;
  threefry2x32(0u, 42u, a, b);
  unsigned c = 0u, d = 1u;
  threefry2x32(a, b, c, d);
  k0 = c; k1 = d;
}

extern "C" void kernel_launch(void* const* d_in, const int* in_sizes, int n_in,
                              void* d_out, int out_size)
{
  const float* x     = (const float*)d_in[0];
  const float* emb_w = (const float*)d_in[1];
  const float* emb_b = (const float*)d_in[2];
  const float* ln1_s = (const float*)d_in[3];
  const float* ln1_b = (const float*)d_in[4];
  const float* w1    = (const float*)d_in[5];
  const float* b1    = (const float*)d_in[6];
  const float* w2    = (const float*)d_in[7];
  const float* b2    = (const float*)d_in[8];
  const float* ln2_s = (const float*)d_in[9];
  const float* ln2_b = (const float*)d_in[10];
  const float* out_w = (const float*)d_in[11];
  const float* out_b = (const float*)d_in[12];
  float* out = (float*)d_out;

  float *ph, *px, *pz;
  __half *pxhi, *pxlo, *pyhi;
  __half *pw1hi, *pw2hi, *powhi;
  __half *pexhi, *pexlo, *pewhi, *pewlo;
  cudaGetSymbolAddress((void**)&ph,   g_h);
  cudaGetSymbolAddress((void**)&px,   g_x);
  cudaGetSymbolAddress((void**)&pz,   g_z);
  cudaGetSymbolAddress((void**)&pxhi, g_xhi);
  cudaGetSymbolAddress((void**)&pxlo, g_xlo);
  cudaGetSymbolAddress((void**)&pyhi, g_yhi);
  cudaGetSymbolAddress((void**)&pw1hi, g_w1hi);
  cudaGetSymbolAddress((void**)&pw2hi, g_w2hi);
  cudaGetSymbolAddress((void**)&powhi, g_owhi);
  cudaGetSymbolAddress((void**)&pexhi, g_exhi);
  cudaGetSymbolAddress((void**)&pexlo, g_exlo);
  cudaGetSymbolAddress((void**)&pewhi, g_ewhi);
  cudaGetSymbolAddress((void**)&pewlo, g_ewlo);

  static int smem_set = 0;
  if (!smem_set) {
    cudaFuncSetAttribute(mma_gemm<2,3>, cudaFuncAttributeMaxDynamicSharedMemorySize, 2 * 4 * PLANE_B);
    cudaFuncSetAttribute(mma_gemm<1,1>, cudaFuncAttributeMaxDynamicSharedMemorySize, 2 * 2 * PLANE_B);
    cudaFuncSetAttribute(mma_gemm<0,1>, cudaFuncAttributeMaxDynamicSharedMemorySize, 2 * 2 * PLANE_B);
    cudaFuncSetAttribute(mma_gemm<0,2>, cudaFuncAttributeMaxDynamicSharedMemorySize, 2 * 3 * PLANE_B);
    cudaFuncSetAttribute(ctx_split_kernel, cudaFuncAttributeMaxDynamicSharedMemorySize, CTX_SMEM_FLOATS * 4);
    smem_set = 1;
  }
  const int ctx_smem = CTX_SMEM_FLOATS * 4;

  // weight/input fp16 conversions
  {
    int n1 = 3 * DFF * DD;
    whalf_kernel<<<(n1 + 255) / 256, 256>>>(w1, pw1hi, n1);
    whalf_kernel<<<(n1 + 255) / 256, 256>>>(w2, pw2hi, n1);
    int n2 = DD * DD;
    whalf_kernel<<<(n2 + 255) / 256, 256>>>(out_w, powhi, n2);
    int n3 = BB * L0 * 64;
    xsplit_kernel<<<(n3 + 255) / 256, 256>>>(x, pexhi, pexlo, n3);
    int n4 = DD * 64;
    xsplit_kernel<<<(n4 + 255) / 256, 256>>>(emb_w, pewhi, pewlo, n4);
  }

  // Embed (3-pass fp16 mma): h = x @ emb_w^T + emb_b + PE (M=32768,N=512,K=64)
  {
    int M = BB * L0;
    mma_gemm<2,3><<<dim3(DD / 128, M / 128), 256, 2 * 4 * PLANE_B>>>(
        pexhi, pexlo, pewhi, pewlo, emb_b, ph, nullptr, M, DD, 64, L0 - 1);
  }

  int L = L0;
  float* cur = ph;
  for (int i = 0; i < 3; i++) {
    int u = (i == 0) ? 45 : (i == 1) ? 40 : 35;
    int M = BB * L;
    unsigned k0, k1; layer_key(i, k0, k1);
    int total = L * u;
    idx_part<<<(total + 255) / 256, 256>>>(k0, k1, total, L - 1);
    prob_m_kernel<<<dim3(L / 8, 64), 256>>>(cur, L, u, 1.0f / (float)L);
    topk_kernel<<<64, 256>>>(L, u);
    int nsplit = L / 1024; if (nsplit < 1) nsplit = 1; if (nsplit > 4) nsplit = 4;
    ctx_split_kernel<<<dim3(nsplit, 64), 256, ctx_smem>>>(cur, L, u, L / nsplit);
    ctx_merge_kernel<<<64, 256>>>(L, u, nsplit);
    assemble_ln1_kernel<<<M, 128>>>(cur, px, pxhi,
                                    ln1_s + i * DD, ln1_b + i * DD, L, u);

    // FFN1: y = gelu(x @ w1^T + b1), 1-pass, fp16 out
    mma_gemm<1,1><<<dim3(DFF / 128, M / 128), 256, 2 * 2 * PLANE_B>>>(
        pxhi, nullptr, pw1hi + (size_t)i * DFF * DD, nullptr,
        b1 + i * DFF, nullptr, pyhi, M, DFF, DD, 0);
    // FFN2: z = y @ w2^T + b2, 1-pass, fp32 out
    mma_gemm<0,1><<<dim3(DD / 128, M / 128), 256, 2 * 2 * PLANE_B>>>(
        pyhi, nullptr, pw2hi + (size_t)i * DD * DFF, nullptr,
        b2 + i * DD, pz, nullptr, M, DD, DFF, 0);

    if (i < 2) {
      int L2 = L / 2;
      ln2_distil_kernel<<<BB * L2, 128>>>(px, pz, cur,
                                          ln2_s + i * DD, ln2_b + i * DD, L2);
      L = L2;
    } else {
      ln2_split_kernel<<<M, 128>>>(px, pz, pxhi, pxlo,
                                   ln2_s + i * DD, ln2_b + i * DD);
    }
  }

  // Final projection: out = h @ out_w^T + out_b, 2-pass A (M=8192,N=512,K=512)
  {
    int M = BB * L;   // L = 1024
    mma_gemm<0,2><<<dim3(DD / 128, M / 128), 256, 2 * 3 * PLANE_B>>>(
        pxhi, pxlo, powhi, nullptr, out_b, out, nullptr, M, DD, DD, 0);
  }
}

// round 10
// speedup vs baseline: 4.0502x; 1.0705x over previous
#include <cuda_runtime.h>
#include <cuda_fp16.h>
#include <math.h>
#include <stdint.h>

#define BB 8
#define DD 512
#define DFF 2048
#define L0 4096
#define UMAX 45
#define LN_EPS 1e-5f

// ------------------- scratch (device globals; no allocs) -------------------
__device__ __align__(16) float g_h  [BB*L0*DD];
__device__ __align__(16) __half g_hh [BB*L0*DD];   // fp16 mirror for attention reads
__device__ __align__(16) float g_x  [BB*L0*DD];
__device__ __align__(16) float g_z  [BB*L0*DD];
__device__ __align__(16) __half g_xhi[BB*L0*DD];
__device__ __align__(16) __half g_xlo[BB*L0*DD];
__device__ __align__(16) __half g_yhi[BB*L0*DFF];
__device__ __align__(16) __half g_w1hi[3*DFF*DD];
__device__ __align__(16) __half g_w2hi[3*DD*DFF];
__device__ __align__(16) __half g_owhi[DD*DD];
__device__ __align__(16) __half g_exhi[BB*L0*64];
__device__ __align__(16) __half g_exlo[BB*L0*64];
__device__ __align__(16) __half g_ewhi[DD*64];
__device__ __align__(16) __half g_ewlo[DD*64];
__device__ __align__(16) float g_M  [BB*8*L0];
__device__ __align__(16) int   g_idx[L0*UMAX];
__device__ __align__(16) int   g_top[BB*8*UMAX];
__device__ __align__(16) int   g_rowmap[BB*8*L0];
__device__ __align__(16) float g_ctx[BB*8*UMAX*64];
__device__ __align__(16) float g_qmean[BB*8*64];
// split-L ctx partials (max 4 splits)
__device__ __align__(16) float g_pm  [64*4*UMAX];
__device__ __align__(16) float g_ps  [64*4*UMAX];
__device__ __align__(16) float g_pctx[64*4*UMAX*64];
__device__ __align__(16) float g_pq  [64*4*64];

// ------------------- fp16 split helpers -------------------------------------
__device__ __forceinline__ void split_fp16(float v, __half &hi, __half &lo)
{
  hi = __float2half_rn(v);
  lo = __float2half_rn(v - __half2float(hi));
}

// ------------------- threefry2x32 (JAX-compatible) -------------------------
#define TF_R(x0,x1,r) { x0 += x1; x1 = ((x1 << (r)) | (x1 >> (32-(r)))); x1 ^= x0; }
__host__ __device__ inline void threefry2x32(unsigned ks0, unsigned ks1,
                                             unsigned &x0, unsigned &x1)
{
  unsigned ks2 = ks0 ^ ks1 ^ 0x1BD11BDAu;
  x0 += ks0; x1 += ks1;
  TF_R(x0,x1,13) TF_R(x0,x1,15) TF_R(x0,x1,26) TF_R(x0,x1,6)
  x0 += ks1; x1 += ks2 + 1u;
  TF_R(x0,x1,17) TF_R(x0,x1,29) TF_R(x0,x1,16) TF_R(x0,x1,24)
  x0 += ks2; x1 += ks0 + 2u;
  TF_R(x0,x1,13) TF_R(x0,x1,15) TF_R(x0,x1,26) TF_R(x0,x1,6)
  x0 += ks0; x1 += ks1 + 3u;
  TF_R(x0,x1,17) TF_R(x0,x1,29) TF_R(x0,x1,16) TF_R(x0,x1,24)
  x0 += ks1; x1 += ks2 + 4u;
  TF_R(x0,x1,13) TF_R(x0,x1,15) TF_R(x0,x1,26) TF_R(x0,x1,6)
  x0 += ks2; x1 += ks0 + 5u;
}

__global__ void idx_part(unsigned k0, unsigned k1, int total, int mask)
{
  int t = blockIdx.x * 256 + threadIdx.x;
  if (t >= total) return;
  unsigned x0 = 0u, x1 = (unsigned)t;
  threefry2x32(k0, k1, x0, x1);
  g_idx[t] = (int)((x0 ^ x1) & (unsigned)mask);
}

// ------------------- splits -------------------------------------------------
__global__ void whalf_kernel(const float* __restrict__ w,
                             __half* __restrict__ hi, int n)
{
  int i = blockIdx.x * 256 + threadIdx.x;
  if (i >= n) return;
  hi[i] = __float2half_rn(w[i]);
}

__global__ void xsplit_kernel(const float* __restrict__ w,
                              __half* __restrict__ hi, __half* __restrict__ lo, int n)
{
  int i = blockIdx.x * 256 + threadIdx.x;
  if (i >= n) return;
  __half h, l;
  split_fp16(w[i], h, l);
  hi[i] = h; lo[i] = l;
}

// ------------------- M = max_s qk - sum_s qk / L (fp16 reads) ---------------
__global__ __launch_bounds__(256) void prob_m_kernel(
    const __half* __restrict__ hh, int L, int u, float invL)
{
  int bh = blockIdx.y; int b = bh >> 3, hd = bh & 7;
  int warp = threadIdx.x >> 5, lane = threadIdx.x & 31;
  int l = blockIdx.x * 8 + warp;
  const __half* base = hh + (size_t)b * L * DD + hd * 64;
  float2 q2;
  {
    __half2 t = *(const __half2*)(base + (size_t)l * DD + 2 * lane);
    q2 = __half22float2(t);
  }

  int idxA = (lane < u)      ? g_idx[l * u + lane]      : 0;
  int idxB = (lane + 32 < u) ? g_idx[l * u + lane + 32] : 0;

  float mx = -INFINITY, sm = 0.f;
  for (int s = 0; s < u; s++) {
    int kl = __shfl_sync(0xffffffffu, (s < 32) ? idxA : idxB, s & 31);
    __half2 kh = *(const __half2*)(base + (size_t)kl * DD + 2 * lane);
    float2 k2 = __half22float2(kh);
    float p = q2.x * k2.x + q2.y * k2.y;
    #pragma unroll
    for (int o = 16; o; o >>= 1) p += __shfl_xor_sync(0xffffffffu, p, o);
    mx = fmaxf(mx, p); sm += p;
  }
  if (lane == 0) g_M[(size_t)bh * L + l] = mx - sm * invL;
}

// ------------------- top-k (iterative argmax, lower-index tiebreak) --------
__global__ __launch_bounds__(256) void topk_kernel(int L, int u)
{
  __shared__ float sM[L0];
  __shared__ float sval[8];
  __shared__ int   sidx[8];
  int bh = blockIdx.x;
  int tid = threadIdx.x;
  int w = tid >> 5, lane = tid & 31;
  for (int l = tid; l < L; l += 256) {
    sM[l] = g_M[(size_t)bh * L + l];
    g_rowmap[(size_t)bh * L + l] = -1;
  }
  __syncthreads();
  for (int r = 0; r < u; r++) {
    float bv = -INFINITY; int bi = 0x7fffffff;
    for (int l = tid; l < L; l += 256) {
      float v = sM[l];
      if (v > bv || (v == bv && l < bi)) { bv = v; bi = l; }
    }
    #pragma unroll
    for (int o = 16; o; o >>= 1) {
      float v2 = __shfl_xor_sync(0xffffffffu, bv, o);
      int   i2 = __shfl_xor_sync(0xffffffffu, bi, o);
      if (v2 > bv || (v2 == bv && i2 < bi)) { bv = v2; bi = i2; }
    }
    if (lane == 0) { sval[w] = bv; sidx[w] = bi; }
    __syncthreads();
    if (tid == 0) {
      float Bv = sval[0]; int Bi = sidx[0];
      #pragma unroll
      for (int q = 1; q < 8; q++) {
        if (sval[q] > Bv || (sval[q] == Bv && sidx[q] < Bi)) {
          Bv = sval[q]; Bi = sidx[q];
        }
      }
      g_top[bh * u + r] = Bi;
      g_rowmap[(size_t)bh * L + Bi] = r;
      sM[Bi] = -INFINITY;
    }
    __syncthreads();
  }
}

// ------------------- split-L ctx (fp16 key reads) ---------------------------
// smem floats: qs 3072 | kt 4352 | sc 3072 | ctxs 3072 | rm/rs/rsc 144 | qred 256
#define CTX_SMEM_FLOATS (13568 + 144 + 256)
__global__ __launch_bounds__(256) void ctx_split_kernel(
    const __half* __restrict__ hh, int L, int u, int klen)
{
  extern __shared__ float dsm[];
  float* qs   = dsm;            // stride 64
  float* kt   = dsm + 3072;     // stride 68
  float* sc   = dsm + 7424;     // stride 64
  float* ctxs = dsm + 10496;    // stride 64
  float* rm   = dsm + 13568;
  float* rs   = dsm + 13616;
  float* rsc  = dsm + 13664;
  float* qred = dsm + 13712;    // [4][64]

  int split = blockIdx.x;
  int bh = blockIdx.y; int b = bh >> 3, hd = bh & 7;
  const __half* base = hh + (size_t)b * L * DD + hd * 64;
  int tid = threadIdx.x;
  int kbeg = split * klen;

  for (int e = tid; e < u * 64; e += 256) {
    int r = e >> 6, d = e & 63;
    qs[r * 64 + d] = __half2float(base[(size_t)g_top[bh * u + r] * DD + d]);
    ctxs[e] = 0.f;
  }
  if (tid < u) { rm[tid] = -INFINITY; rs[tid] = 0.f; }
  __syncthreads();

  const int j  = tid & 63;
  const int rg = tid >> 6;
  const int w  = tid >> 5, lane = tid & 31;
  float qacc = 0.f;

  for (int t0 = kbeg; t0 < kbeg + klen; t0 += 64) {
    // load 64-key tile (fp16 -> fp32 smem); 8 halfs per thread-iter
    for (int e = tid; e < 64 * 8; e += 256) {
      int r = e >> 3, c8 = e & 7;
      uint4 v = *(const uint4*)(base + (size_t)(t0 + r) * DD + c8 * 8);
      const __half2* hp = (const __half2*)&v;
      float* kr = kt + r * 68 + c8 * 8;
      #pragma unroll
      for (int q = 0; q < 4; q++) {
        float2 f = __half22float2(hp[q]);
        kr[2 * q] = f.x; kr[2 * q + 1] = f.y;
      }
    }
    __syncthreads();

    #pragma unroll
    for (int r = 0; r < 16; r++) qacc += kt[(rg + r * 4) * 68 + j];

    {
      float kreg[64];
      #pragma unroll
      for (int d = 0; d < 64; d++) kreg[d] = kt[j * 68 + d];
      for (int r = rg; r < u; r += 4) {
        const float* qr = qs + r * 64;
        float dot = 0.f;
        #pragma unroll
        for (int d = 0; d < 64; d++) dot += qr[d] * kreg[d];
        sc[r * 64 + j] = dot * 0.125f;
      }
    }
    __syncthreads();
    for (int r = w; r < u; r += 8) {
      float v0 = sc[r * 64 + lane], v1 = sc[r * 64 + lane + 32];
      float mx = fmaxf(v0, v1);
      #pragma unroll
      for (int o = 16; o; o >>= 1) mx = fmaxf(mx, __shfl_xor_sync(0xffffffffu, mx, o));
      float mold = rm[r];
      float mnew = fmaxf(mold, mx);
      float p0 = __expf(v0 - mnew), p1 = __expf(v1 - mnew);
      float ps = p0 + p1;
      #pragma unroll
      for (int o = 16; o; o >>= 1) ps += __shfl_xor_sync(0xffffffffu, ps, o);
      if (lane == 0) {
        float cold = __expf(mold - mnew);
        rsc[r] = cold;
        rs[r] = rs[r] * cold + ps;
        rm[r] = mnew;
      }
      sc[r * 64 + lane] = p0; sc[r * 64 + lane + 32] = p1;
    }
    __syncthreads();
    for (int r = rg; r < u; r += 4) {
      const float* pr = sc + r * 64;
      float a = 0.f;
      #pragma unroll
      for (int jj = 0; jj < 64; jj++) a += pr[jj] * kt[jj * 68 + j];
      ctxs[r * 64 + j] = ctxs[r * 64 + j] * rsc[r] + a;
    }
    __syncthreads();
  }

  // write partials
  qred[rg * 64 + j] = qacc;
  __syncthreads();
  if (rg == 0)
    g_pq[(bh * 4 + split) * 64 + j] =
      qred[j] + qred[64 + j] + qred[128 + j] + qred[192 + j];
  if (tid < u) {
    g_pm[(bh * 4 + split) * UMAX + tid] = rm[tid];
    g_ps[(bh * 4 + split) * UMAX + tid] = rs[tid];
  }
  for (int e = tid; e < u * 64; e += 256) {
    int r = e >> 6, d = e & 63;
    g_pctx[((size_t)((bh * 4 + split) * UMAX + r)) * 64 + d] = ctxs[r * 64 + d];
  }
}

// ------------------- merge split-L partials ---------------------------------
__global__ __launch_bounds__(256) void ctx_merge_kernel(int L, int u, int nsplit)
{
  int bh = blockIdx.x;
  int tid = threadIdx.x;
  if (tid < 64) {
    float q = 0.f;
    for (int s = 0; s < nsplit; s++) q += g_pq[(bh * 4 + s) * 64 + tid];
    g_qmean[bh * 64 + tid] = q / (float)L;
  }
  for (int e = tid; e < u * 64; e += 256) {
    int r = e >> 6, d = e & 63;
    float M0 = -INFINITY;
    for (int s = 0; s < nsplit; s++)
      M0 = fmaxf(M0, g_pm[(bh * 4 + s) * UMAX + r]);
    float num = 0.f, den = 0.f;
    for (int s = 0; s < nsplit; s++) {
      float c = __expf(g_pm[(bh * 4 + s) * UMAX + r] - M0);
      num += g_pctx[((size_t)((bh * 4 + s) * UMAX + r)) * 64 + d] * c;
      den += g_ps[(bh * 4 + s) * UMAX + r] * c;
    }
    g_ctx[((size_t)(bh * u + r)) * 64 + d] = num / den;
  }
}

// ------------------- block reduce helper (128 threads) ---------------------
__device__ __forceinline__ float blocksum128(float v, float* sred)
{
  #pragma unroll
  for (int o = 16; o; o >>= 1) v += __shfl_xor_sync(0xffffffffu, v, o);
  if ((threadIdx.x & 31) == 0) sred[threadIdx.x >> 5] = v;
  __syncthreads();
  float t = sred[0] + sred[1] + sred[2] + sred[3];
  __syncthreads();
  return t;
}

// ------------------- assemble attention out + residual + LN1 + fp16 hi -----
__global__ __launch_bounds__(128) void assemble_ln1_kernel(
    const float* __restrict__ hin, float* __restrict__ xout,
    __half* __restrict__ xhi,
    const float* __restrict__ gamma, const float* __restrict__ beta,
    int L, int u)
{
  __shared__ float sred[4];
  int row = blockIdx.x;
  int b = row / L, l = row - b * L;
  int tid = threadIdx.x;
  float v[4];
  #pragma unroll
  for (int i = 0; i < 4; i++) {
    int e = i * 128 + tid;
    int hh = e >> 6, dd = e & 63;
    int bh = b * 8 + hh;
    int r = g_rowmap[(size_t)bh * L + l];
    float nv = (r >= 0) ? g_ctx[((size_t)(bh * u + r)) * 64 + dd]
                        : g_qmean[bh * 64 + dd];
    v[i] = hin[(size_t)row * DD + e] + nv;
  }
  float s = blocksum128(v[0] + v[1] + v[2] + v[3], sred);
  float mu = s * (1.0f / 512.0f);
  float vs = 0.f;
  #pragma unroll
  for (int i = 0; i < 4; i++) { float d = v[i] - mu; vs += d * d; }
  vs = blocksum128(vs, sred);
  float rstd = rsqrtf(vs * (1.0f / 512.0f) + LN_EPS);
  #pragma unroll
  for (int i = 0; i < 4; i++) {
    int e = i * 128 + tid;
    float o = (v[i] - mu) * rstd * gamma[e] + beta[e];
    xout[(size_t)row * DD + e] = o;
    xhi[(size_t)row * DD + e] = __float2half_rn(o);
  }
}

// ------------------- fused residual+LN2+distil (layers 0,1) ----------------
// writes fp32 next-layer input + fp16 mirror for attention reads
__global__ __launch_bounds__(128) void ln2_distil_kernel(
    const float* __restrict__ xin, const float* __restrict__ zin,
    float* __restrict__ outp, __half* __restrict__ outh,
    const float* __restrict__ gamma, const float* __restrict__ beta, int L2)
{
  __shared__ float sred[4];
  int rowo = blockIdx.x;
  int b = rowo / L2, l2 = rowo - b * L2;
  size_t r0 = ((size_t)b * (2 * L2) + 2 * l2);
  int tid = threadIdx.x;
  float o01[4];
  #pragma unroll
  for (int half = 0; half < 2; half++) {
    size_t row = r0 + half;
    float v[4];
    #pragma unroll
    for (int i = 0; i < 4; i++) {
      int e = i * 128 + tid;
      v[i] = xin[row * DD + e] + zin[row * DD + e];
    }
    float s = blocksum128(v[0] + v[1] + v[2] + v[3], sred);
    float mu = s * (1.0f / 512.0f);
    float vs = 0.f;
    #pragma unroll
    for (int i = 0; i < 4; i++) { float d = v[i] - mu; vs += d * d; }
    vs = blocksum128(vs, sred);
    float rstd = rsqrtf(vs * (1.0f / 512.0f) + LN_EPS);
    #pragma unroll
    for (int i = 0; i < 4; i++) {
      int e = i * 128 + tid;
      float o = (v[i] - mu) * rstd * gamma[e] + beta[e];
      if (half == 0) o01[i] = o; else o01[i] = 0.5f * (o01[i] + o);
    }
  }
  #pragma unroll
  for (int i = 0; i < 4; i++) {
    int e = i * 128 + tid;
    outp[(size_t)rowo * DD + e] = o01[i];
    outh[(size_t)rowo * DD + e] = __float2half_rn(o01[i]);
  }
}

// ------------------- residual + LN2 -> fp16 split only (last layer) --------
__global__ __launch_bounds__(128) void ln2_split_kernel(
    const float* __restrict__ xin, const float* __restrict__ zin,
    __half* __restrict__ ohi, __half* __restrict__ olo,
    const float* __restrict__ gamma, const float* __restrict__ beta)
{
  __shared__ float sred[4];
  size_t row = blockIdx.x;
  int tid = threadIdx.x;
  float v[4];
  #pragma unroll
  for (int i = 0; i < 4; i++) {
    int e = i * 128 + tid;
    v[i] = xin[row * DD + e] + zin[row * DD + e];
  }
  float s = blocksum128(v[0] + v[1] + v[2] + v[3], sred);
  float mu = s * (1.0f / 512.0f);
  float vs = 0.f;
  #pragma unroll
  for (int i = 0; i < 4; i++) { float d = v[i] - mu; vs += d * d; }
  vs = blocksum128(vs, sred);
  float rstd = rsqrtf(vs * (1.0f / 512.0f) + LN_EPS);
  #pragma unroll
  for (int i = 0; i < 4; i++) {
    int e = i * 128 + tid;
    float o = (v[i] - mu) * rstd * gamma[e] + beta[e];
    __half h16, l16;
    split_fp16(o, h16, l16);
    ohi[row * DD + e] = h16;
    olo[row * DD + e] = l16;
  }
}

// ------------------- fp16 tensor-core GEMM (1/2/3-pass) ---------------------
#define KC 32                     // k elems per stage
#define LDPB 80                   // padded row stride in BYTES (40 fp16)
#define PLANE_B (128*LDPB)        // 10240 bytes per plane

__device__ __forceinline__ void mma_fp16(float* c, const unsigned* a, const unsigned* b)
{
  asm volatile(
    "mma.sync.aligned.m16n8k16.row.col.f32.f16.f16.f32 "
    "{%0,%1,%2,%3},{%4,%5,%6,%7},{%8,%9},{%0,%1,%2,%3};\n"
    : "+f"(c[0]), "+f"(c[1]), "+f"(c[2]), "+f"(c[3])
    : "r"(a[0]), "r"(a[1]), "r"(a[2]), "r"(a[3]), "r"(b[0]), "r"(b[1]));
}

__device__ __forceinline__ void ldsm4(unsigned* r, const char* sptr)
{
  unsigned addr = (unsigned)__cvta_generic_to_shared(sptr);
  asm volatile("ldmatrix.sync.aligned.m8n8.x4.shared.b16 {%0,%1,%2,%3}, [%4];\n"
    : "=r"(r[0]), "=r"(r[1]), "=r"(r[2]), "=r"(r[3]) : "r"(addr));
}

// EPI 0: Cf = acc + bias (fp32)
// EPI 1: Chi = fp16(gelu(acc + bias))
// EPI 2: Cf = acc + bias + PE (fp32) AND Chh = fp16 copy
// NPASS 1: A_hi x B_hi | NPASS 2: (A_hi+A_lo) x B_hi | NPASS 3: + A_hi x B_lo
template<int EPI, int NPASS>
__global__ __launch_bounds__(256, 2) void mma_gemm(
    const __half* __restrict__ Ahi, const __half* __restrict__ Alo,
    const __half* __restrict__ Bhi, const __half* __restrict__ Blo,
    const float* __restrict__ bias,
    float* __restrict__ Cf, __half* __restrict__ Chi, __half* __restrict__ Chh,
    int M, int N, int K, int Lmask)
{
  constexpr int NPLANES = (NPASS == 3) ? 4 : (NPASS + 1);
  const int STGB = NPLANES * PLANE_B;
  extern __shared__ char smc[];
  const int tid = threadIdx.x;
  const int bm = blockIdx.y * 128, bn = blockIdx.x * 128;
  const int lane = tid & 31;
  const int g = lane >> 2, t4 = lane & 3;
  const int warp = tid >> 5;
  const int wm = warp >> 2, wn = warp & 3;      // warps 2(m) x 4(n)
  const int moff = wm * 64, noff = wn * 32;

  const int aoff = (lane & 15) * LDPB + ((lane & 16) ? 16 : 0);
  const int boff = ((lane & 7) + ((lane & 16) ? 8 : 0)) * LDPB + ((lane & 8) ? 16 : 0);

  float acc[4][4][4];
  #pragma unroll
  for (int i = 0; i < 4; i++)
    #pragma unroll
    for (int j = 0; j < 4; j++)
      #pragma unroll
      for (int q = 0; q < 4; q++) acc[i][j][q] = 0.f;

  const int KT = K / KC;

  #define PREFETCH(kt, s) do {                                                   \
    int k0_ = (kt) * KC;                                                         \
    const char* srcs_[NPLANES];                                                  \
    int np_ = 0;                                                                 \
    srcs_[np_++] = (const char*)(Ahi + (size_t)bm * K + k0_);                    \
    if (NPASS >= 2) srcs_[np_++] = (const char*)(Alo + (size_t)bm * K + k0_);    \
    srcs_[np_++] = (const char*)(Bhi + (size_t)bn * K + k0_);                    \
    if (NPASS == 3) srcs_[np_++] = (const char*)(Blo + (size_t)bn * K + k0_);    \
    _Pragma("unroll")                                                            \
    for (int p_ = 0; p_ < NPLANES; p_++) {                                       \
      char* dstp_ = smc + (s) * STGB + p_ * PLANE_B;                             \
      _Pragma("unroll")                                                          \
      for (int j_ = 0; j_ < 2; j_++) {                                           \
        int idx_ = j_ * 256 + tid;                                               \
        int row_ = idx_ >> 2, ch_ = idx_ & 3;                                    \
        unsigned sa_ = (unsigned)__cvta_generic_to_shared(dstp_ + row_ * LDPB + ch_ * 16); \
        const char* ga_ = srcs_[p_] + (size_t)row_ * K * 2 + ch_ * 16;           \
        asm volatile("cp.async.ca.shared.global [%0], [%1], 16;\n"               \
                     :: "r"(sa_), "l"(ga_));                                     \
      }                                                                          \
    }                                                                            \
    asm volatile("cp.async.commit_group;\n");                                    \
  } while (0)

  PREFETCH(0, 0);

  for (int kt = 0; kt < KT; kt++) {
    asm volatile("cp.async.wait_group 0;\n");
    __syncthreads();
    if (kt + 1 < KT) PREFETCH(kt + 1, (kt + 1) & 1);

    const char* Sahi = smc + (kt & 1) * STGB;
    const char* Salo = Sahi + PLANE_B;                         // NPASS>=2
    const char* Sbhi = Sahi + ((NPASS >= 2) ? 2 : 1) * PLANE_B;
    const char* Sblo = Sbhi + PLANE_B;                         // NPASS==3

    #pragma unroll
    for (int ks = 0; ks < 2; ks++) {
      int kb = ks * 32;   // 16 fp16 = 32 bytes
      unsigned bh_[2][4], bl_[2][4];
      #pragma unroll
      for (int pp = 0; pp < 2; pp++) {
        ldsm4(bh_[pp], Sbhi + (noff + pp * 16) * LDPB + kb + boff);
        if (NPASS == 3)
          ldsm4(bl_[pp], Sblo + (noff + pp * 16) * LDPB + kb + boff);
      }
      #pragma unroll
      for (int tm = 0; tm < 4; tm++) {
        unsigned ah[4], al[4];
        ldsm4(ah, Sahi + (moff + tm * 16) * LDPB + kb + aoff);
        if (NPASS >= 2)
          ldsm4(al, Salo + (moff + tm * 16) * LDPB + kb + aoff);
        #pragma unroll
        for (int tn = 0; tn < 4; tn++) {
          const unsigned* bhp = &bh_[tn >> 1][(tn & 1) * 2];
          mma_fp16(acc[tm][tn], ah, bhp);
          if (NPASS >= 2) mma_fp16(acc[tm][tn], al, bhp);
          if (NPASS == 3) {
            const unsigned* blp = &bl_[tn >> 1][(tn & 1) * 2];
            mma_fp16(acc[tm][tn], ah, blp);
          }
        }
      }
    }
    __syncthreads();
  }

  // ---- epilogue ----
  #pragma unroll
  for (int tm = 0; tm < 4; tm++) {
    int r0 = bm + moff + tm * 16 + g;
    int r1 = r0 + 8;
    #pragma unroll
    for (int tn = 0; tn < 4; tn++) {
      int c0 = bn + noff + tn * 8 + 2 * t4;   // even column
      float b0 = bias[c0], b1 = bias[c0 + 1];
      float v00 = acc[tm][tn][0] + b0;
      float v01 = acc[tm][tn][1] + b1;
      float v10 = acc[tm][tn][2] + b0;
      float v11 = acc[tm][tn][3] + b1;
      if (EPI == 1) {
        v00 = 0.5f * v00 * (1.f + erff(v00 * 0.70710678118654752f));
        v01 = 0.5f * v01 * (1.f + erff(v01 * 0.70710678118654752f));
        v10 = 0.5f * v10 * (1.f + erff(v10 * 0.70710678118654752f));
        v11 = 0.5f * v11 * (1.f + erff(v11 * 0.70710678118654752f));
        *(__half2*)(Chi + (size_t)r0 * N + c0) =
          __halves2half2(__float2half_rn(v00), __float2half_rn(v01));
        *(__half2*)(Chi + (size_t)r1 * N + c0) =
          __halves2half2(__float2half_rn(v10), __float2half_rn(v11));
      } else {
        if (EPI == 2) {
          float df = expf((float)c0 * (-0.017988946039015984f));
          float a0 = (float)(r0 & Lmask) * df;
          float a1 = (float)(r1 & Lmask) * df;
          v00 += sinf(a0); v01 += cosf(a0);
          v10 += sinf(a1); v11 += cosf(a1);
          *(__half2*)(Chh + (size_t)r0 * N + c0) =
            __halves2half2(__float2half_rn(v00), __float2half_rn(v01));
          *(__half2*)(Chh + (size_t)r1 * N + c0) =
            __halves2half2(__float2half_rn(v10), __float2half_rn(v11));
        }
        *(float2*)(Cf + (size_t)r0 * N + c0) = make_float2(v00, v01);
        *(float2*)(Cf + (size_t)r1 * N + c0) = make_float2(v10, v11);
      }
    }
  }
  #undef PREFETCH
}

// ------------------- host: layer key derivation ----------------------------
static void layer_key(int i, unsigned &k0, unsigned &k1)
{
  unsigned a = 0u, b = (unsigned)i;
  threefry2x32(0u, 42u, a, b);
  unsigned c = 0u, d = 1u;
  threefry2x32(a, b, c, d);
  k0 = c; k1 = d;
}

extern "C" void kernel_launch(void* const* d_in, const int* in_sizes, int n_in,
                              void* d_out, int out_size)
{
  const float* x     = (const float*)d_in[0];
  const float* emb_w = (const float*)d_in[1];
  const float* emb_b = (const float*)d_in[2];
  const float* ln1_s = (const float*)d_in[3];
  const float* ln1_b = (const float*)d_in[4];
  const float* w1    = (const float*)d_in[5];
  const float* b1    = (const float*)d_in[6];
  const float* w2    = (const float*)d_in[7];
  const float* b2    = (const float*)d_in[8];
  const float* ln2_s = (const float*)d_in[9];
  const float* ln2_b = (const float*)d_in[10];
  const float* out_w = (const float*)d_in[11];
  const float* out_b = (const float*)d_in[12];
  float* out = (float*)d_out;

  float *ph, *px, *pz;
  __half *phh, *pxhi, *pxlo, *pyhi;
  __half *pw1hi, *pw2hi, *powhi;
  __half *pexhi, *pexlo, *pewhi, *pewlo;
  cudaGetSymbolAddress((void**)&ph,   g_h);
  cudaGetSymbolAddress((void**)&phh,  g_hh);
  cudaGetSymbolAddress((void**)&px,   g_x);
  cudaGetSymbolAddress((void**)&pz,   g_z);
  cudaGetSymbolAddress((void**)&pxhi, g_xhi);
  cudaGetSymbolAddress((void**)&pxlo, g_xlo);
  cudaGetSymbolAddress((void**)&pyhi, g_yhi);
  cudaGetSymbolAddress((void**)&pw1hi, g_w1hi);
  cudaGetSymbolAddress((void**)&pw2hi, g_w2hi);
  cudaGetSymbolAddress((void**)&powhi, g_owhi);
  cudaGetSymbolAddress((void**)&pexhi, g_exhi);
  cudaGetSymbolAddress((void**)&pexlo, g_exlo);
  cudaGetSymbolAddress((void**)&pewhi, g_ewhi);
  cudaGetSymbolAddress((void**)&pewlo, g_ewlo);

  static int smem_set = 0;
  if (!smem_set) {
    cudaFuncSetAttribute(mma_gemm<2,3>, cudaFuncAttributeMaxDynamicSharedMemorySize, 2 * 4 * PLANE_B);
    cudaFuncSetAttribute(mma_gemm<1,1>, cudaFuncAttributeMaxDynamicSharedMemorySize, 2 * 2 * PLANE_B);
    cudaFuncSetAttribute(mma_gemm<0,1>, cudaFuncAttributeMaxDynamicSharedMemorySize, 2 * 2 * PLANE_B);
    cudaFuncSetAttribute(mma_gemm<0,2>, cudaFuncAttributeMaxDynamicSharedMemorySize, 2 * 3 * PLANE_B);
    cudaFuncSetAttribute(ctx_split_kernel, cudaFuncAttributeMaxDynamicSharedMemorySize, CTX_SMEM_FLOATS * 4);
    smem_set = 1;
  }
  const int ctx_smem = CTX_SMEM_FLOATS * 4;

  // weight/input fp16 conversions
  {
    int n1 = 3 * DFF * DD;
    whalf_kernel<<<(n1 + 255) / 256, 256>>>(w1, pw1hi, n1);
    whalf_kernel<<<(n1 + 255) / 256, 256>>>(w2, pw2hi, n1);
    int n2 = DD * DD;
    whalf_kernel<<<(n2 + 255) / 256, 256>>>(out_w, powhi, n2);
    int n3 = BB * L0 * 64;
    xsplit_kernel<<<(n3 + 255) / 256, 256>>>(x, pexhi, pexlo, n3);
    int n4 = DD * 64;
    xsplit_kernel<<<(n4 + 255) / 256, 256>>>(emb_w, pewhi, pewlo, n4);
  }

  // Embed (3-pass fp16 mma): h = x @ emb_w^T + emb_b + PE; also fp16 mirror
  {
    int M = BB * L0;
    mma_gemm<2,3><<<dim3(DD / 128, M / 128), 256, 2 * 4 * PLANE_B>>>(
        pexhi, pexlo, pewhi, pewlo, emb_b, ph, nullptr, phh, M, DD, 64, L0 - 1);
  }

  int L = L0;
  float* cur = ph;
  for (int i = 0; i < 3; i++) {
    int u = (i == 0) ? 45 : (i == 1) ? 40 : 35;
    int M = BB * L;
    unsigned k0, k1; layer_key(i, k0, k1);
    int total = L * u;
    idx_part<<<(total + 255) / 256, 256>>>(k0, k1, total, L - 1);
    prob_m_kernel<<<dim3(L / 8, 64), 256>>>(phh, L, u, 1.0f / (float)L);
    topk_kernel<<<64, 256>>>(L, u);
    int nsplit = L / 1024; if (nsplit < 1) nsplit = 1; if (nsplit > 4) nsplit = 4;
    ctx_split_kernel<<<dim3(nsplit, 64), 256, ctx_smem>>>(phh, L, u, L / nsplit);
    ctx_merge_kernel<<<64, 256>>>(L, u, nsplit);
    assemble_ln1_kernel<<<M, 128>>>(cur, px, pxhi,
                                    ln1_s + i * DD, ln1_b + i * DD, L, u);

    // FFN1: y = gelu(x @ w1^T + b1), 1-pass, fp16 out
    mma_gemm<1,1><<<dim3(DFF / 128, M / 128), 256, 2 * 2 * PLANE_B>>>(
        pxhi, nullptr, pw1hi + (size_t)i * DFF * DD, nullptr,
        b1 + i * DFF, nullptr, pyhi, nullptr, M, DFF, DD, 0);
    // FFN2: z = y @ w2^T + b2, 1-pass, fp32 out
    mma_gemm<0,1><<<dim3(DD / 128, M / 128), 256, 2 * 2 * PLANE_B>>>(
        pyhi, nullptr, pw2hi + (size_t)i * DD * DFF, nullptr,
        b2 + i * DD, pz, nullptr, nullptr, M, DD, DFF, 0);

    if (i < 2) {
      int L2 = L / 2;
      ln2_distil_kernel<<<BB * L2, 128>>>(px, pz, cur, phh,
                                          ln2_s + i * DD, ln2_b + i * DD, L2);
      L = L2;
    } else {
      ln2_split_kernel<<<M, 128>>>(px, pz, pxhi, pxlo,
                                   ln2_s + i * DD, ln2_b + i * DD);
    }
  }

  // Final projection: out = h @ out_w^T + out_b, 2-pass A (M=8192,N=512,K=512)
  {
    int M = BB * L;   // L = 1024
    mma_gemm<0,2><<<dim3(DD / 128, M / 128), 256, 2 * 3 * PLANE_B>>>(
        pxhi, pxlo, powhi, nullptr, out_b, out, nullptr, nullptr, M, DD, DD, 0);
  }
}

// round 11
// speedup vs baseline: 4.1546x; 1.0258x over previous
#include <cuda_runtime.h>
#include <cuda_fp16.h>
#include <math.h>
#include <stdint.h>

#define BB 8
#define DD 512
#define DFF 2048
#define L0 4096
#define UMAX 45
#define LN_EPS 1e-5f

// ------------------- scratch (device globals; no allocs) -------------------
__device__ __align__(16) float g_h  [BB*L0*DD];
__device__ __align__(16) __half g_hh [BB*L0*DD];   // fp16 mirror for attention reads
__device__ __align__(16) float g_x  [BB*L0*DD];
__device__ __align__(16) float g_z  [BB*L0*DD];
__device__ __align__(16) __half g_xhi[BB*L0*DD];
__device__ __align__(16) __half g_xlo[BB*L0*DD];
__device__ __align__(16) __half g_yhi[BB*L0*DFF];
__device__ __align__(16) __half g_w1hi[3*DFF*DD];
__device__ __align__(16) __half g_w2hi[3*DD*DFF];
__device__ __align__(16) __half g_owhi[DD*DD];
__device__ __align__(16) __half g_exhi[BB*L0*64];
__device__ __align__(16) __half g_exlo[BB*L0*64];
__device__ __align__(16) __half g_ewhi[DD*64];
__device__ __align__(16) __half g_ewlo[DD*64];
__device__ __align__(16) float g_M  [BB*8*L0];
__device__ __align__(16) int   g_idx[L0*UMAX];
__device__ __align__(16) int   g_top[BB*8*UMAX];
__device__ __align__(16) int   g_rowmap[BB*8*L0];
__device__ __align__(16) float g_ctx[BB*8*UMAX*64];
__device__ __align__(16) float g_qmean[BB*8*64];
// split-L ctx partials (max 8 splits)
__device__ __align__(16) float g_pm  [64*8*UMAX];
__device__ __align__(16) float g_ps  [64*8*UMAX];
__device__ __align__(16) float g_pctx[64*8*UMAX*64];
__device__ __align__(16) float g_pq  [64*8*64];

// ------------------- fp16 split helpers -------------------------------------
__device__ __forceinline__ void split_fp16(float v, __half &hi, __half &lo)
{
  hi = __float2half_rn(v);
  lo = __float2half_rn(v - __half2float(hi));
}

// ------------------- threefry2x32 (JAX-compatible) -------------------------
#define TF_R(x0,x1,r) { x0 += x1; x1 = ((x1 << (r)) | (x1 >> (32-(r)))); x1 ^= x0; }
__host__ __device__ inline void threefry2x32(unsigned ks0, unsigned ks1,
                                             unsigned &x0, unsigned &x1)
{
  unsigned ks2 = ks0 ^ ks1 ^ 0x1BD11BDAu;
  x0 += ks0; x1 += ks1;
  TF_R(x0,x1,13) TF_R(x0,x1,15) TF_R(x0,x1,26) TF_R(x0,x1,6)
  x0 += ks1; x1 += ks2 + 1u;
  TF_R(x0,x1,17) TF_R(x0,x1,29) TF_R(x0,x1,16) TF_R(x0,x1,24)
  x0 += ks2; x1 += ks0 + 2u;
  TF_R(x0,x1,13) TF_R(x0,x1,15) TF_R(x0,x1,26) TF_R(x0,x1,6)
  x0 += ks0; x1 += ks1 + 3u;
  TF_R(x0,x1,17) TF_R(x0,x1,29) TF_R(x0,x1,16) TF_R(x0,x1,24)
  x0 += ks1; x1 += ks2 + 4u;
  TF_R(x0,x1,13) TF_R(x0,x1,15) TF_R(x0,x1,26) TF_R(x0,x1,6)
  x0 += ks2; x1 += ks0 + 5u;
}

__global__ void idx_part(unsigned k0, unsigned k1, int total, int mask)
{
  int t = blockIdx.x * 256 + threadIdx.x;
  if (t >= total) return;
  unsigned x0 = 0u, x1 = (unsigned)t;
  threefry2x32(k0, k1, x0, x1);
  g_idx[t] = (int)((x0 ^ x1) & (unsigned)mask);
}

// ------------------- splits -------------------------------------------------
__global__ void whalf_kernel(const float* __restrict__ w,
                             __half* __restrict__ hi, int n)
{
  int i = blockIdx.x * 256 + threadIdx.x;
  if (i >= n) return;
  hi[i] = __float2half_rn(w[i]);
}

__global__ void xsplit_kernel(const float* __restrict__ w,
                              __half* __restrict__ hi, __half* __restrict__ lo, int n)
{
  int i = blockIdx.x * 256 + threadIdx.x;
  if (i >= n) return;
  __half h, l;
  split_fp16(w[i], h, l);
  hi[i] = h; lo[i] = l;
}

// ------------------- M = max_s qk - sum_s qk / L (fp16, MLP=2) --------------
__global__ __launch_bounds__(256) void prob_m_kernel(
    const __half* __restrict__ hh, int L, int u, float invL)
{
  int bh = blockIdx.y; int b = bh >> 3, hd = bh & 7;
  int warp = threadIdx.x >> 5, lane = threadIdx.x & 31;
  int l = blockIdx.x * 8 + warp;
  const __half* base = hh + (size_t)b * L * DD + hd * 64;
  float2 q2;
  {
    __half2 t = *(const __half2*)(base + (size_t)l * DD + 2 * lane);
    q2 = __half22float2(t);
  }

  int idxA = (lane < u)      ? g_idx[l * u + lane]      : 0;
  int idxB = (lane + 32 < u) ? g_idx[l * u + lane + 32] : 0;

  float mx = -INFINITY, sm = 0.f;
  int s = 0;
  for (; s + 1 < u; s += 2) {
    int kl0 = __shfl_sync(0xffffffffu, (s < 32) ? idxA : idxB, s & 31);
    int kl1 = __shfl_sync(0xffffffffu, (s + 1 < 32) ? idxA : idxB, (s + 1) & 31);
    __half2 kh0 = *(const __half2*)(base + (size_t)kl0 * DD + 2 * lane);
    __half2 kh1 = *(const __half2*)(base + (size_t)kl1 * DD + 2 * lane);
    float2 k0 = __half22float2(kh0);
    float2 k1 = __half22float2(kh1);
    float p0 = q2.x * k0.x + q2.y * k0.y;
    float p1 = q2.x * k1.x + q2.y * k1.y;
    #pragma unroll
    for (int o = 16; o; o >>= 1) {
      p0 += __shfl_xor_sync(0xffffffffu, p0, o);
      p1 += __shfl_xor_sync(0xffffffffu, p1, o);
    }
    mx = fmaxf(mx, p0); sm += p0;
    mx = fmaxf(mx, p1); sm += p1;
  }
  if (s < u) {
    int kl = __shfl_sync(0xffffffffu, (s < 32) ? idxA : idxB, s & 31);
    __half2 kh = *(const __half2*)(base + (size_t)kl * DD + 2 * lane);
    float2 k2 = __half22float2(kh);
    float p = q2.x * k2.x + q2.y * k2.y;
    #pragma unroll
    for (int o = 16; o; o >>= 1) p += __shfl_xor_sync(0xffffffffu, p, o);
    mx = fmaxf(mx, p); sm += p;
  }
  if (lane == 0) g_M[(size_t)bh * L + l] = mx - sm * invL;
}

// ------------------- top-k (512 threads, lower-index tiebreak) --------------
__global__ __launch_bounds__(512) void topk_kernel(int L, int u)
{
  __shared__ float sM[L0];
  __shared__ float sval[16];
  __shared__ int   sidx[16];
  int bh = blockIdx.x;
  int tid = threadIdx.x;
  int w = tid >> 5, lane = tid & 31;
  for (int l = tid; l < L; l += 512) {
    sM[l] = g_M[(size_t)bh * L + l];
    g_rowmap[(size_t)bh * L + l] = -1;
  }
  __syncthreads();
  for (int r = 0; r < u; r++) {
    float bv = -INFINITY; int bi = 0x7fffffff;
    for (int l = tid; l < L; l += 512) {
      float v = sM[l];
      if (v > bv || (v == bv && l < bi)) { bv = v; bi = l; }
    }
    #pragma unroll
    for (int o = 16; o; o >>= 1) {
      float v2 = __shfl_xor_sync(0xffffffffu, bv, o);
      int   i2 = __shfl_xor_sync(0xffffffffu, bi, o);
      if (v2 > bv || (v2 == bv && i2 < bi)) { bv = v2; bi = i2; }
    }
    if (lane == 0) { sval[w] = bv; sidx[w] = bi; }
    __syncthreads();
    if (tid == 0) {
      float Bv = sval[0]; int Bi = sidx[0];
      #pragma unroll
      for (int q = 1; q < 16; q++) {
        if (sval[q] > Bv || (sval[q] == Bv && sidx[q] < Bi)) {
          Bv = sval[q]; Bi = sidx[q];
        }
      }
      g_top[bh * u + r] = Bi;
      g_rowmap[(size_t)bh * L + Bi] = r;
      sM[Bi] = -INFINITY;
    }
    __syncthreads();
  }
}

// ------------------- split-L ctx (fp16 key reads) ---------------------------
// smem floats: qs 3072 | kt 4352 | sc 3072 | ctxs 3072 | rm/rs/rsc 144 | qred 256
#define CTX_SMEM_FLOATS (13568 + 144 + 256)
__global__ __launch_bounds__(256) void ctx_split_kernel(
    const __half* __restrict__ hh, int L, int u, int klen)
{
  extern __shared__ float dsm[];
  float* qs   = dsm;            // stride 64
  float* kt   = dsm + 3072;     // stride 68
  float* sc   = dsm + 7424;     // stride 64
  float* ctxs = dsm + 10496;    // stride 64
  float* rm   = dsm + 13568;
  float* rs   = dsm + 13616;
  float* rsc  = dsm + 13664;
  float* qred = dsm + 13712;    // [4][64]

  int split = blockIdx.x;
  int bh = blockIdx.y; int b = bh >> 3, hd = bh & 7;
  const __half* base = hh + (size_t)b * L * DD + hd * 64;
  int tid = threadIdx.x;
  int kbeg = split * klen;

  for (int e = tid; e < u * 64; e += 256) {
    int r = e >> 6, d = e & 63;
    qs[r * 64 + d] = __half2float(base[(size_t)g_top[bh * u + r] * DD + d]);
    ctxs[e] = 0.f;
  }
  if (tid < u) { rm[tid] = -INFINITY; rs[tid] = 0.f; }
  __syncthreads();

  const int j  = tid & 63;
  const int rg = tid >> 6;
  const int w  = tid >> 5, lane = tid & 31;
  float qacc = 0.f;

  for (int t0 = kbeg; t0 < kbeg + klen; t0 += 64) {
    for (int e = tid; e < 64 * 8; e += 256) {
      int r = e >> 3, c8 = e & 7;
      uint4 v = *(const uint4*)(base + (size_t)(t0 + r) * DD + c8 * 8);
      const __half2* hp = (const __half2*)&v;
      float* kr = kt + r * 68 + c8 * 8;
      #pragma unroll
      for (int q = 0; q < 4; q++) {
        float2 f = __half22float2(hp[q]);
        kr[2 * q] = f.x; kr[2 * q + 1] = f.y;
      }
    }
    __syncthreads();

    #pragma unroll
    for (int r = 0; r < 16; r++) qacc += kt[(rg + r * 4) * 68 + j];

    {
      float kreg[64];
      #pragma unroll
      for (int d = 0; d < 64; d++) kreg[d] = kt[j * 68 + d];
      for (int r = rg; r < u; r += 4) {
        const float* qr = qs + r * 64;
        float dot = 0.f;
        #pragma unroll
        for (int d = 0; d < 64; d++) dot += qr[d] * kreg[d];
        sc[r * 64 + j] = dot * 0.125f;
      }
    }
    __syncthreads();
    for (int r = w; r < u; r += 8) {
      float v0 = sc[r * 64 + lane], v1 = sc[r * 64 + lane + 32];
      float mx = fmaxf(v0, v1);
      #pragma unroll
      for (int o = 16; o; o >>= 1) mx = fmaxf(mx, __shfl_xor_sync(0xffffffffu, mx, o));
      float mold = rm[r];
      float mnew = fmaxf(mold, mx);
      float p0 = __expf(v0 - mnew), p1 = __expf(v1 - mnew);
      float ps = p0 + p1;
      #pragma unroll
      for (int o = 16; o; o >>= 1) ps += __shfl_xor_sync(0xffffffffu, ps, o);
      if (lane == 0) {
        float cold = __expf(mold - mnew);
        rsc[r] = cold;
        rs[r] = rs[r] * cold + ps;
        rm[r] = mnew;
      }
      sc[r * 64 + lane] = p0; sc[r * 64 + lane + 32] = p1;
    }
    __syncthreads();
    for (int r = rg; r < u; r += 4) {
      const float* pr = sc + r * 64;
      float a = 0.f;
      #pragma unroll
      for (int jj = 0; jj < 64; jj++) a += pr[jj] * kt[jj * 68 + j];
      ctxs[r * 64 + j] = ctxs[r * 64 + j] * rsc[r] + a;
    }
    __syncthreads();
  }

  // write partials
  qred[rg * 64 + j] = qacc;
  __syncthreads();
  if (rg == 0)
    g_pq[(bh * 8 + split) * 64 + j] =
      qred[j] + qred[64 + j] + qred[128 + j] + qred[192 + j];
  if (tid < u) {
    g_pm[(bh * 8 + split) * UMAX + tid] = rm[tid];
    g_ps[(bh * 8 + split) * UMAX + tid] = rs[tid];
  }
  for (int e = tid; e < u * 64; e += 256) {
    int r = e >> 6, d = e & 63;
    g_pctx[((size_t)((bh * 8 + split) * UMAX + r)) * 64 + d] = ctxs[r * 64 + d];
  }
}

// ------------------- merge split-L partials ---------------------------------
__global__ __launch_bounds__(256) void ctx_merge_kernel(int L, int u, int nsplit)
{
  int bh = blockIdx.x;
  int tid = threadIdx.x;
  if (tid < 64) {
    float q = 0.f;
    for (int s = 0; s < nsplit; s++) q += g_pq[(bh * 8 + s) * 64 + tid];
    g_qmean[bh * 64 + tid] = q / (float)L;
  }
  for (int e = tid; e < u * 64; e += 256) {
    int r = e >> 6, d = e & 63;
    float M0 = -INFINITY;
    for (int s = 0; s < nsplit; s++)
      M0 = fmaxf(M0, g_pm[(bh * 8 + s) * UMAX + r]);
    float num = 0.f, den = 0.f;
    for (int s = 0; s < nsplit; s++) {
      float c = __expf(g_pm[(bh * 8 + s) * UMAX + r] - M0);
      num += g_pctx[((size_t)((bh * 8 + s) * UMAX + r)) * 64 + d] * c;
      den += g_ps[(bh * 8 + s) * UMAX + r] * c;
    }
    g_ctx[((size_t)(bh * u + r)) * 64 + d] = num / den;
  }
}

// ------------------- block reduce helper (128 threads) ---------------------
__device__ __forceinline__ float blocksum128(float v, float* sred)
{
  #pragma unroll
  for (int o = 16; o; o >>= 1) v += __shfl_xor_sync(0xffffffffu, v, o);
  if ((threadIdx.x & 31) == 0) sred[threadIdx.x >> 5] = v;
  __syncthreads();
  float t = sred[0] + sred[1] + sred[2] + sred[3];
  __syncthreads();
  return t;
}

// ------------------- assemble attention out + residual + LN1 + fp16 hi -----
__global__ __launch_bounds__(128) void assemble_ln1_kernel(
    const float* __restrict__ hin, float* __restrict__ xout,
    __half* __restrict__ xhi,
    const float* __restrict__ gamma, const float* __restrict__ beta,
    int L, int u)
{
  __shared__ float sred[4];
  int row = blockIdx.x;
  int b = row / L, l = row - b * L;
  int tid = threadIdx.x;
  float v[4];
  #pragma unroll
  for (int i = 0; i < 4; i++) {
    int e = i * 128 + tid;
    int hh = e >> 6, dd = e & 63;
    int bh = b * 8 + hh;
    int r = g_rowmap[(size_t)bh * L + l];
    float nv = (r >= 0) ? g_ctx[((size_t)(bh * u + r)) * 64 + dd]
                        : g_qmean[bh * 64 + dd];
    v[i] = hin[(size_t)row * DD + e] + nv;
  }
  float s = blocksum128(v[0] + v[1] + v[2] + v[3], sred);
  float mu = s * (1.0f / 512.0f);
  float vs = 0.f;
  #pragma unroll
  for (int i = 0; i < 4; i++) { float d = v[i] - mu; vs += d * d; }
  vs = blocksum128(vs, sred);
  float rstd = rsqrtf(vs * (1.0f / 512.0f) + LN_EPS);
  #pragma unroll
  for (int i = 0; i < 4; i++) {
    int e = i * 128 + tid;
    float o = (v[i] - mu) * rstd * gamma[e] + beta[e];
    xout[(size_t)row * DD + e] = o;
    xhi[(size_t)row * DD + e] = __float2half_rn(o);
  }
}

// ------------------- fused residual+LN2+distil (layers 0,1) ----------------
__global__ __launch_bounds__(128) void ln2_distil_kernel(
    const float* __restrict__ xin, const float* __restrict__ zin,
    float* __restrict__ outp, __half* __restrict__ outh,
    const float* __restrict__ gamma, const float* __restrict__ beta, int L2)
{
  __shared__ float sred[4];
  int rowo = blockIdx.x;
  int b = rowo / L2, l2 = rowo - b * L2;
  size_t r0 = ((size_t)b * (2 * L2) + 2 * l2);
  int tid = threadIdx.x;
  float o01[4];
  #pragma unroll
  for (int half = 0; half < 2; half++) {
    size_t row = r0 + half;
    float v[4];
    #pragma unroll
    for (int i = 0; i < 4; i++) {
      int e = i * 128 + tid;
      v[i] = xin[row * DD + e] + zin[row * DD + e];
    }
    float s = blocksum128(v[0] + v[1] + v[2] + v[3], sred);
    float mu = s * (1.0f / 512.0f);
    float vs = 0.f;
    #pragma unroll
    for (int i = 0; i < 4; i++) { float d = v[i] - mu; vs += d * d; }
    vs = blocksum128(vs, sred);
    float rstd = rsqrtf(vs * (1.0f / 512.0f) + LN_EPS);
    #pragma unroll
    for (int i = 0; i < 4; i++) {
      int e = i * 128 + tid;
      float o = (v[i] - mu) * rstd * gamma[e] + beta[e];
      if (half == 0) o01[i] = o; else o01[i] = 0.5f * (o01[i] + o);
    }
  }
  #pragma unroll
  for (int i = 0; i < 4; i++) {
    int e = i * 128 + tid;
    outp[(size_t)rowo * DD + e] = o01[i];
    outh[(size_t)rowo * DD + e] = __float2half_rn(o01[i]);
  }
}

// ------------------- residual + LN2 -> fp16 split only (last layer) --------
__global__ __launch_bounds__(128) void ln2_split_kernel(
    const float* __restrict__ xin, const float* __restrict__ zin,
    __half* __restrict__ ohi, __half* __restrict__ olo,
    const float* __restrict__ gamma, const float* __restrict__ beta)
{
  __shared__ float sred[4];
  size_t row = blockIdx.x;
  int tid = threadIdx.x;
  float v[4];
  #pragma unroll
  for (int i = 0; i < 4; i++) {
    int e = i * 128 + tid;
    v[i] = xin[row * DD + e] + zin[row * DD + e];
  }
  float s = blocksum128(v[0] + v[1] + v[2] + v[3], sred);
  float mu = s * (1.0f / 512.0f);
  float vs = 0.f;
  #pragma unroll
  for (int i = 0; i < 4; i++) { float d = v[i] - mu; vs += d * d; }
  vs = blocksum128(vs, sred);
  float rstd = rsqrtf(vs * (1.0f / 512.0f) + LN_EPS);
  #pragma unroll
  for (int i = 0; i < 4; i++) {
    int e = i * 128 + tid;
    float o = (v[i] - mu) * rstd * gamma[e] + beta[e];
    __half h16, l16;
    split_fp16(o, h16, l16);
    ohi[row * DD + e] = h16;
    olo[row * DD + e] = l16;
  }
}

// ------------------- fp16 tensor-core GEMM (1/2/3-pass) ---------------------
#define KC 32                     // k elems per stage
#define LDPB 80                   // padded row stride in BYTES (40 fp16)
#define PLANE_B (128*LDPB)        // 10240 bytes per plane

__device__ __forceinline__ void mma_fp16(float* c, const unsigned* a, const unsigned* b)
{
  asm volatile(
    "mma.sync.aligned.m16n8k16.row.col.f32.f16.f16.f32 "
    "{%0,%1,%2,%3},{%4,%5,%6,%7},{%8,%9},{%0,%1,%2,%3};\n"
    : "+f"(c[0]), "+f"(c[1]), "+f"(c[2]), "+f"(c[3])
    : "r"(a[0]), "r"(a[1]), "r"(a[2]), "r"(a[3]), "r"(b[0]), "r"(b[1]));
}

__device__ __forceinline__ void ldsm4(unsigned* r, const char* sptr)
{
  unsigned addr = (unsigned)__cvta_generic_to_shared(sptr);
  asm volatile("ldmatrix.sync.aligned.m8n8.x4.shared.b16 {%0,%1,%2,%3}, [%4];\n"
    : "=r"(r[0]), "=r"(r[1]), "=r"(r[2]), "=r"(r[3]) : "r"(addr));
}

// EPI 0: Cf = acc + bias (fp32)
// EPI 1: Chi = fp16(gelu(acc + bias))
// EPI 2: Cf = acc + bias + PE (fp32) AND Chh = fp16 copy
// NPASS 1: A_hi x B_hi | NPASS 2: (A_hi+A_lo) x B_hi | NPASS 3: + A_hi x B_lo
template<int EPI, int NPASS>
__global__ __launch_bounds__(256, 2) void mma_gemm(
    const __half* __restrict__ Ahi, const __half* __restrict__ Alo,
    const __half* __restrict__ Bhi, const __half* __restrict__ Blo,
    const float* __restrict__ bias,
    float* __restrict__ Cf, __half* __restrict__ Chi, __half* __restrict__ Chh,
    int M, int N, int K, int Lmask)
{
  constexpr int NPLANES = (NPASS == 3) ? 4 : (NPASS + 1);
  const int STGB = NPLANES * PLANE_B;
  extern __shared__ char smc[];
  const int tid = threadIdx.x;
  const int bm = blockIdx.y * 128, bn = blockIdx.x * 128;
  const int lane = tid & 31;
  const int g = lane >> 2, t4 = lane & 3;
  const int warp = tid >> 5;
  const int wm = warp >> 2, wn = warp & 3;      // warps 2(m) x 4(n)
  const int moff = wm * 64, noff = wn * 32;

  const int aoff = (lane & 15) * LDPB + ((lane & 16) ? 16 : 0);
  const int boff = ((lane & 7) + ((lane & 16) ? 8 : 0)) * LDPB + ((lane & 8) ? 16 : 0);

  float acc[4][4][4];
  #pragma unroll
  for (int i = 0; i < 4; i++)
    #pragma unroll
    for (int j = 0; j < 4; j++)
      #pragma unroll
      for (int q = 0; q < 4; q++) acc[i][j][q] = 0.f;

  const int KT = K / KC;

  #define PREFETCH(kt, s) do {                                                   \
    int k0_ = (kt) * KC;                                                         \
    const char* srcs_[NPLANES];                                                  \
    int np_ = 0;                                                                 \
    srcs_[np_++] = (const char*)(Ahi + (size_t)bm * K + k0_);                    \
    if (NPASS >= 2) srcs_[np_++] = (const char*)(Alo + (size_t)bm * K + k0_);    \
    srcs_[np_++] = (const char*)(Bhi + (size_t)bn * K + k0_);                    \
    if (NPASS == 3) srcs_[np_++] = (const char*)(Blo + (size_t)bn * K + k0_);    \
    _Pragma("unroll")                                                            \
    for (int p_ = 0; p_ < NPLANES; p_++) {                                       \
      char* dstp_ = smc + (s) * STGB + p_ * PLANE_B;                             \
      _Pragma("unroll")                                                          \
      for (int j_ = 0; j_ < 2; j_++) {                                           \
        int idx_ = j_ * 256 + tid;                                               \
        int row_ = idx_ >> 2, ch_ = idx_ & 3;                                    \
        unsigned sa_ = (unsigned)__cvta_generic_to_shared(dstp_ + row_ * LDPB + ch_ * 16); \
        const char* ga_ = srcs_[p_] + (size_t)row_ * K * 2 + ch_ * 16;           \
        asm volatile("cp.async.ca.shared.global [%0], [%1], 16;\n"               \
                     :: "r"(sa_), "l"(ga_));                                     \
      }                                                                          \
    }                                                                            \
    asm volatile("cp.async.commit_group;\n");                                    \
  } while (0)

  PREFETCH(0, 0);

  for (int kt = 0; kt < KT; kt++) {
    asm volatile("cp.async.wait_group 0;\n");
    __syncthreads();
    if (kt + 1 < KT) PREFETCH(kt + 1, (kt + 1) & 1);

    const char* Sahi = smc + (kt & 1) * STGB;
    const char* Salo = Sahi + PLANE_B;                         // NPASS>=2
    const char* Sbhi = Sahi + ((NPASS >= 2) ? 2 : 1) * PLANE_B;
    const char* Sblo = Sbhi + PLANE_B;                         // NPASS==3

    #pragma unroll
    for (int ks = 0; ks < 2; ks++) {
      int kb = ks * 32;   // 16 fp16 = 32 bytes
      unsigned bh_[2][4], bl_[2][4];
      #pragma unroll
      for (int pp = 0; pp < 2; pp++) {
        ldsm4(bh_[pp], Sbhi + (noff + pp * 16) * LDPB + kb + boff);
        if (NPASS == 3)
          ldsm4(bl_[pp], Sblo + (noff + pp * 16) * LDPB + kb + boff);
      }
      #pragma unroll
      for (int tm = 0; tm < 4; tm++) {
        unsigned ah[4], al[4];
        ldsm4(ah, Sahi + (moff + tm * 16) * LDPB + kb + aoff);
        if (NPASS >= 2)
          ldsm4(al, Salo + (moff + tm * 16) * LDPB + kb + aoff);
        #pragma unroll
        for (int tn = 0; tn < 4; tn++) {
          const unsigned* bhp = &bh_[tn >> 1][(tn & 1) * 2];
          mma_fp16(acc[tm][tn], ah, bhp);
          if (NPASS >= 2) mma_fp16(acc[tm][tn], al, bhp);
          if (NPASS == 3) {
            const unsigned* blp = &bl_[tn >> 1][(tn & 1) * 2];
            mma_fp16(acc[tm][tn], ah, blp);
          }
        }
      }
    }
    __syncthreads();
  }

  // ---- epilogue ----
  #pragma unroll
  for (int tm = 0; tm < 4; tm++) {
    int r0 = bm + moff + tm * 16 + g;
    int r1 = r0 + 8;
    #pragma unroll
    for (int tn = 0; tn < 4; tn++) {
      int c0 = bn + noff + tn * 8 + 2 * t4;   // even column
      float b0 = bias[c0], b1 = bias[c0 + 1];
      float v00 = acc[tm][tn][0] + b0;
      float v01 = acc[tm][tn][1] + b1;
      float v10 = acc[tm][tn][2] + b0;
      float v11 = acc[tm][tn][3] + b1;
      if (EPI == 1) {
        v00 = 0.5f * v00 * (1.f + erff(v00 * 0.70710678118654752f));
        v01 = 0.5f * v01 * (1.f + erff(v01 * 0.70710678118654752f));
        v10 = 0.5f * v10 * (1.f + erff(v10 * 0.70710678118654752f));
        v11 = 0.5f * v11 * (1.f + erff(v11 * 0.70710678118654752f));
        *(__half2*)(Chi + (size_t)r0 * N + c0) =
          __halves2half2(__float2half_rn(v00), __float2half_rn(v01));
        *(__half2*)(Chi + (size_t)r1 * N + c0) =
          __halves2half2(__float2half_rn(v10), __float2half_rn(v11));
      } else {
        if (EPI == 2) {
          float df = expf((float)c0 * (-0.017988946039015984f));
          float a0 = (float)(r0 & Lmask) * df;
          float a1 = (float)(r1 & Lmask) * df;
          v00 += sinf(a0); v01 += cosf(a0);
          v10 += sinf(a1); v11 += cosf(a1);
          *(__half2*)(Chh + (size_t)r0 * N + c0) =
            __halves2half2(__float2half_rn(v00), __float2half_rn(v01));
          *(__half2*)(Chh + (size_t)r1 * N + c0) =
            __halves2half2(__float2half_rn(v10), __float2half_rn(v11));
        }
        *(float2*)(Cf + (size_t)r0 * N + c0) = make_float2(v00, v01);
        *(float2*)(Cf + (size_t)r1 * N + c0) = make_float2(v10, v11);
      }
    }
  }
  #undef PREFETCH
}

// ------------------- host: layer key derivation ----------------------------
static void layer_key(int i, unsigned &k0, unsigned &k1)
{
  unsigned a = 0u, b = (unsigned)i;
  threefry2x32(0u, 42u, a, b);
  unsigned c = 0u, d = 1u;
  threefry2x32(a, b, c, d);
  k0 = c; k1 = d;
}

extern "C" void kernel_launch(void* const* d_in, const int* in_sizes, int n_in,
                              void* d_out, int out_size)
{
  const float* x     = (const float*)d_in[0];
  const float* emb_w = (const float*)d_in[1];
  const float* emb_b = (const float*)d_in[2];
  const float* ln1_s = (const float*)d_in[3];
  const float* ln1_b = (const float*)d_in[4];
  const float* w1    = (const float*)d_in[5];
  const float* b1    = (const float*)d_in[6];
  const float* w2    = (const float*)d_in[7];
  const float* b2    = (const float*)d_in[8];
  const float* ln2_s = (const float*)d_in[9];
  const float* ln2_b = (const float*)d_in[10];
  const float* out_w = (const float*)d_in[11];
  const float* out_b = (const float*)d_in[12];
  float* out = (float*)d_out;

  float *ph, *px, *pz;
  __half *phh, *pxhi, *pxlo, *pyhi;
  __half *pw1hi, *pw2hi, *powhi;
  __half *pexhi, *pexlo, *pewhi, *pewlo;
  cudaGetSymbolAddress((void**)&ph,   g_h);
  cudaGetSymbolAddress((void**)&phh,  g_hh);
  cudaGetSymbolAddress((void**)&px,   g_x);
  cudaGetSymbolAddress((void**)&pz,   g_z);
  cudaGetSymbolAddress((void**)&pxhi, g_xhi);
  cudaGetSymbolAddress((void**)&pxlo, g_xlo);
  cudaGetSymbolAddress((void**)&pyhi, g_yhi);
  cudaGetSymbolAddress((void**)&pw1hi, g_w1hi);
  cudaGetSymbolAddress((void**)&pw2hi, g_w2hi);
  cudaGetSymbolAddress((void**)&powhi, g_owhi);
  cudaGetSymbolAddress((void**)&pexhi, g_exhi);
  cudaGetSymbolAddress((void**)&pexlo, g_exlo);
  cudaGetSymbolAddress((void**)&pewhi, g_ewhi);
  cudaGetSymbolAddress((void**)&pewlo, g_ewlo);

  static int smem_set = 0;
  if (!smem_set) {
    cudaFuncSetAttribute(mma_gemm<2,3>, cudaFuncAttributeMaxDynamicSharedMemorySize, 2 * 4 * PLANE_B);
    cudaFuncSetAttribute(mma_gemm<1,1>, cudaFuncAttributeMaxDynamicSharedMemorySize, 2 * 2 * PLANE_B);
    cudaFuncSetAttribute(mma_gemm<0,1>, cudaFuncAttributeMaxDynamicSharedMemorySize, 2 * 2 * PLANE_B);
    cudaFuncSetAttribute(mma_gemm<0,2>, cudaFuncAttributeMaxDynamicSharedMemorySize, 2 * 3 * PLANE_B);
    cudaFuncSetAttribute(ctx_split_kernel, cudaFuncAttributeMaxDynamicSharedMemorySize, CTX_SMEM_FLOATS * 4);
    smem_set = 1;
  }
  const int ctx_smem = CTX_SMEM_FLOATS * 4;

  // input conversions first (embed deps only) — places prob_m at launch #5
  {
    int n3 = BB * L0 * 64;
    xsplit_kernel<<<(n3 + 255) / 256, 256>>>(x, pexhi, pexlo, n3);      // #1
    int n4 = DD * 64;
    xsplit_kernel<<<(n4 + 255) / 256, 256>>>(emb_w, pewhi, pewlo, n4);  // #2
  }

  // Embed (3-pass fp16 mma): h = x @ emb_w^T + emb_b + PE; also fp16 mirror
  {
    int M = BB * L0;
    mma_gemm<2,3><<<dim3(DD / 128, M / 128), 256, 2 * 4 * PLANE_B>>>(   // #3
        pexhi, pexlo, pewhi, pewlo, emb_b, ph, nullptr, phh, M, DD, 64, L0 - 1);
  }

  int L = L0;
  float* cur = ph;
  for (int i = 0; i < 3; i++) {
    int u = (i == 0) ? 45 : (i == 1) ? 40 : 35;
    int M = BB * L;
    unsigned k0, k1; layer_key(i, k0, k1);
    int total = L * u;
    idx_part<<<(total + 255) / 256, 256>>>(k0, k1, total, L - 1);       // #4
    prob_m_kernel<<<dim3(L / 8, 64), 256>>>(phh, L, u, 1.0f / (float)L);// #5 (i=0)
    topk_kernel<<<64, 512>>>(L, u);
    int nsplit = L / 512; if (nsplit < 1) nsplit = 1; if (nsplit > 8) nsplit = 8;
    ctx_split_kernel<<<dim3(nsplit, 64), 256, ctx_smem>>>(phh, L, u, L / nsplit);
    ctx_merge_kernel<<<64, 256>>>(L, u, nsplit);
    assemble_ln1_kernel<<<M, 128>>>(cur, px, pxhi,
                                    ln1_s + i * DD, ln1_b + i * DD, L, u);

    if (i == 0) {
      // weight conversions (first use is FFN1 below)
      int n1 = 3 * DFF * DD;
      whalf_kernel<<<(n1 + 255) / 256, 256>>>(w1, pw1hi, n1);
      whalf_kernel<<<(n1 + 255) / 256, 256>>>(w2, pw2hi, n1);
      int n2 = DD * DD;
      whalf_kernel<<<(n2 + 255) / 256, 256>>>(out_w, powhi, n2);
    }

    // FFN1: y = gelu(x @ w1^T + b1), 1-pass, fp16 out
    mma_gemm<1,1><<<dim3(DFF / 128, M / 128), 256, 2 * 2 * PLANE_B>>>(
        pxhi, nullptr, pw1hi + (size_t)i * DFF * DD, nullptr,
        b1 + i * DFF, nullptr, pyhi, nullptr, M, DFF, DD, 0);
    // FFN2: z = y @ w2^T + b2, 1-pass, fp32 out
    mma_gemm<0,1><<<dim3(DD / 128, M / 128), 256, 2 * 2 * PLANE_B>>>(
        pyhi, nullptr, pw2hi + (size_t)i * DD * DFF, nullptr,
        b2 + i * DD, pz, nullptr, nullptr, M, DD, DFF, 0);

    if (i < 2) {
      int L2 = L / 2;
      ln2_distil_kernel<<<BB * L2, 128>>>(px, pz, cur, phh,
                                          ln2_s + i * DD, ln2_b + i * DD, L2);
      L = L2;
    } else {
      ln2_split_kernel<<<M, 128>>>(px, pz, pxhi, pxlo,
                                   ln2_s + i * DD, ln2_b + i * DD);
    }
  }

  // Final projection: out = h @ out_w^T + out_b, 2-pass A (M=8192,N=512,K=512)
  {
    int M = BB * L;   // L = 1024
    mma_gemm<0,2><<<dim3(DD / 128, M / 128), 256, 2 * 3 * PLANE_B>>>(
        pxhi, pxlo, powhi, nullptr, out_b, out, nullptr, nullptr, M, DD, DD, 0);
  }
}

// round 12
// speedup vs baseline: 4.1978x; 1.0104x over previous
#include <cuda_runtime.h>
#include <cuda_fp16.h>
#include <math.h>
#include <stdint.h>

#define BB 8
#define DD 512
#define DFF 2048
#define L0 4096
#define UMAX 45
#define LN_EPS 1e-5f

// ------------------- scratch (device globals; no allocs) -------------------
__device__ __align__(16) float g_h  [BB*L0*DD];
__device__ __align__(16) __half g_hh [BB*L0*DD];   // fp16 mirror for attention reads
__device__ __align__(16) float g_x  [BB*L0*DD];
__device__ __align__(16) float g_z  [BB*L0*DD];
__device__ __align__(16) __half g_xhi[BB*L0*DD];
__device__ __align__(16) __half g_xlo[BB*L0*DD];
__device__ __align__(16) __half g_yhi[BB*L0*DFF];
__device__ __align__(16) __half g_w1hi[3*DFF*DD];
__device__ __align__(16) __half g_w2hi[3*DD*DFF];
__device__ __align__(16) __half g_owhi[DD*DD];
__device__ __align__(16) __half g_exhi[BB*L0*64];
__device__ __align__(16) __half g_exlo[BB*L0*64];
__device__ __align__(16) __half g_ewhi[DD*64];
__device__ __align__(16) __half g_ewlo[DD*64];
__device__ __align__(16) float g_M  [BB*8*L0];
__device__ __align__(16) int   g_idx[L0*UMAX];
__device__ __align__(16) int   g_top[BB*8*UMAX];
__device__ __align__(16) int   g_rowmap[BB*8*L0];
__device__ __align__(16) float g_ctx[BB*8*UMAX*64];
__device__ __align__(16) float g_qmean[BB*8*64];
// split-L ctx partials (max 8 splits)
__device__ __align__(16) float g_pm  [64*8*UMAX];
__device__ __align__(16) float g_ps  [64*8*UMAX];
__device__ __align__(16) float g_pctx[64*8*UMAX*64];
__device__ __align__(16) float g_pq  [64*8*64];

// ------------------- fp16 split helpers -------------------------------------
__device__ __forceinline__ void split_fp16(float v, __half &hi, __half &lo)
{
  hi = __float2half_rn(v);
  lo = __float2half_rn(v - __half2float(hi));
}

// ------------------- threefry2x32 (JAX-compatible) -------------------------
#define TF_R(x0,x1,r) { x0 += x1; x1 = ((x1 << (r)) | (x1 >> (32-(r)))); x1 ^= x0; }
__host__ __device__ inline void threefry2x32(unsigned ks0, unsigned ks1,
                                             unsigned &x0, unsigned &x1)
{
  unsigned ks2 = ks0 ^ ks1 ^ 0x1BD11BDAu;
  x0 += ks0; x1 += ks1;
  TF_R(x0,x1,13) TF_R(x0,x1,15) TF_R(x0,x1,26) TF_R(x0,x1,6)
  x0 += ks1; x1 += ks2 + 1u;
  TF_R(x0,x1,17) TF_R(x0,x1,29) TF_R(x0,x1,16) TF_R(x0,x1,24)
  x0 += ks2; x1 += ks0 + 2u;
  TF_R(x0,x1,13) TF_R(x0,x1,15) TF_R(x0,x1,26) TF_R(x0,x1,6)
  x0 += ks0; x1 += ks1 + 3u;
  TF_R(x0,x1,17) TF_R(x0,x1,29) TF_R(x0,x1,16) TF_R(x0,x1,24)
  x0 += ks1; x1 += ks2 + 4u;
  TF_R(x0,x1,13) TF_R(x0,x1,15) TF_R(x0,x1,26) TF_R(x0,x1,6)
  x0 += ks2; x1 += ks0 + 5u;
}

__global__ void idx_part(unsigned k0, unsigned k1, int total, int mask)
{
  int t = blockIdx.x * 256 + threadIdx.x;
  if (t >= total) return;
  unsigned x0 = 0u, x1 = (unsigned)t;
  threefry2x32(k0, k1, x0, x1);
  g_idx[t] = (int)((x0 ^ x1) & (unsigned)mask);
}

// ------------------- splits -------------------------------------------------
__global__ void whalf_kernel(const float* __restrict__ w,
                             __half* __restrict__ hi, int n)
{
  int i = blockIdx.x * 256 + threadIdx.x;
  if (i >= n) return;
  hi[i] = __float2half_rn(w[i]);
}

__global__ void xsplit_kernel(const float* __restrict__ w,
                              __half* __restrict__ hi, __half* __restrict__ lo, int n)
{
  int i = blockIdx.x * 256 + threadIdx.x;
  if (i >= n) return;
  __half h, l;
  split_fp16(w[i], h, l);
  hi[i] = h; lo[i] = l;
}

// ------------------- M = max_s qk - sum_s qk / L (fp16, MLP=4) --------------
__global__ __launch_bounds__(256) void prob_m_kernel(
    const __half* __restrict__ hh, int L, int u, float invL)
{
  int bh = blockIdx.y; int b = bh >> 3, hd = bh & 7;
  int warp = threadIdx.x >> 5, lane = threadIdx.x & 31;
  int l = blockIdx.x * 8 + warp;
  const __half* base = hh + (size_t)b * L * DD + hd * 64;
  float2 q2;
  {
    __half2 t = *(const __half2*)(base + (size_t)l * DD + 2 * lane);
    q2 = __half22float2(t);
  }

  int idxA = (lane < u)      ? g_idx[l * u + lane]      : 0;
  int idxB = (lane + 32 < u) ? g_idx[l * u + lane + 32] : 0;

  float mx = -INFINITY, sm = 0.f;
  int s = 0;
  for (; s + 3 < u; s += 4) {
    int kls[4];
    #pragma unroll
    for (int q = 0; q < 4; q++)
      kls[q] = __shfl_sync(0xffffffffu, ((s + q) < 32) ? idxA : idxB, (s + q) & 31);
    float p[4];
    #pragma unroll
    for (int q = 0; q < 4; q++) {
      __half2 kh = *(const __half2*)(base + (size_t)kls[q] * DD + 2 * lane);
      float2 k2 = __half22float2(kh);
      p[q] = q2.x * k2.x + q2.y * k2.y;
    }
    #pragma unroll
    for (int o = 16; o; o >>= 1) {
      #pragma unroll
      for (int q = 0; q < 4; q++)
        p[q] += __shfl_xor_sync(0xffffffffu, p[q], o);
    }
    #pragma unroll
    for (int q = 0; q < 4; q++) { mx = fmaxf(mx, p[q]); sm += p[q]; }
  }
  for (; s < u; s++) {
    int kl = __shfl_sync(0xffffffffu, (s < 32) ? idxA : idxB, s & 31);
    __half2 kh = *(const __half2*)(base + (size_t)kl * DD + 2 * lane);
    float2 k2 = __half22float2(kh);
    float p = q2.x * k2.x + q2.y * k2.y;
    #pragma unroll
    for (int o = 16; o; o >>= 1) p += __shfl_xor_sync(0xffffffffu, p, o);
    mx = fmaxf(mx, p); sm += p;
  }
  if (lane == 0) g_M[(size_t)bh * L + l] = mx - sm * invL;
}

// ------------------- top-k: tournament argmax (exact, lower-index ties) ----
// groups of 64; per round: argmax over group maxima + single-group rescan.
__global__ __launch_bounds__(256) void topk_kernel(int L, int u)
{
  __shared__ float sM[L0];
  __shared__ float gmax[64];
  __shared__ int   gidx[64];
  int bh = blockIdx.x;
  int tid = threadIdx.x;
  int ngroups = L >> 6;
  for (int l = tid; l < L; l += 256) {
    sM[l] = g_M[(size_t)bh * L + l];
    g_rowmap[(size_t)bh * L + l] = -1;
  }
  __syncthreads();
  // initial group maxima: thread g scans group g (strict > keeps lowest index)
  if (tid < ngroups) {
    float bv = -INFINITY; int bi = tid * 64;
    #pragma unroll 8
    for (int j = 0; j < 64; j++) {
      float v = sM[tid * 64 + j];
      if (v > bv) { bv = v; bi = tid * 64 + j; }
    }
    gmax[tid] = bv; gidx[tid] = bi;
  }
  __syncthreads();

  if (tid < 32) {
    for (int r = 0; r < u; r++) {
      // argmax over group maxima (<=64): 2 per lane
      float bv = -INFINITY; int bi = 0x7fffffff;
      for (int g = tid; g < ngroups; g += 32) {
        float v = gmax[g]; int i = gidx[g];
        if (v > bv || (v == bv && i < bi)) { bv = v; bi = i; }
      }
      #pragma unroll
      for (int o = 16; o; o >>= 1) {
        float v2 = __shfl_xor_sync(0xffffffffu, bv, o);
        int   i2 = __shfl_xor_sync(0xffffffffu, bi, o);
        if (v2 > bv || (v2 == bv && i2 < bi)) { bv = v2; bi = i2; }
      }
      int sel = __shfl_sync(0xffffffffu, bi, 0);
      if (tid == 0) {
        g_top[bh * u + r] = sel;
        g_rowmap[(size_t)bh * L + sel] = r;
        sM[sel] = -INFINITY;
      }
      __syncwarp();
      // rescan the affected group (64 elems, 2 per lane)
      int gs = sel >> 6;
      int e0 = gs * 64 + tid, e1 = e0 + 32;
      float v0 = sM[e0], v1 = sM[e1];
      float nv; int ni;
      if (v0 >= v1) { nv = v0; ni = e0; } else { nv = v1; ni = e1; }
      if (v0 == v1) { ni = e0; }   // lower index on tie
      #pragma unroll
      for (int o = 16; o; o >>= 1) {
        float v2 = __shfl_xor_sync(0xffffffffu, nv, o);
        int   i2 = __shfl_xor_sync(0xffffffffu, ni, o);
        if (v2 > nv || (v2 == nv && i2 < ni)) { nv = v2; ni = i2; }
      }
      if (tid == 0) { gmax[gs] = nv; gidx[gs] = ni; }
      __syncwarp();
    }
  }
}

// ------------------- split-L ctx (fp16 key reads) ---------------------------
// smem floats: qs 3072 | kt 4352 | sc 3072 | ctxs 3072 | rm/rs/rsc 144 | qred 256
#define CTX_SMEM_FLOATS (13568 + 144 + 256)
__global__ __launch_bounds__(256) void ctx_split_kernel(
    const __half* __restrict__ hh, int L, int u, int klen)
{
  extern __shared__ float dsm[];
  float* qs   = dsm;            // stride 64
  float* kt   = dsm + 3072;     // stride 68
  float* sc   = dsm + 7424;     // stride 64
  float* ctxs = dsm + 10496;    // stride 64
  float* rm   = dsm + 13568;
  float* rs   = dsm + 13616;
  float* rsc  = dsm + 13664;
  float* qred = dsm + 13712;    // [4][64]

  int split = blockIdx.x;
  int bh = blockIdx.y; int b = bh >> 3, hd = bh & 7;
  const __half* base = hh + (size_t)b * L * DD + hd * 64;
  int tid = threadIdx.x;
  int kbeg = split * klen;

  for (int e = tid; e < u * 64; e += 256) {
    int r = e >> 6, d = e & 63;
    qs[r * 64 + d] = __half2float(base[(size_t)g_top[bh * u + r] * DD + d]);
    ctxs[e] = 0.f;
  }
  if (tid < u) { rm[tid] = -INFINITY; rs[tid] = 0.f; }
  __syncthreads();

  const int j  = tid & 63;
  const int rg = tid >> 6;
  const int w  = tid >> 5, lane = tid & 31;
  float qacc = 0.f;

  for (int t0 = kbeg; t0 < kbeg + klen; t0 += 64) {
    for (int e = tid; e < 64 * 8; e += 256) {
      int r = e >> 3, c8 = e & 7;
      uint4 v = *(const uint4*)(base + (size_t)(t0 + r) * DD + c8 * 8);
      const __half2* hp = (const __half2*)&v;
      float* kr = kt + r * 68 + c8 * 8;
      #pragma unroll
      for (int q = 0; q < 4; q++) {
        float2 f = __half22float2(hp[q]);
        kr[2 * q] = f.x; kr[2 * q + 1] = f.y;
      }
    }
    __syncthreads();

    #pragma unroll
    for (int r = 0; r < 16; r++) qacc += kt[(rg + r * 4) * 68 + j];

    {
      float kreg[64];
      #pragma unroll
      for (int d = 0; d < 64; d++) kreg[d] = kt[j * 68 + d];
      for (int r = rg; r < u; r += 4) {
        const float* qr = qs + r * 64;
        float dot = 0.f;
        #pragma unroll
        for (int d = 0; d < 64; d++) dot += qr[d] * kreg[d];
        sc[r * 64 + j] = dot * 0.125f;
      }
    }
    __syncthreads();
    for (int r = w; r < u; r += 8) {
      float v0 = sc[r * 64 + lane], v1 = sc[r * 64 + lane + 32];
      float mx = fmaxf(v0, v1);
      #pragma unroll
      for (int o = 16; o; o >>= 1) mx = fmaxf(mx, __shfl_xor_sync(0xffffffffu, mx, o));
      float mold = rm[r];
      float mnew = fmaxf(mold, mx);
      float p0 = __expf(v0 - mnew), p1 = __expf(v1 - mnew);
      float ps = p0 + p1;
      #pragma unroll
      for (int o = 16; o; o >>= 1) ps += __shfl_xor_sync(0xffffffffu, ps, o);
      if (lane == 0) {
        float cold = __expf(mold - mnew);
        rsc[r] = cold;
        rs[r] = rs[r] * cold + ps;
        rm[r] = mnew;
      }
      sc[r * 64 + lane] = p0; sc[r * 64 + lane + 32] = p1;
    }
    __syncthreads();
    for (int r = rg; r < u; r += 4) {
      const float* pr = sc + r * 64;
      float a = 0.f;
      #pragma unroll
      for (int jj = 0; jj < 64; jj++) a += pr[jj] * kt[jj * 68 + j];
      ctxs[r * 64 + j] = ctxs[r * 64 + j] * rsc[r] + a;
    }
    __syncthreads();
  }

  // write partials
  qred[rg * 64 + j] = qacc;
  __syncthreads();
  if (rg == 0)
    g_pq[(bh * 8 + split) * 64 + j] =
      qred[j] + qred[64 + j] + qred[128 + j] + qred[192 + j];
  if (tid < u) {
    g_pm[(bh * 8 + split) * UMAX + tid] = rm[tid];
    g_ps[(bh * 8 + split) * UMAX + tid] = rs[tid];
  }
  for (int e = tid; e < u * 64; e += 256) {
    int r = e >> 6, d = e & 63;
    g_pctx[((size_t)((bh * 8 + split) * UMAX + r)) * 64 + d] = ctxs[r * 64 + d];
  }
}

// ------------------- merge split-L partials ---------------------------------
__global__ __launch_bounds__(256) void ctx_merge_kernel(int L, int u, int nsplit)
{
  int bh = blockIdx.x;
  int tid = threadIdx.x;
  if (tid < 64) {
    float q = 0.f;
    for (int s = 0; s < nsplit; s++) q += g_pq[(bh * 8 + s) * 64 + tid];
    g_qmean[bh * 64 + tid] = q / (float)L;
  }
  for (int e = tid; e < u * 64; e += 256) {
    int r = e >> 6, d = e & 63;
    float M0 = -INFINITY;
    for (int s = 0; s < nsplit; s++)
      M0 = fmaxf(M0, g_pm[(bh * 8 + s) * UMAX + r]);
    float num = 0.f, den = 0.f;
    for (int s = 0; s < nsplit; s++) {
      float c = __expf(g_pm[(bh * 8 + s) * UMAX + r] - M0);
      num += g_pctx[((size_t)((bh * 8 + s) * UMAX + r)) * 64 + d] * c;
      den += g_ps[(bh * 8 + s) * UMAX + r] * c;
    }
    g_ctx[((size_t)(bh * u + r)) * 64 + d] = num / den;
  }
}

// ------------------- block reduce helper (128 threads) ---------------------
__device__ __forceinline__ float blocksum128(float v, float* sred)
{
  #pragma unroll
  for (int o = 16; o; o >>= 1) v += __shfl_xor_sync(0xffffffffu, v, o);
  if ((threadIdx.x & 31) == 0) sred[threadIdx.x >> 5] = v;
  __syncthreads();
  float t = sred[0] + sred[1] + sred[2] + sred[3];
  __syncthreads();
  return t;
}

// ------------------- assemble attention out + residual + LN1 + fp16 hi -----
__global__ __launch_bounds__(128) void assemble_ln1_kernel(
    const float* __restrict__ hin, float* __restrict__ xout,
    __half* __restrict__ xhi,
    const float* __restrict__ gamma, const float* __restrict__ beta,
    int L, int u)
{
  __shared__ float sred[4];
  int row = blockIdx.x;
  int b = row / L, l = row - b * L;
  int tid = threadIdx.x;
  float v[4];
  #pragma unroll
  for (int i = 0; i < 4; i++) {
    int e = i * 128 + tid;
    int hh = e >> 6, dd = e & 63;
    int bh = b * 8 + hh;
    int r = g_rowmap[(size_t)bh * L + l];
    float nv = (r >= 0) ? g_ctx[((size_t)(bh * u + r)) * 64 + dd]
                        : g_qmean[bh * 64 + dd];
    v[i] = hin[(size_t)row * DD + e] + nv;
  }
  float s = blocksum128(v[0] + v[1] + v[2] + v[3], sred);
  float mu = s * (1.0f / 512.0f);
  float vs = 0.f;
  #pragma unroll
  for (int i = 0; i < 4; i++) { float d = v[i] - mu; vs += d * d; }
  vs = blocksum128(vs, sred);
  float rstd = rsqrtf(vs * (1.0f / 512.0f) + LN_EPS);
  #pragma unroll
  for (int i = 0; i < 4; i++) {
    int e = i * 128 + tid;
    float o = (v[i] - mu) * rstd * gamma[e] + beta[e];
    xout[(size_t)row * DD + e] = o;
    xhi[(size_t)row * DD + e] = __float2half_rn(o);
  }
}

// ------------------- fused residual+LN2+distil (layers 0,1) ----------------
__global__ __launch_bounds__(128) void ln2_distil_kernel(
    const float* __restrict__ xin, const float* __restrict__ zin,
    float* __restrict__ outp, __half* __restrict__ outh,
    const float* __restrict__ gamma, const float* __restrict__ beta, int L2)
{
  __shared__ float sred[4];
  int rowo = blockIdx.x;
  int b = rowo / L2, l2 = rowo - b * L2;
  size_t r0 = ((size_t)b * (2 * L2) + 2 * l2);
  int tid = threadIdx.x;
  float o01[4];
  #pragma unroll
  for (int half = 0; half < 2; half++) {
    size_t row = r0 + half;
    float v[4];
    #pragma unroll
    for (int i = 0; i < 4; i++) {
      int e = i * 128 + tid;
      v[i] = xin[row * DD + e] + zin[row * DD + e];
    }
    float s = blocksum128(v[0] + v[1] + v[2] + v[3], sred);
    float mu = s * (1.0f / 512.0f);
    float vs = 0.f;
    #pragma unroll
    for (int i = 0; i < 4; i++) { float d = v[i] - mu; vs += d * d; }
    vs = blocksum128(vs, sred);
    float rstd = rsqrtf(vs * (1.0f / 512.0f) + LN_EPS);
    #pragma unroll
    for (int i = 0; i < 4; i++) {
      int e = i * 128 + tid;
      float o = (v[i] - mu) * rstd * gamma[e] + beta[e];
      if (half == 0) o01[i] = o; else o01[i] = 0.5f * (o01[i] + o);
    }
  }
  #pragma unroll
  for (int i = 0; i < 4; i++) {
    int e = i * 128 + tid;
    outp[(size_t)rowo * DD + e] = o01[i];
    outh[(size_t)rowo * DD + e] = __float2half_rn(o01[i]);
  }
}

// ------------------- residual + LN2 -> fp16 split only (last layer) --------
__global__ __launch_bounds__(128) void ln2_split_kernel(
    const float* __restrict__ xin, const float* __restrict__ zin,
    __half* __restrict__ ohi, __half* __restrict__ olo,
    const float* __restrict__ gamma, const float* __restrict__ beta)
{
  __shared__ float sred[4];
  size_t row = blockIdx.x;
  int tid = threadIdx.x;
  float v[4];
  #pragma unroll
  for (int i = 0; i < 4; i++) {
    int e = i * 128 + tid;
    v[i] = xin[row * DD + e] + zin[row * DD + e];
  }
  float s = blocksum128(v[0] + v[1] + v[2] + v[3], sred);
  float mu = s * (1.0f / 512.0f);
  float vs = 0.f;
  #pragma unroll
  for (int i = 0; i < 4; i++) { float d = v[i] - mu; vs += d * d; }
  vs = blocksum128(vs, sred);
  float rstd = rsqrtf(vs * (1.0f / 512.0f) + LN_EPS);
  #pragma unroll
  for (int i = 0; i < 4; i++) {
    int e = i * 128 + tid;
    float o = (v[i] - mu) * rstd * gamma[e] + beta[e];
    __half h16, l16;
    split_fp16(o, h16, l16);
    ohi[row * DD + e] = h16;
    olo[row * DD + e] = l16;
  }
}

// ------------------- fp16 tensor-core GEMM (1/2/3-pass) ---------------------
#define KC 32                     // k elems per stage
#define LDPB 80                   // padded row stride in BYTES (40 fp16)
#define PLANE_B (128*LDPB)        // 10240 bytes per plane

__device__ __forceinline__ void mma_fp16(float* c, const unsigned* a, const unsigned* b)
{
  asm volatile(
    "mma.sync.aligned.m16n8k16.row.col.f32.f16.f16.f32 "
    "{%0,%1,%2,%3},{%4,%5,%6,%7},{%8,%9},{%0,%1,%2,%3};\n"
    : "+f"(c[0]), "+f"(c[1]), "+f"(c[2]), "+f"(c[3])
    : "r"(a[0]), "r"(a[1]), "r"(a[2]), "r"(a[3]), "r"(b[0]), "r"(b[1]));
}

__device__ __forceinline__ void ldsm4(unsigned* r, const char* sptr)
{
  unsigned addr = (unsigned)__cvta_generic_to_shared(sptr);
  asm volatile("ldmatrix.sync.aligned.m8n8.x4.shared.b16 {%0,%1,%2,%3}, [%4];\n"
    : "=r"(r[0]), "=r"(r[1]), "=r"(r[2]), "=r"(r[3]) : "r"(addr));
}

// EPI 0: Cf = acc + bias (fp32)
// EPI 1: Chi = fp16(gelu(acc + bias))
// EPI 2: Cf = acc + bias + PE (fp32) AND Chh = fp16 copy
// NPASS 1: A_hi x B_hi | NPASS 2: (A_hi+A_lo) x B_hi | NPASS 3: + A_hi x B_lo
template<int EPI, int NPASS>
__global__ __launch_bounds__(256, 2) void mma_gemm(
    const __half* __restrict__ Ahi, const __half* __restrict__ Alo,
    const __half* __restrict__ Bhi, const __half* __restrict__ Blo,
    const float* __restrict__ bias,
    float* __restrict__ Cf, __half* __restrict__ Chi, __half* __restrict__ Chh,
    int M, int N, int K, int Lmask)
{
  constexpr int NPLANES = (NPASS == 3) ? 4 : (NPASS + 1);
  const int STGB = NPLANES * PLANE_B;
  extern __shared__ char smc[];
  const int tid = threadIdx.x;
  const int bm = blockIdx.y * 128, bn = blockIdx.x * 128;
  const int lane = tid & 31;
  const int g = lane >> 2, t4 = lane & 3;
  const int warp = tid >> 5;
  const int wm = warp >> 2, wn = warp & 3;      // warps 2(m) x 4(n)
  const int moff = wm * 64, noff = wn * 32;

  const int aoff = (lane & 15) * LDPB + ((lane & 16) ? 16 : 0);
  const int boff = ((lane & 7) + ((lane & 16) ? 8 : 0)) * LDPB + ((lane & 8) ? 16 : 0);

  float acc[4][4][4];
  #pragma unroll
  for (int i = 0; i < 4; i++)
    #pragma unroll
    for (int j = 0; j < 4; j++)
      #pragma unroll
      for (int q = 0; q < 4; q++) acc[i][j][q] = 0.f;

  const int KT = K / KC;

  #define PREFETCH(kt, s) do {                                                   \
    int k0_ = (kt) * KC;                                                         \
    const char* srcs_[NPLANES];                                                  \
    int np_ = 0;                                                                 \
    srcs_[np_++] = (const char*)(Ahi + (size_t)bm * K + k0_);                    \
    if (NPASS >= 2) srcs_[np_++] = (const char*)(Alo + (size_t)bm * K + k0_);    \
    srcs_[np_++] = (const char*)(Bhi + (size_t)bn * K + k0_);                    \
    if (NPASS == 3) srcs_[np_++] = (const char*)(Blo + (size_t)bn * K + k0_);    \
    _Pragma("unroll")                                                            \
    for (int p_ = 0; p_ < NPLANES; p_++) {                                       \
      char* dstp_ = smc + (s) * STGB + p_ * PLANE_B;                             \
      _Pragma("unroll")                                                          \
      for (int j_ = 0; j_ < 2; j_++) {                                           \
        int idx_ = j_ * 256 + tid;                                               \
        int row_ = idx_ >> 2, ch_ = idx_ & 3;                                    \
        unsigned sa_ = (unsigned)__cvta_generic_to_shared(dstp_ + row_ * LDPB + ch_ * 16); \
        const char* ga_ = srcs_[p_] + (size_t)row_ * K * 2 + ch_ * 16;           \
        asm volatile("cp.async.ca.shared.global [%0], [%1], 16;\n"               \
                     :: "r"(sa_), "l"(ga_));                                     \
      }                                                                          \
    }                                                                            \
    asm volatile("cp.async.commit_group;\n");                                    \
  } while (0)

  PREFETCH(0, 0);

  for (int kt = 0; kt < KT; kt++) {
    asm volatile("cp.async.wait_group 0;\n");
    __syncthreads();
    if (kt + 1 < KT) PREFETCH(kt + 1, (kt + 1) & 1);

    const char* Sahi = smc + (kt & 1) * STGB;
    const char* Salo = Sahi + PLANE_B;                         // NPASS>=2
    const char* Sbhi = Sahi + ((NPASS >= 2) ? 2 : 1) * PLANE_B;
    const char* Sblo = Sbhi + PLANE_B;                         // NPASS==3

    #pragma unroll
    for (int ks = 0; ks < 2; ks++) {
      int kb = ks * 32;   // 16 fp16 = 32 bytes
      unsigned bh_[2][4], bl_[2][4];
      #pragma unroll
      for (int pp = 0; pp < 2; pp++) {
        ldsm4(bh_[pp], Sbhi + (noff + pp * 16) * LDPB + kb + boff);
        if (NPASS == 3)
          ldsm4(bl_[pp], Sblo + (noff + pp * 16) * LDPB + kb + boff);
      }
      #pragma unroll
      for (int tm = 0; tm < 4; tm++) {
        unsigned ah[4], al[4];
        ldsm4(ah, Sahi + (moff + tm * 16) * LDPB + kb + aoff);
        if (NPASS >= 2)
          ldsm4(al, Salo + (moff + tm * 16) * LDPB + kb + aoff);
        #pragma unroll
        for (int tn = 0; tn < 4; tn++) {
          const unsigned* bhp = &bh_[tn >> 1][(tn & 1) * 2];
          mma_fp16(acc[tm][tn], ah, bhp);
          if (NPASS >= 2) mma_fp16(acc[tm][tn], al, bhp);
          if (NPASS == 3) {
            const unsigned* blp = &bl_[tn >> 1][(tn & 1) * 2];
            mma_fp16(acc[tm][tn], ah, blp);
          }
        }
      }
    }
    __syncthreads();
  }

  // ---- epilogue ----
  #pragma unroll
  for (int tm = 0; tm < 4; tm++) {
    int r0 = bm + moff + tm * 16 + g;
    int r1 = r0 + 8;
    #pragma unroll
    for (int tn = 0; tn < 4; tn++) {
      int c0 = bn + noff + tn * 8 + 2 * t4;   // even column
      float b0 = bias[c0], b1 = bias[c0 + 1];
      float v00 = acc[tm][tn][0] + b0;
      float v01 = acc[tm][tn][1] + b1;
      float v10 = acc[tm][tn][2] + b0;
      float v11 = acc[tm][tn][3] + b1;
      if (EPI == 1) {
        v00 = 0.5f * v00 * (1.f + erff(v00 * 0.70710678118654752f));
        v01 = 0.5f * v01 * (1.f + erff(v01 * 0.70710678118654752f));
        v10 = 0.5f * v10 * (1.f + erff(v10 * 0.70710678118654752f));
        v11 = 0.5f * v11 * (1.f + erff(v11 * 0.70710678118654752f));
        *(__half2*)(Chi + (size_t)r0 * N + c0) =
          __halves2half2(__float2half_rn(v00), __float2half_rn(v01));
        *(__half2*)(Chi + (size_t)r1 * N + c0) =
          __halves2half2(__float2half_rn(v10), __float2half_rn(v11));
      } else {
        if (EPI == 2) {
          float df = expf((float)c0 * (-0.017988946039015984f));
          float a0 = (float)(r0 & Lmask) * df;
          float a1 = (float)(r1 & Lmask) * df;
          v00 += sinf(a0); v01 += cosf(a0);
          v10 += sinf(a1); v11 += cosf(a1);
          *(__half2*)(Chh + (size_t)r0 * N + c0) =
            __halves2half2(__float2half_rn(v00), __float2half_rn(v01));
          *(__half2*)(Chh + (size_t)r1 * N + c0) =
            __halves2half2(__float2half_rn(v10), __float2half_rn(v11));
        }
        *(float2*)(Cf + (size_t)r0 * N + c0) = make_float2(v00, v01);
        *(float2*)(Cf + (size_t)r1 * N + c0) = make_float2(v10, v11);
      }
    }
  }
  #undef PREFETCH
}

// ------------------- host: layer key derivation ----------------------------
static void layer_key(int i, unsigned &k0, unsigned &k1)
{
  unsigned a = 0u, b = (unsigned)i;
  threefry2x32(0u, 42u, a, b);
  unsigned c = 0u, d = 1u;
  threefry2x32(a, b, c, d);
  k0 = c; k1 = d;
}

extern "C" void kernel_launch(void* const* d_in, const int* in_sizes, int n_in,
                              void* d_out, int out_size)
{
  const float* x     = (const float*)d_in[0];
  const float* emb_w = (const float*)d_in[1];
  const float* emb_b = (const float*)d_in[2];
  const float* ln1_s = (const float*)d_in[3];
  const float* ln1_b = (const float*)d_in[4];
  const float* w1    = (const float*)d_in[5];
  const float* b1    = (const float*)d_in[6];
  const float* w2    = (const float*)d_in[7];
  const float* b2    = (const float*)d_in[8];
  const float* ln2_s = (const float*)d_in[9];
  const float* ln2_b = (const float*)d_in[10];
  const float* out_w = (const float*)d_in[11];
  const float* out_b = (const float*)d_in[12];
  float* out = (float*)d_out;

  float *ph, *px, *pz;
  __half *phh, *pxhi, *pxlo, *pyhi;
  __half *pw1hi, *pw2hi, *powhi;
  __half *pexhi, *pexlo, *pewhi, *pewlo;
  cudaGetSymbolAddress((void**)&ph,   g_h);
  cudaGetSymbolAddress((void**)&phh,  g_hh);
  cudaGetSymbolAddress((void**)&px,   g_x);
  cudaGetSymbolAddress((void**)&pz,   g_z);
  cudaGetSymbolAddress((void**)&pxhi, g_xhi);
  cudaGetSymbolAddress((void**)&pxlo, g_xlo);
  cudaGetSymbolAddress((void**)&pyhi, g_yhi);
  cudaGetSymbolAddress((void**)&pw1hi, g_w1hi);
  cudaGetSymbolAddress((void**)&pw2hi, g_w2hi);
  cudaGetSymbolAddress((void**)&powhi, g_owhi);
  cudaGetSymbolAddress((void**)&pexhi, g_exhi);
  cudaGetSymbolAddress((void**)&pexlo, g_exlo);
  cudaGetSymbolAddress((void**)&pewhi, g_ewhi);
  cudaGetSymbolAddress((void**)&pewlo, g_ewlo);

  static int smem_set = 0;
  if (!smem_set) {
    cudaFuncSetAttribute(mma_gemm<2,3>, cudaFuncAttributeMaxDynamicSharedMemorySize, 2 * 4 * PLANE_B);
    cudaFuncSetAttribute(mma_gemm<1,1>, cudaFuncAttributeMaxDynamicSharedMemorySize, 2 * 2 * PLANE_B);
    cudaFuncSetAttribute(mma_gemm<0,1>, cudaFuncAttributeMaxDynamicSharedMemorySize, 2 * 2 * PLANE_B);
    cudaFuncSetAttribute(mma_gemm<0,2>, cudaFuncAttributeMaxDynamicSharedMemorySize, 2 * 3 * PLANE_B);
    cudaFuncSetAttribute(ctx_split_kernel, cudaFuncAttributeMaxDynamicSharedMemorySize, CTX_SMEM_FLOATS * 4);
    smem_set = 1;
  }
  const int ctx_smem = CTX_SMEM_FLOATS * 4;

  // input conversions (embed deps)
  {
    int n3 = BB * L0 * 64;
    xsplit_kernel<<<(n3 + 255) / 256, 256>>>(x, pexhi, pexlo, n3);
    int n4 = DD * 64;
    xsplit_kernel<<<(n4 + 255) / 256, 256>>>(emb_w, pewhi, pewlo, n4);
  }

  // Embed (3-pass fp16 mma): h = x @ emb_w^T + emb_b + PE; also fp16 mirror
  {
    int M = BB * L0;
    mma_gemm<2,3><<<dim3(DD / 128, M / 128), 256, 2 * 4 * PLANE_B>>>(
        pexhi, pexlo, pewhi, pewlo, emb_b, ph, nullptr, phh, M, DD, 64, L0 - 1);
  }

  int L = L0;
  float* cur = ph;
  for (int i = 0; i < 3; i++) {
    int u = (i == 0) ? 45 : (i == 1) ? 40 : 35;
    int M = BB * L;
    unsigned k0, k1; layer_key(i, k0, k1);
    int total = L * u;
    idx_part<<<(total + 255) / 256, 256>>>(k0, k1, total, L - 1);
    prob_m_kernel<<<dim3(L / 8, 64), 256>>>(phh, L, u, 1.0f / (float)L);
    topk_kernel<<<64, 256>>>(L, u);
    int nsplit = L / 512; if (nsplit < 1) nsplit = 1; if (nsplit > 8) nsplit = 8;
    ctx_split_kernel<<<dim3(nsplit, 64), 256, ctx_smem>>>(phh, L, u, L / nsplit);
    ctx_merge_kernel<<<64, 256>>>(L, u, nsplit);
    assemble_ln1_kernel<<<M, 128>>>(cur, px, pxhi,
                                    ln1_s + i * DD, ln1_b + i * DD, L, u);

    if (i == 0) {
      int n1 = 3 * DFF * DD;
      whalf_kernel<<<(n1 + 255) / 256, 256>>>(w1, pw1hi, n1);
      whalf_kernel<<<(n1 + 255) / 256, 256>>>(w2, pw2hi, n1);
      int n2 = DD * DD;
      whalf_kernel<<<(n2 + 255) / 256, 256>>>(out_w, powhi, n2);
    }

    // FFN1: y = gelu(x @ w1^T + b1), 1-pass, fp16 out
    mma_gemm<1,1><<<dim3(DFF / 128, M / 128), 256, 2 * 2 * PLANE_B>>>(
        pxhi, nullptr, pw1hi + (size_t)i * DFF * DD, nullptr,
        b1 + i * DFF, nullptr, pyhi, nullptr, M, DFF, DD, 0);
    // FFN2: z = y @ w2^T + b2, 1-pass, fp32 out
    mma_gemm<0,1><<<dim3(DD / 128, M / 128), 256, 2 * 2 * PLANE_B>>>(
        pyhi, nullptr, pw2hi + (size_t)i * DD * DFF, nullptr,
        b2 + i * DD, pz, nullptr, nullptr, M, DD, DFF, 0);

    if (i < 2) {
      int L2 = L / 2;
      ln2_distil_kernel<<<BB * L2, 128>>>(px, pz, cur, phh,
                                          ln2_s + i * DD, ln2_b + i * DD, L2);
      L = L2;
    } else {
      ln2_split_kernel<<<M, 128>>>(px, pz, pxhi, pxlo,
                                   ln2_s + i * DD, ln2_b + i * DD);
    }
  }

  // Final projection: out = h @ out_w^T + out_b, 2-pass A (M=8192,N=512,K=512)
  {
    int M = BB * L;   // L = 1024
    mma_gemm<0,2><<<dim3(DD / 128, M / 128), 256, 2 * 3 * PLANE_B>>>(
        pxhi, pxlo, powhi, nullptr, out_b, out, nullptr, nullptr, M, DD, DD, 0);
  }
}